// round 9
// baseline (speedup 1.0000x reference)
#include <cuda_runtime.h>
#include <cuda_bf16.h>
#include <mma.h>
#include <math.h>
#include <stdint.h>

using namespace nvcuda;

#define B_ 4
#define C_ 96
#define H_ 256
#define W_ 256
#define HW (H_*W_)
#define LDA 104
#define LDW 72        // 64-px tile B row stride (bf16)

typedef __nv_bfloat16 bf16;

// Scratch (allocation-free rule: __device__ globals)
__device__ float g_xn[B_*C_*HW];
__device__ float g_e0[B_*C_*HW];
__device__ float g_xa[B_*C_*HW];
__device__ float g_x1[B_*C_*HW];
__device__ bf16  g_hh[B_*192*HW];   // gelu(h) hi plane
__device__ bf16  g_hl[B_*192*HW];   // gelu(h) lo plane

// Pre-split weights (hi/lo) in padded [96][LDA] smem-image layout
__device__ __align__(16) bf16 g_we0h[96*LDA],  g_we0l[96*LDA];
__device__ __align__(16) bf16 g_wpjh[96*LDA],  g_wpjl[96*LDA];
__device__ __align__(16) bf16 g_w1h[2*96*LDA], g_w1l[2*96*LDA];
__device__ __align__(16) bf16 g_w2h[2*96*LDA], g_w2l[2*96*LDA];

using FragA = wmma::fragment<wmma::matrix_a, 16, 16, 16, bf16, wmma::row_major>;
using FragB = wmma::fragment<wmma::matrix_b, 16, 16, 16, bf16, wmma::row_major>;
using FragC = wmma::fragment<wmma::accumulator, 16, 16, 16, float>;

__device__ __forceinline__ void split_bf16(float v, bf16& h, bf16& l) {
    h = __float2bfloat16_rn(v);
    l = __float2bfloat16_rn(v - __bfloat162float(h));
}

// Copy pre-split weight chunk ([96][LDA] bf16 x2) global -> smem. Pure uint4 copies.
__device__ __forceinline__ void copy_w(const bf16* __restrict__ srch,
                                       const bf16* __restrict__ srcl,
                                       bf16* wsh, bf16* wsl, int t)
{
    const uint4* sh = (const uint4*)srch;
    const uint4* sl = (const uint4*)srcl;
    uint4* dh = (uint4*)wsh;
    uint4* dl = (uint4*)wsl;
    for (int i = t; i < 1248; i += 256) { dh[i] = sh[i]; dl[i] = sl[i]; }
}

// Split-load activations tile [96 ch][64 px] (f32, row stride HW) -> smem [96][LDW]
__device__ __forceinline__ void load_act(const float* __restrict__ src,
                                         bf16* xh, bf16* xl, int t)
{
    for (int i = t; i < 1536; i += 256) {     // 96*16 float4
        int k = i >> 4, cc = (i & 15) * 4;
        float4 v = *(const float4*)(src + (size_t)k * HW + cc);
        bf16 h0,l0,h1,l1,h2,l2,h3,l3;
        split_bf16(v.x, h0, l0); split_bf16(v.y, h1, l1);
        split_bf16(v.z, h2, l2); split_bf16(v.w, h3, l3);
        __nv_bfloat162* ph = (__nv_bfloat162*)(xh + k * LDW + cc);
        __nv_bfloat162* pl = (__nv_bfloat162*)(xl + k * LDW + cc);
        ph[0] = __nv_bfloat162{h0, h1}; ph[1] = __nv_bfloat162{h2, h3};
        pl[0] = __nv_bfloat162{l0, l1}; pl[1] = __nv_bfloat162{l2, l3};
    }
}

// 3-pass GEMM: C[96 x 64] += A[96x96] * B[96x64]. 8 warps: wm 0..1, wn 0..3.
__device__ __forceinline__ void gemm3(
    const bf16* ah, const bf16* al, const bf16* bh, const bf16* bl,
    FragC (&acc)[3], int wm, int wn)
{
    #pragma unroll 1
    for (int k = 0; k < 6; k++) {
        FragB b_h, b_l;
        wmma::load_matrix_sync(b_h, bh + (k*16)*LDW + wn*16, LDW);
        wmma::load_matrix_sync(b_l, bl + (k*16)*LDW + wn*16, LDW);
        #pragma unroll
        for (int mf = 0; mf < 3; mf++) {
            FragA a_h, a_l;
            wmma::load_matrix_sync(a_h, ah + (wm*48 + mf*16)*LDA + k*16, LDA);
            wmma::load_matrix_sync(a_l, al + (wm*48 + mf*16)*LDA + k*16, LDA);
            wmma::mma_sync(acc[mf], a_h, b_h, acc[mf]);
            wmma::mma_sync(acc[mf], a_h, b_l, acc[mf]);
            wmma::mma_sync(acc[mf], a_l, b_h, acc[mf]);
        }
    }
}

__device__ __forceinline__ void zero3(FragC (&acc)[3]) {
    #pragma unroll
    for (int mf = 0; mf < 3; mf++) wmma::fill_fragment(acc[mf], 0.f);
}

// smem layout (bytes)
#define S_XSH 0
#define S_XSL 13824
#define S_WSH 27648
#define S_WSL 47616
#define S_PRM 67584
#define S_END (S_PRM + 4608)

// ---------------------------------------------------------------------------
// Weight prep: f32 -> bf16 hi/lo in padded layouts (runs once per launch)
// ---------------------------------------------------------------------------
__global__ void k_prep(const float* __restrict__ e0, const float* __restrict__ pj,
                       const float* __restrict__ w1, const float* __restrict__ w2)
{
    int i = blockIdx.x * 256 + threadIdx.x;
    float v; bf16 *dh, *dl; int off;
    if (i < 9216) {
        int m = i / 96, k = i % 96;
        v = e0[i]; dh = g_we0h; dl = g_we0l; off = m * LDA + k;
    } else if (i < 18432) {
        int j = i - 9216; int m = j / 96, k = j % 96;
        v = pj[j]; dh = g_wpjh; dl = g_wpjl; off = m * LDA + k;
    } else if (i < 36864) {
        int j = i - 18432; int m = j / 96, k = j % 96;     // m 0..191
        v = w1[j]; dh = g_w1h; dl = g_w1l;
        off = (m / 96) * 96 * LDA + (m % 96) * LDA + k;
    } else if (i < 55296) {
        int j = i - 36864; int m = j / 192, k = j % 192;   // w2 [96][192]
        v = w2[j]; dh = g_w2h; dl = g_w2l;
        off = (k / 96) * 96 * LDA + m * LDA + (k % 96);
    } else return;
    bf16 h, l; split_bf16(v, h, l);
    dh[off] = h; dl[off] = l;
}

// ---------------------------------------------------------------------------
// Kernel 1: LayerNorm (2-phase global read) + e0 pointwise -> g_xn, g_e0
// ---------------------------------------------------------------------------
__global__ __launch_bounds__(256, 3) void k_ln_e0pw(
    const float* __restrict__ x,
    const float* __restrict__ lnw, const float* __restrict__ lnb,
    const float* __restrict__ bias)
{
    extern __shared__ unsigned char smraw[];
    bf16* xsh = (bf16*)(smraw + S_XSH);
    bf16* xsl = (bf16*)(smraw + S_XSL);
    bf16* wsh = (bf16*)(smraw + S_WSH);
    bf16* wsl = (bf16*)(smraw + S_WSL);
    float* stg = (float*)(smraw + S_WSH);        // aliases WSH after GEMM
    float* prm = (float*)(smraw + S_PRM);
    float* psum = prm;            // [8][64]
    float* psq  = prm + 512;      // [8][64]
    float* mu   = prm + 1024;
    float* inv  = prm + 1088;

    const int t = threadIdx.x, wid = t >> 5, lane = t & 31;
    const int b = blockIdx.y, p0 = blockIdx.x * 64;
    const float* xb = x + (size_t)b * C_ * HW + p0;

    copy_w(g_we0h, g_we0l, wsh, wsl, t);

    // stats: warp wid covers rows {wid, wid+8,...}, lane covers 2 px
    {
        const int c2 = lane * 2;
        float s0=0, s1=0, q0=0, q1=0;
        #pragma unroll 1
        for (int it = 0; it < 12; it++) {
            float2 v = *(const float2*)(xb + (size_t)(it * 8 + wid) * HW + c2);
            s0 += v.x; s1 += v.y; q0 += v.x*v.x; q1 += v.y*v.y;
        }
        psum[wid*64 + c2] = s0; psum[wid*64 + c2 + 1] = s1;
        psq [wid*64 + c2] = q0; psq [wid*64 + c2 + 1] = q1;
    }
    __syncthreads();
    if (t < 64) {
        float s = 0.f, q = 0.f;
        #pragma unroll
        for (int g = 0; g < 8; g++) { s += psum[g*64 + t]; q += psq[g*64 + t]; }
        float m = s * (1.f / 96.f);
        mu[t] = m;
        inv[t] = rsqrtf(q * (1.f / 96.f) - m * m + 1e-6f);
    }
    __syncthreads();

    // normalize (L2-hot re-read) + write xn + split into smem
    float* xnb = g_xn + (size_t)b * C_ * HW + p0;
    for (int i = t; i < 1536; i += 256) {
        int k = i >> 4, cc = (i & 15) * 4;
        float4 v = *(const float4*)(xb + (size_t)k * HW + cc);
        float lw = __ldg(&lnw[k]), lb = __ldg(&lnb[k]);
        float o0 = (v.x - mu[cc+0]) * inv[cc+0] * lw + lb;
        float o1 = (v.y - mu[cc+1]) * inv[cc+1] * lw + lb;
        float o2 = (v.z - mu[cc+2]) * inv[cc+2] * lw + lb;
        float o3 = (v.w - mu[cc+3]) * inv[cc+3] * lw + lb;
        *(float4*)(xnb + (size_t)k * HW + cc) = make_float4(o0, o1, o2, o3);
        bf16 h0,l0,h1,l1,h2,l2,h3,l3;
        split_bf16(o0, h0, l0); split_bf16(o1, h1, l1);
        split_bf16(o2, h2, l2); split_bf16(o3, h3, l3);
        __nv_bfloat162* ph = (__nv_bfloat162*)(xsh + k * LDW + cc);
        __nv_bfloat162* pl = (__nv_bfloat162*)(xsl + k * LDW + cc);
        ph[0] = __nv_bfloat162{h0, h1}; ph[1] = __nv_bfloat162{h2, h3};
        pl[0] = __nv_bfloat162{l0, l1}; pl[1] = __nv_bfloat162{l2, l3};
    }
    __syncthreads();

    const int wm = wid >> 2, wn = wid & 3;
    FragC acc[3];
    zero3(acc);
    gemm3(wsh, wsl, xsh, xsl, acc, wm, wn);
    __syncthreads();                 // ws dead -> stg alias safe

    float* st = stg + wid * 256;
    float* gb = g_e0 + (size_t)b * C_ * HW + p0;
    const int r = lane >> 1, c8 = (lane & 1) * 8;
    #pragma unroll
    for (int mf = 0; mf < 3; mf++) {
        wmma::store_matrix_sync(st, acc[mf], 16, wmma::mem_row_major);
        __syncwarp();
        int mm = wm*48 + mf*16 + r;
        int pp = wn*16 + c8;
        float bb = __ldg(&bias[mm]);
        float* gp = gb + (size_t)mm * HW + pp;
        const float* sp = st + r*16 + c8;
        #pragma unroll
        for (int q = 0; q < 8; q++) gp[q] = sp[q] + bb;
        __syncwarp();
    }
}

// ---------------------------------------------------------------------------
// Kernel 2: depthwise experts + mixing (64x64 tiles, 512 thr) — unchanged
// ---------------------------------------------------------------------------
__global__ __launch_bounds__(512, 2) void k_dw(
    const float* __restrict__ sw,
    const float* __restrict__ prompt,
    const float* __restrict__ w0, const float* __restrict__ b0,
    const float* __restrict__ w1, const float* __restrict__ b1,
    const float* __restrict__ w2, const float* __restrict__ b2)
{
    __shared__ float xs[76 * 77];
    __shared__ float es[66 * 67];
    __shared__ float kw[43];

    const int t = threadIdx.x;
    int c = blockIdx.y, b = blockIdx.z;
    int ty0 = (blockIdx.x >> 2) * 64;
    int tx0 = (blockIdx.x & 3) * 64;
    const float* xn = g_xn + ((size_t)(b * C_ + c)) * HW;
    const float* ep = g_e0 + ((size_t)(b * C_ + c)) * HW;

    for (int i = t; i < 76 * 76; i += 512) {
        int r = i / 76, cc = i % 76;
        int yy = ty0 - 6 + r, xx = tx0 - 6 + cc;
        xs[r * 77 + cc] = (yy >= 0 && yy < H_ && xx >= 0 && xx < W_) ? xn[yy * W_ + xx] : 0.f;
    }
    for (int i = t; i < 66 * 66; i += 512) {
        int r = i / 66, cc = i % 66;
        int yy = ty0 - 1 + r, xx = tx0 - 1 + cc;
        es[r * 67 + cc] = (yy >= 0 && yy < H_ && xx >= 0 && xx < W_) ? ep[yy * W_ + xx] : 0.f;
    }
    if (t < 43) {
        kw[t] = (t < 9) ? __ldg(&w0[c*9 + t])
              : (t < 18) ? __ldg(&w1[c*9 + t - 9])
              : __ldg(&w2[c*25 + t - 18]);
    }
    float bb0 = __ldg(&b0[c]), bb1 = __ldg(&b1[c]), bb2 = __ldg(&b2[c]);
    float s0 = __ldg(&sw[b*3+0]), s1 = __ldg(&sw[b*3+1]), s2 = __ldg(&sw[b*3+2]);
    float pm = 1.f + __ldg(&prompt[b * C_ + c]);
    __syncthreads();

    const int py = t >> 3, px0 = (t & 7) * 8;
    float o[8], r8[8];

    #pragma unroll
    for (int j = 0; j < 8; j++) r8[j] = bb0;
    #pragma unroll
    for (int ky = 0; ky < 3; ky++)
        #pragma unroll
        for (int kx = 0; kx < 3; kx++) {
            float wv = kw[ky*3 + kx];
            const float* rowp = es + (py + ky) * 67 + px0 + kx;
            #pragma unroll
            for (int j = 0; j < 8; j++) r8[j] += wv * rowp[j];
        }
    #pragma unroll
    for (int j = 0; j < 8; j++) o[j] = s0 * r8[j];

    #pragma unroll
    for (int j = 0; j < 8; j++) r8[j] = bb1;
    #pragma unroll
    for (int ky = 0; ky < 3; ky++)
        #pragma unroll
        for (int kx = 0; kx < 3; kx++) {
            float wv = kw[9 + ky*3 + kx];
            const float* rowp = xs + (py + 4 + 2*ky) * 77 + px0 + 4 + 2*kx;
            #pragma unroll
            for (int j = 0; j < 8; j++) r8[j] += wv * rowp[j];
        }
    #pragma unroll
    for (int j = 0; j < 8; j++) o[j] += s1 * r8[j];

    #pragma unroll
    for (int j = 0; j < 8; j++) r8[j] = bb2;
    #pragma unroll
    for (int ky = 0; ky < 5; ky++)
        #pragma unroll
        for (int kx = 0; kx < 5; kx++) {
            float wv = kw[18 + ky*5 + kx];
            const float* rowp = xs + (py + 3*ky) * 77 + px0 + 3*kx;
            #pragma unroll
            for (int j = 0; j < 8; j++) r8[j] += wv * rowp[j];
        }
    #pragma unroll
    for (int j = 0; j < 8; j++) o[j] = (o[j] + s2 * r8[j]) * pm;

    float* outp = g_xa + ((size_t)(b * C_ + c)) * HW + (ty0 + py) * W_ + tx0 + px0;
    *(float4*)(outp)     = make_float4(o[0], o[1], o[2], o[3]);
    *(float4*)(outp + 4) = make_float4(o[4], o[5], o[6], o[7]);
}

// ---------------------------------------------------------------------------
// Kernel 3: x1 = x + proj(xa) -> g_x1
// ---------------------------------------------------------------------------
__global__ __launch_bounds__(256, 3) void k_proj(
    const float* __restrict__ x, const float* __restrict__ bias)
{
    extern __shared__ unsigned char smraw[];
    bf16* xsh = (bf16*)(smraw + S_XSH);
    bf16* xsl = (bf16*)(smraw + S_XSL);
    bf16* wsh = (bf16*)(smraw + S_WSH);
    bf16* wsl = (bf16*)(smraw + S_WSL);
    float* stg = (float*)(smraw + S_WSH);

    const int t = threadIdx.x, wid = t >> 5, lane = t & 31;
    const int b = blockIdx.y, p0 = blockIdx.x * 64;

    load_act(g_xa + (size_t)b * C_ * HW + p0, xsh, xsl, t);
    copy_w(g_wpjh, g_wpjl, wsh, wsl, t);
    __syncthreads();

    const int wm = wid >> 2, wn = wid & 3;
    FragC acc[3];
    zero3(acc);
    gemm3(wsh, wsl, xsh, xsl, acc, wm, wn);
    __syncthreads();

    float* st = stg + wid * 256;
    const float* rb = x   + (size_t)b * C_ * HW + p0;
    float* gb = g_x1 + (size_t)b * C_ * HW + p0;
    const int r = lane >> 1, c8 = (lane & 1) * 8;
    #pragma unroll
    for (int mf = 0; mf < 3; mf++) {
        wmma::store_matrix_sync(st, acc[mf], 16, wmma::mem_row_major);
        __syncwarp();
        int mm = wm*48 + mf*16 + r;
        int pp = wn*16 + c8;
        float bb = __ldg(&bias[mm]);
        const float* rp = rb + (size_t)mm * HW + pp;
        const float* sp = st + r*16 + c8;
        float* gp = gb + (size_t)mm * HW + pp;
        #pragma unroll
        for (int q = 0; q < 8; q++) gp[q] = sp[q] + bb + rp[q];
        __syncwarp();
    }
}

// ---------------------------------------------------------------------------
// Kernel 4: h = gelu(ffn1(x1) + b1) -> bf16 hi/lo planes g_hh/g_hl
// ---------------------------------------------------------------------------
__global__ __launch_bounds__(256, 3) void k_ffn1(const float* __restrict__ b1v)
{
    extern __shared__ unsigned char smraw[];
    bf16* xsh = (bf16*)(smraw + S_XSH);
    bf16* xsl = (bf16*)(smraw + S_XSL);
    bf16* wsh = (bf16*)(smraw + S_WSH);
    bf16* wsl = (bf16*)(smraw + S_WSL);
    float* stg = (float*)(smraw + S_WSH);

    const int t = threadIdx.x, wid = t >> 5, lane = t & 31;
    const int b = blockIdx.y, p0 = blockIdx.x * 64;

    load_act(g_x1 + (size_t)b * C_ * HW + p0, xsh, xsl, t);

    const int wm = wid >> 2, wn = wid & 3;
    const int r = lane >> 1, c8 = (lane & 1) * 8;
    float* st = stg + wid * 256;
    bf16* hhb = g_hh + (size_t)b * 192 * HW + p0;
    bf16* hlb = g_hl + (size_t)b * 192 * HW + p0;

    #pragma unroll 1
    for (int oc = 0; oc < 2; oc++) {
        __syncthreads();                       // xs ready / stg readers done
        copy_w(g_w1h + oc * 96 * LDA, g_w1l + oc * 96 * LDA, wsh, wsl, t);
        __syncthreads();

        FragC acc[3];
        zero3(acc);
        gemm3(wsh, wsl, xsh, xsl, acc, wm, wn);
        __syncthreads();                       // ws dead -> stg alias

        #pragma unroll
        for (int mf = 0; mf < 3; mf++) {
            wmma::store_matrix_sync(st, acc[mf], 16, wmma::mem_row_major);
            __syncwarp();
            int k2 = oc*96 + wm*48 + mf*16 + r;
            int pp = wn*16 + c8;
            float bb = __ldg(&b1v[k2]);
            const float* sp = st + r*16 + c8;
            bf16* gph = hhb + (size_t)k2 * HW + pp;
            bf16* gpl = hlb + (size_t)k2 * HW + pp;
            #pragma unroll
            for (int q = 0; q < 8; q++) {
                float hv = sp[q] + bb;
                float gv = hv * normcdff(hv);
                bf16 hh, ll; split_bf16(gv, hh, ll);
                gph[q] = hh; gpl[q] = ll;
            }
            __syncwarp();
        }
    }
}

// ---------------------------------------------------------------------------
// Kernel 5: out = x1 + ffn2(h) + b2 (K=192 in two chunks; h planes are copies)
// ---------------------------------------------------------------------------
__global__ __launch_bounds__(256, 3) void k_ffn2(
    const float* __restrict__ b2v, float* __restrict__ out)
{
    extern __shared__ unsigned char smraw[];
    bf16* hsh = (bf16*)(smraw + S_XSH);
    bf16* hsl = (bf16*)(smraw + S_XSL);
    bf16* wsh = (bf16*)(smraw + S_WSH);
    bf16* wsl = (bf16*)(smraw + S_WSL);
    float* stg = (float*)(smraw + S_WSH);

    const int t = threadIdx.x, wid = t >> 5, lane = t & 31;
    const int b = blockIdx.y, p0 = blockIdx.x * 64;
    const bf16* hhb = g_hh + (size_t)b * 192 * HW + p0;
    const bf16* hlb = g_hl + (size_t)b * 192 * HW + p0;

    const int wm = wid >> 2, wn = wid & 3;
    FragC acc[3];
    zero3(acc);

    #pragma unroll 1
    for (int kc = 0; kc < 2; kc++) {
        if (kc) __syncthreads();               // prior readers done
        // copy h chunk (bf16 planes -> smem, no conversion)
        for (int i = t; i < 768; i += 256) {   // 96 rows x 8 uint4
            int r = i >> 3, cc = (i & 7) * 8;
            size_t go = (size_t)(kc * 96 + r) * HW + cc;
            *(uint4*)(hsh + r * LDW + cc) = *(const uint4*)(hhb + go);
            *(uint4*)(hsl + r * LDW + cc) = *(const uint4*)(hlb + go);
        }
        copy_w(g_w2h + kc * 96 * LDA, g_w2l + kc * 96 * LDA, wsh, wsl, t);
        __syncthreads();
        gemm3(wsh, wsl, hsh, hsl, acc, wm, wn);
    }
    __syncthreads();                           // ws dead -> stg alias

    float* st = stg + wid * 256;
    const float* x1b = g_x1 + (size_t)b * C_ * HW + p0;
    float* ob = out + (size_t)b * C_ * HW + p0;
    const int r = lane >> 1, c8 = (lane & 1) * 8;
    #pragma unroll
    for (int mf = 0; mf < 3; mf++) {
        wmma::store_matrix_sync(st, acc[mf], 16, wmma::mem_row_major);
        __syncwarp();
        int mm = wm*48 + mf*16 + r;
        int pp = wn*16 + c8;
        float bb = __ldg(&b2v[mm]);
        const float* sp = st + r*16 + c8;
        const float* rp = x1b + (size_t)mm * HW + pp;
        float* gp = ob + (size_t)mm * HW + pp;
        #pragma unroll
        for (int q = 0; q < 8; q++) gp[q] = sp[q] + bb + rp[q];
        __syncwarp();
    }
}

// ---------------------------------------------------------------------------
extern "C" void kernel_launch(void* const* d_in, const int* in_sizes, int n_in,
                              void* d_out, int out_size)
{
    const float* x       = (const float*)d_in[0];
    const float* prompt  = (const float*)d_in[1];
    const float* sweights= (const float*)d_in[2];
    const float* ln_w    = (const float*)d_in[3];
    const float* ln_b    = (const float*)d_in[4];
    const float* e0_pw_w = (const float*)d_in[5];
    const float* e0_pw_b = (const float*)d_in[6];
    const float* e0_dw_w = (const float*)d_in[7];
    const float* e0_dw_b = (const float*)d_in[8];
    const float* e1_dw_w = (const float*)d_in[9];
    const float* e1_dw_b = (const float*)d_in[10];
    const float* e2_dw_w = (const float*)d_in[11];
    const float* e2_dw_b = (const float*)d_in[12];
    const float* proj_w  = (const float*)d_in[13];
    const float* proj_b  = (const float*)d_in[14];
    const float* ffn1_w  = (const float*)d_in[15];
    const float* ffn1_b  = (const float*)d_in[16];
    const float* ffn2_w  = (const float*)d_in[17];
    const float* ffn2_b  = (const float*)d_in[18];
    float* out = (float*)d_out;

    cudaFuncSetAttribute(k_ln_e0pw, cudaFuncAttributeMaxDynamicSharedMemorySize, S_END);
    cudaFuncSetAttribute(k_proj,    cudaFuncAttributeMaxDynamicSharedMemorySize, S_END);
    cudaFuncSetAttribute(k_ffn1,    cudaFuncAttributeMaxDynamicSharedMemorySize, S_END);
    cudaFuncSetAttribute(k_ffn2,    cudaFuncAttributeMaxDynamicSharedMemorySize, S_END);

    dim3 gg(HW / 64, B_);

    k_prep<<<216, 256>>>(e0_pw_w, proj_w, ffn1_w, ffn2_w);

    k_ln_e0pw<<<gg, 256, S_END>>>(x, ln_w, ln_b, e0_pw_b);

    dim3 gdw(16, C_, B_);
    k_dw<<<gdw, 512>>>(sweights, prompt,
                       e0_dw_w, e0_dw_b, e1_dw_w, e1_dw_b, e2_dw_w, e2_dw_b);

    k_proj<<<gg, 256, S_END>>>(x, proj_b);

    k_ffn1<<<gg, 256, S_END>>>(ffn1_b);

    k_ffn2<<<gg, 256, S_END>>>(ffn2_b, out);
}

// round 10
// speedup vs baseline: 1.4903x; 1.4903x over previous
#include <cuda_runtime.h>
#include <cuda_bf16.h>
#include <mma.h>
#include <math.h>
#include <stdint.h>

using namespace nvcuda;

#define B_ 4
#define C_ 96
#define H_ 256
#define W_ 256
#define HW (H_*W_)
#define LDA 104
#define LDW 72        // 64-px tile B row stride (bf16)

typedef __nv_bfloat16 bf16;

// Scratch (allocation-free rule: __device__ globals)
__device__ float g_xn[B_*C_*HW];
__device__ float g_e0[B_*C_*HW];
__device__ float g_xa[B_*C_*HW];
__device__ float g_x1[B_*C_*HW];
__device__ float g_h [B_*192*HW];

using FragA = wmma::fragment<wmma::matrix_a, 16, 16, 16, bf16, wmma::row_major>;
using FragB = wmma::fragment<wmma::matrix_b, 16, 16, 16, bf16, wmma::row_major>;
using FragC = wmma::fragment<wmma::accumulator, 16, 16, 16, float>;

__device__ __forceinline__ void split_bf16(float v, bf16& h, bf16& l) {
    h = __float2bfloat16_rn(v);
    l = __float2bfloat16_rn(v - __bfloat162float(h));
}

__device__ __forceinline__ unsigned pack2(bf16 a, bf16 b) {
    unsigned short ra = *reinterpret_cast<unsigned short*>(&a);
    unsigned short rb = *reinterpret_cast<unsigned short*>(&b);
    return (unsigned)ra | ((unsigned)rb << 16);
}

// Split-load a [96][96] f32 weight chunk (row stride rs) -> smem bf16 hi/lo [96][LDA]
__device__ __forceinline__ void load_w(const float* __restrict__ src, int rs,
                                       bf16* wsh, bf16* wsl, int t)
{
    for (int i = t; i < 2304; i += 256) {
        int m = i / 24, kk = (i % 24) * 4;
        float4 v = *(const float4*)(src + m * rs + kk);
        bf16 h0,l0,h1,l1,h2,l2,h3,l3;
        split_bf16(v.x, h0, l0); split_bf16(v.y, h1, l1);
        split_bf16(v.z, h2, l2); split_bf16(v.w, h3, l3);
        uint2 ph = make_uint2(pack2(h0,h1), pack2(h2,h3));
        uint2 pl = make_uint2(pack2(l0,l1), pack2(l2,l3));
        *(uint2*)(wsh + m * LDA + kk) = ph;
        *(uint2*)(wsl + m * LDA + kk) = pl;
    }
}

// Split-load activations tile [96 ch][64 px] (f32, stride HW) -> smem [96][LDW]
// 8 px per thread: 2 float4 loads, 2 uint2 stores per plane.
__device__ __forceinline__ void load_act(const float* __restrict__ src,
                                         bf16* xh, bf16* xl, int t)
{
    for (int i = t; i < 768; i += 256) {      // 96 rows x 8 px-groups
        int k = i >> 3, cc = (i & 7) * 8;
        const float* sp = src + (size_t)k * HW + cc;
        float4 v0 = *(const float4*)(sp);
        float4 v1 = *(const float4*)(sp + 4);
        bf16 h0,l0,h1,l1,h2,l2,h3,l3,h4,l4,h5,l5,h6,l6,h7,l7;
        split_bf16(v0.x,h0,l0); split_bf16(v0.y,h1,l1);
        split_bf16(v0.z,h2,l2); split_bf16(v0.w,h3,l3);
        split_bf16(v1.x,h4,l4); split_bf16(v1.y,h5,l5);
        split_bf16(v1.z,h6,l6); split_bf16(v1.w,h7,l7);
        uint2* ph = (uint2*)(xh + k * LDW + cc);
        uint2* pl = (uint2*)(xl + k * LDW + cc);
        ph[0] = make_uint2(pack2(h0,h1), pack2(h2,h3));
        ph[1] = make_uint2(pack2(h4,h5), pack2(h6,h7));
        pl[0] = make_uint2(pack2(l0,l1), pack2(l2,l3));
        pl[1] = make_uint2(pack2(l4,l5), pack2(l6,l7));
    }
}

// 3-pass GEMM: C[96 x 64] += A[96x96] * B[96x64]. 8 warps: wm 0..1, wn 0..3.
__device__ __forceinline__ void gemm3(
    const bf16* ah, const bf16* al, const bf16* bh, const bf16* bl,
    FragC (&acc)[3], int wm, int wn)
{
    #pragma unroll 1
    for (int k = 0; k < 6; k++) {
        FragB b_h, b_l;
        wmma::load_matrix_sync(b_h, bh + (k*16)*LDW + wn*16, LDW);
        wmma::load_matrix_sync(b_l, bl + (k*16)*LDW + wn*16, LDW);
        #pragma unroll
        for (int mf = 0; mf < 3; mf++) {
            FragA a_h, a_l;
            wmma::load_matrix_sync(a_h, ah + (wm*48 + mf*16)*LDA + k*16, LDA);
            wmma::load_matrix_sync(a_l, al + (wm*48 + mf*16)*LDA + k*16, LDA);
            wmma::mma_sync(acc[mf], a_h, b_h, acc[mf]);
            wmma::mma_sync(acc[mf], a_h, b_l, acc[mf]);
            wmma::mma_sync(acc[mf], a_l, b_h, acc[mf]);
        }
    }
}

__device__ __forceinline__ void zero3(FragC (&acc)[3]) {
    #pragma unroll
    for (int mf = 0; mf < 3; mf++) wmma::fill_fragment(acc[mf], 0.f);
}

// smem layout (bytes)
#define S_XSH 0
#define S_XSL 13824
#define S_WSH 27648
#define S_WSL 47616
#define S_PRM 67584
#define S_END (S_PRM + 4608)

// ---------------------------------------------------------------------------
// Kernel 1: LayerNorm (2-phase global read) + e0 pointwise -> g_xn, g_e0
// ---------------------------------------------------------------------------
__global__ __launch_bounds__(256, 3) void k_ln_e0pw(
    const float* __restrict__ x,
    const float* __restrict__ lnw, const float* __restrict__ lnb,
    const float* __restrict__ w, const float* __restrict__ bias)
{
    extern __shared__ unsigned char smraw[];
    bf16* xsh = (bf16*)(smraw + S_XSH);
    bf16* xsl = (bf16*)(smraw + S_XSL);
    bf16* wsh = (bf16*)(smraw + S_WSH);
    bf16* wsl = (bf16*)(smraw + S_WSL);
    float* stg = (float*)(smraw + S_WSH);        // aliases WSH after GEMM
    float* prm = (float*)(smraw + S_PRM);
    float* psum = prm;            // [8][64]
    float* psq  = prm + 512;      // [8][64]
    float* mu   = prm + 1024;
    float* inv  = prm + 1088;

    const int t = threadIdx.x, wid = t >> 5, lane = t & 31;
    const int b = blockIdx.y, p0 = blockIdx.x * 64;
    const float* xb = x + (size_t)b * C_ * HW + p0;

    load_w(w, 96, wsh, wsl, t);

    // stats: warp wid covers rows {wid, wid+8,...}, lane covers 2 px
    {
        const int c2 = lane * 2;
        float s0=0, s1=0, q0=0, q1=0;
        #pragma unroll 1
        for (int it = 0; it < 12; it++) {
            float2 v = *(const float2*)(xb + (size_t)(it * 8 + wid) * HW + c2);
            s0 += v.x; s1 += v.y; q0 += v.x*v.x; q1 += v.y*v.y;
        }
        psum[wid*64 + c2] = s0; psum[wid*64 + c2 + 1] = s1;
        psq [wid*64 + c2] = q0; psq [wid*64 + c2 + 1] = q1;
    }
    __syncthreads();
    if (t < 64) {
        float s = 0.f, q = 0.f;
        #pragma unroll
        for (int g = 0; g < 8; g++) { s += psum[g*64 + t]; q += psq[g*64 + t]; }
        float m = s * (1.f / 96.f);
        mu[t] = m;
        inv[t] = rsqrtf(q * (1.f / 96.f) - m * m + 1e-6f);
    }
    __syncthreads();

    // normalize (L2-hot re-read) + write xn (float4) + split to smem (uint2 x2)
    float* xnb = g_xn + (size_t)b * C_ * HW + p0;
    for (int i = t; i < 768; i += 256) {
        int k = i >> 3, cc = (i & 7) * 8;
        const float* sp = xb + (size_t)k * HW + cc;
        float4 v0 = *(const float4*)(sp);
        float4 v1 = *(const float4*)(sp + 4);
        float lw = __ldg(&lnw[k]), lb = __ldg(&lnb[k]);
        float o0 = (v0.x - mu[cc+0]) * inv[cc+0] * lw + lb;
        float o1 = (v0.y - mu[cc+1]) * inv[cc+1] * lw + lb;
        float o2 = (v0.z - mu[cc+2]) * inv[cc+2] * lw + lb;
        float o3 = (v0.w - mu[cc+3]) * inv[cc+3] * lw + lb;
        float o4 = (v1.x - mu[cc+4]) * inv[cc+4] * lw + lb;
        float o5 = (v1.y - mu[cc+5]) * inv[cc+5] * lw + lb;
        float o6 = (v1.z - mu[cc+6]) * inv[cc+6] * lw + lb;
        float o7 = (v1.w - mu[cc+7]) * inv[cc+7] * lw + lb;
        float* dp = xnb + (size_t)k * HW + cc;
        *(float4*)(dp)     = make_float4(o0, o1, o2, o3);
        *(float4*)(dp + 4) = make_float4(o4, o5, o6, o7);
        bf16 h0,l0,h1,l1,h2,l2,h3,l3,h4,l4,h5,l5,h6,l6,h7,l7;
        split_bf16(o0,h0,l0); split_bf16(o1,h1,l1);
        split_bf16(o2,h2,l2); split_bf16(o3,h3,l3);
        split_bf16(o4,h4,l4); split_bf16(o5,h5,l5);
        split_bf16(o6,h6,l6); split_bf16(o7,h7,l7);
        uint2* ph = (uint2*)(xsh + k * LDW + cc);
        uint2* pl = (uint2*)(xsl + k * LDW + cc);
        ph[0] = make_uint2(pack2(h0,h1), pack2(h2,h3));
        ph[1] = make_uint2(pack2(h4,h5), pack2(h6,h7));
        pl[0] = make_uint2(pack2(l0,l1), pack2(l2,l3));
        pl[1] = make_uint2(pack2(l4,l5), pack2(l6,l7));
    }
    __syncthreads();

    const int wm = wid >> 2, wn = wid & 3;
    FragC acc[3];
    zero3(acc);
    gemm3(wsh, wsl, xsh, xsl, acc, wm, wn);
    __syncthreads();                 // ws dead -> stg alias safe

    float* st = stg + wid * 256;
    float* gb = g_e0 + (size_t)b * C_ * HW + p0;
    const int r = lane >> 1, c8 = (lane & 1) * 8;
    #pragma unroll
    for (int mf = 0; mf < 3; mf++) {
        wmma::store_matrix_sync(st, acc[mf], 16, wmma::mem_row_major);
        __syncwarp();
        int mm = wm*48 + mf*16 + r;
        int pp = wn*16 + c8;
        float bb = __ldg(&bias[mm]);
        const float* sp = st + r*16 + c8;
        float4 s0 = *(const float4*)(sp);
        float4 s1 = *(const float4*)(sp + 4);
        float* gp = gb + (size_t)mm * HW + pp;
        *(float4*)(gp)     = make_float4(s0.x+bb, s0.y+bb, s0.z+bb, s0.w+bb);
        *(float4*)(gp + 4) = make_float4(s1.x+bb, s1.y+bb, s1.z+bb, s1.w+bb);
        __syncwarp();
    }
}

// ---------------------------------------------------------------------------
// Kernel 2: depthwise experts + mixing (64x64 tiles, 512 thr) — unchanged
// ---------------------------------------------------------------------------
__global__ __launch_bounds__(512, 2) void k_dw(
    const float* __restrict__ sw,
    const float* __restrict__ prompt,
    const float* __restrict__ w0, const float* __restrict__ b0,
    const float* __restrict__ w1, const float* __restrict__ b1,
    const float* __restrict__ w2, const float* __restrict__ b2)
{
    __shared__ float xs[76 * 77];
    __shared__ float es[66 * 67];
    __shared__ float kw[43];

    const int t = threadIdx.x;
    int c = blockIdx.y, b = blockIdx.z;
    int ty0 = (blockIdx.x >> 2) * 64;
    int tx0 = (blockIdx.x & 3) * 64;
    const float* xn = g_xn + ((size_t)(b * C_ + c)) * HW;
    const float* ep = g_e0 + ((size_t)(b * C_ + c)) * HW;

    for (int i = t; i < 76 * 76; i += 512) {
        int r = i / 76, cc = i % 76;
        int yy = ty0 - 6 + r, xx = tx0 - 6 + cc;
        xs[r * 77 + cc] = (yy >= 0 && yy < H_ && xx >= 0 && xx < W_) ? xn[yy * W_ + xx] : 0.f;
    }
    for (int i = t; i < 66 * 66; i += 512) {
        int r = i / 66, cc = i % 66;
        int yy = ty0 - 1 + r, xx = tx0 - 1 + cc;
        es[r * 67 + cc] = (yy >= 0 && yy < H_ && xx >= 0 && xx < W_) ? ep[yy * W_ + xx] : 0.f;
    }
    if (t < 43) {
        kw[t] = (t < 9) ? __ldg(&w0[c*9 + t])
              : (t < 18) ? __ldg(&w1[c*9 + t - 9])
              : __ldg(&w2[c*25 + t - 18]);
    }
    float bb0 = __ldg(&b0[c]), bb1 = __ldg(&b1[c]), bb2 = __ldg(&b2[c]);
    float s0 = __ldg(&sw[b*3+0]), s1 = __ldg(&sw[b*3+1]), s2 = __ldg(&sw[b*3+2]);
    float pm = 1.f + __ldg(&prompt[b * C_ + c]);
    __syncthreads();

    const int py = t >> 3, px0 = (t & 7) * 8;
    float o[8], r8[8];

    #pragma unroll
    for (int j = 0; j < 8; j++) r8[j] = bb0;
    #pragma unroll
    for (int ky = 0; ky < 3; ky++)
        #pragma unroll
        for (int kx = 0; kx < 3; kx++) {
            float wv = kw[ky*3 + kx];
            const float* rowp = es + (py + ky) * 67 + px0 + kx;
            #pragma unroll
            for (int j = 0; j < 8; j++) r8[j] += wv * rowp[j];
        }
    #pragma unroll
    for (int j = 0; j < 8; j++) o[j] = s0 * r8[j];

    #pragma unroll
    for (int j = 0; j < 8; j++) r8[j] = bb1;
    #pragma unroll
    for (int ky = 0; ky < 3; ky++)
        #pragma unroll
        for (int kx = 0; kx < 3; kx++) {
            float wv = kw[9 + ky*3 + kx];
            const float* rowp = xs + (py + 4 + 2*ky) * 77 + px0 + 4 + 2*kx;
            #pragma unroll
            for (int j = 0; j < 8; j++) r8[j] += wv * rowp[j];
        }
    #pragma unroll
    for (int j = 0; j < 8; j++) o[j] += s1 * r8[j];

    #pragma unroll
    for (int j = 0; j < 8; j++) r8[j] = bb2;
    #pragma unroll
    for (int ky = 0; ky < 5; ky++)
        #pragma unroll
        for (int kx = 0; kx < 5; kx++) {
            float wv = kw[18 + ky*5 + kx];
            const float* rowp = xs + (py + 3*ky) * 77 + px0 + 3*kx;
            #pragma unroll
            for (int j = 0; j < 8; j++) r8[j] += wv * rowp[j];
        }
    #pragma unroll
    for (int j = 0; j < 8; j++) o[j] = (o[j] + s2 * r8[j]) * pm;

    float* outp = g_xa + ((size_t)(b * C_ + c)) * HW + (ty0 + py) * W_ + tx0 + px0;
    *(float4*)(outp)     = make_float4(o[0], o[1], o[2], o[3]);
    *(float4*)(outp + 4) = make_float4(o[4], o[5], o[6], o[7]);
}

// ---------------------------------------------------------------------------
// Kernel 3: x1 = x + proj(xa) -> g_x1
// ---------------------------------------------------------------------------
__global__ __launch_bounds__(256, 3) void k_proj(
    const float* __restrict__ x,
    const float* __restrict__ w, const float* __restrict__ bias)
{
    extern __shared__ unsigned char smraw[];
    bf16* xsh = (bf16*)(smraw + S_XSH);
    bf16* xsl = (bf16*)(smraw + S_XSL);
    bf16* wsh = (bf16*)(smraw + S_WSH);
    bf16* wsl = (bf16*)(smraw + S_WSL);
    float* stg = (float*)(smraw + S_WSH);

    const int t = threadIdx.x, wid = t >> 5, lane = t & 31;
    const int b = blockIdx.y, p0 = blockIdx.x * 64;

    load_act(g_xa + (size_t)b * C_ * HW + p0, xsh, xsl, t);
    load_w(w, 96, wsh, wsl, t);
    __syncthreads();

    const int wm = wid >> 2, wn = wid & 3;
    FragC acc[3];
    zero3(acc);
    gemm3(wsh, wsl, xsh, xsl, acc, wm, wn);
    __syncthreads();

    float* st = stg + wid * 256;
    const float* rb = x   + (size_t)b * C_ * HW + p0;
    float* gb = g_x1 + (size_t)b * C_ * HW + p0;
    const int r = lane >> 1, c8 = (lane & 1) * 8;
    #pragma unroll
    for (int mf = 0; mf < 3; mf++) {
        wmma::store_matrix_sync(st, acc[mf], 16, wmma::mem_row_major);
        __syncwarp();
        int mm = wm*48 + mf*16 + r;
        int pp = wn*16 + c8;
        float bb = __ldg(&bias[mm]);
        const float* sp = st + r*16 + c8;
        const float* rp = rb + (size_t)mm * HW + pp;
        float4 s0 = *(const float4*)(sp);
        float4 s1 = *(const float4*)(sp + 4);
        float4 r0 = *(const float4*)(rp);
        float4 r1 = *(const float4*)(rp + 4);
        float* gp = gb + (size_t)mm * HW + pp;
        *(float4*)(gp)     = make_float4(s0.x+bb+r0.x, s0.y+bb+r0.y, s0.z+bb+r0.z, s0.w+bb+r0.w);
        *(float4*)(gp + 4) = make_float4(s1.x+bb+r1.x, s1.y+bb+r1.y, s1.z+bb+r1.z, s1.w+bb+r1.w);
        __syncwarp();
    }
}

// ---------------------------------------------------------------------------
// Kernel 4: h = gelu(ffn1(x1) + b1) -> g_h (f32, float4 stores)
// ---------------------------------------------------------------------------
__global__ __launch_bounds__(256, 3) void k_ffn1(
    const float* __restrict__ w1, const float* __restrict__ b1v)
{
    extern __shared__ unsigned char smraw[];
    bf16* xsh = (bf16*)(smraw + S_XSH);
    bf16* xsl = (bf16*)(smraw + S_XSL);
    bf16* wsh = (bf16*)(smraw + S_WSH);
    bf16* wsl = (bf16*)(smraw + S_WSL);
    float* stg = (float*)(smraw + S_WSH);

    const int t = threadIdx.x, wid = t >> 5, lane = t & 31;
    const int b = blockIdx.y, p0 = blockIdx.x * 64;

    load_act(g_x1 + (size_t)b * C_ * HW + p0, xsh, xsl, t);

    const int wm = wid >> 2, wn = wid & 3;
    const int r = lane >> 1, c8 = (lane & 1) * 8;
    float* st = stg + wid * 256;
    float* hb = g_h + (size_t)b * 192 * HW + p0;

    #pragma unroll 1
    for (int oc = 0; oc < 2; oc++) {
        __syncthreads();                       // xs ready / stg readers done
        load_w(w1 + oc * 9216, 96, wsh, wsl, t);
        __syncthreads();

        FragC acc[3];
        zero3(acc);
        gemm3(wsh, wsl, xsh, xsl, acc, wm, wn);
        __syncthreads();                       // ws dead -> stg alias

        #pragma unroll
        for (int mf = 0; mf < 3; mf++) {
            wmma::store_matrix_sync(st, acc[mf], 16, wmma::mem_row_major);
            __syncwarp();
            int k2 = oc*96 + wm*48 + mf*16 + r;
            int pp = wn*16 + c8;
            float bb = __ldg(&b1v[k2]);
            const float* sp = st + r*16 + c8;
            float4 s0 = *(const float4*)(sp);
            float4 s1 = *(const float4*)(sp + 4);
            float h0 = s0.x+bb, h1 = s0.y+bb, h2 = s0.z+bb, h3 = s0.w+bb;
            float h4 = s1.x+bb, h5 = s1.y+bb, h6 = s1.z+bb, h7 = s1.w+bb;
            float* gp = hb + (size_t)k2 * HW + pp;
            *(float4*)(gp)     = make_float4(h0*normcdff(h0), h1*normcdff(h1),
                                             h2*normcdff(h2), h3*normcdff(h3));
            *(float4*)(gp + 4) = make_float4(h4*normcdff(h4), h5*normcdff(h5),
                                             h6*normcdff(h6), h7*normcdff(h7));
            __syncwarp();
        }
    }
}

// ---------------------------------------------------------------------------
// Kernel 5: out = x1 + ffn2(h) + b2   (K=192 in two chunks)
// ---------------------------------------------------------------------------
__global__ __launch_bounds__(256, 3) void k_ffn2(
    const float* __restrict__ w2, const float* __restrict__ b2v,
    float* __restrict__ out)
{
    extern __shared__ unsigned char smraw[];
    bf16* hsh = (bf16*)(smraw + S_XSH);
    bf16* hsl = (bf16*)(smraw + S_XSL);
    bf16* wsh = (bf16*)(smraw + S_WSH);
    bf16* wsl = (bf16*)(smraw + S_WSL);
    float* stg = (float*)(smraw + S_WSH);

    const int t = threadIdx.x, wid = t >> 5, lane = t & 31;
    const int b = blockIdx.y, p0 = blockIdx.x * 64;
    const float* hb = g_h + (size_t)b * 192 * HW + p0;

    const int wm = wid >> 2, wn = wid & 3;
    FragC acc[3];
    zero3(acc);

    #pragma unroll 1
    for (int kc = 0; kc < 2; kc++) {
        if (kc) __syncthreads();               // prior readers done
        load_act(hb + (size_t)kc * 96 * HW, hsh, hsl, t);
        load_w(w2 + kc * 96, 192, wsh, wsl, t);
        __syncthreads();
        gemm3(wsh, wsl, hsh, hsl, acc, wm, wn);
    }
    __syncthreads();                           // ws dead -> stg alias

    float* st = stg + wid * 256;
    const float* x1b = g_x1 + (size_t)b * C_ * HW + p0;
    float* ob = out + (size_t)b * C_ * HW + p0;
    const int r = lane >> 1, c8 = (lane & 1) * 8;
    #pragma unroll
    for (int mf = 0; mf < 3; mf++) {
        wmma::store_matrix_sync(st, acc[mf], 16, wmma::mem_row_major);
        __syncwarp();
        int mm = wm*48 + mf*16 + r;
        int pp = wn*16 + c8;
        float bb = __ldg(&b2v[mm]);
        const float* sp = st + r*16 + c8;
        const float* rp = x1b + (size_t)mm * HW + pp;
        float4 s0 = *(const float4*)(sp);
        float4 s1 = *(const float4*)(sp + 4);
        float4 r0 = *(const float4*)(rp);
        float4 r1 = *(const float4*)(rp + 4);
        float* gp = ob + (size_t)mm * HW + pp;
        *(float4*)(gp)     = make_float4(s0.x+bb+r0.x, s0.y+bb+r0.y, s0.z+bb+r0.z, s0.w+bb+r0.w);
        *(float4*)(gp + 4) = make_float4(s1.x+bb+r1.x, s1.y+bb+r1.y, s1.z+bb+r1.z, s1.w+bb+r1.w);
        __syncwarp();
    }
}

// ---------------------------------------------------------------------------
extern "C" void kernel_launch(void* const* d_in, const int* in_sizes, int n_in,
                              void* d_out, int out_size)
{
    const float* x       = (const float*)d_in[0];
    const float* prompt  = (const float*)d_in[1];
    const float* sweights= (const float*)d_in[2];
    const float* ln_w    = (const float*)d_in[3];
    const float* ln_b    = (const float*)d_in[4];
    const float* e0_pw_w = (const float*)d_in[5];
    const float* e0_pw_b = (const float*)d_in[6];
    const float* e0_dw_w = (const float*)d_in[7];
    const float* e0_dw_b = (const float*)d_in[8];
    const float* e1_dw_w = (const float*)d_in[9];
    const float* e1_dw_b = (const float*)d_in[10];
    const float* e2_dw_w = (const float*)d_in[11];
    const float* e2_dw_b = (const float*)d_in[12];
    const float* proj_w  = (const float*)d_in[13];
    const float* proj_b  = (const float*)d_in[14];
    const float* ffn1_w  = (const float*)d_in[15];
    const float* ffn1_b  = (const float*)d_in[16];
    const float* ffn2_w  = (const float*)d_in[17];
    const float* ffn2_b  = (const float*)d_in[18];
    float* out = (float*)d_out;

    cudaFuncSetAttribute(k_ln_e0pw, cudaFuncAttributeMaxDynamicSharedMemorySize, S_END);
    cudaFuncSetAttribute(k_proj,    cudaFuncAttributeMaxDynamicSharedMemorySize, S_END);
    cudaFuncSetAttribute(k_ffn1,    cudaFuncAttributeMaxDynamicSharedMemorySize, S_END);
    cudaFuncSetAttribute(k_ffn2,    cudaFuncAttributeMaxDynamicSharedMemorySize, S_END);

    dim3 gg(HW / 64, B_);

    k_ln_e0pw<<<gg, 256, S_END>>>(x, ln_w, ln_b, e0_pw_w, e0_pw_b);

    dim3 gdw(16, C_, B_);
    k_dw<<<gdw, 512>>>(sweights, prompt,
                       e0_dw_w, e0_dw_b, e1_dw_w, e1_dw_b, e2_dw_w, e2_dw_b);

    k_proj<<<gg, 256, S_END>>>(x, proj_w, proj_b);

    k_ffn1<<<gg, 256, S_END>>>(ffn1_w, ffn1_b);

    k_ffn2<<<gg, 256, S_END>>>(ffn2_w, ffn2_b, out);
}

// round 11
// speedup vs baseline: 1.6084x; 1.0792x over previous
#include <cuda_runtime.h>
#include <cuda_bf16.h>
#include <mma.h>
#include <math.h>
#include <stdint.h>

using namespace nvcuda;

#define B_ 4
#define C_ 96
#define H_ 256
#define W_ 256
#define HW (H_*W_)
#define LDA 104
#define LDW 72        // 64-px tile B row stride (bf16)

typedef __nv_bfloat16 bf16;

// Scratch (allocation-free rule: __device__ globals)
__device__ bf16  g_xnb[B_*C_*HW];   // layernorm output (bf16, dw-only consumer)
__device__ bf16  g_e0b[B_*C_*HW];   // e0 pre-activation (bf16, dw-only consumer)
__device__ float g_xa[B_*C_*HW];
__device__ float g_x1[B_*C_*HW];
__device__ float g_h [B_*192*HW];

// Pre-split weights (hi/lo) in padded [96][LDA] smem-image layout
__device__ __align__(16) bf16 g_we0h[96*LDA],  g_we0l[96*LDA];
__device__ __align__(16) bf16 g_wpjh[96*LDA],  g_wpjl[96*LDA];
__device__ __align__(16) bf16 g_w1h[2*96*LDA], g_w1l[2*96*LDA];
__device__ __align__(16) bf16 g_w2h[2*96*LDA], g_w2l[2*96*LDA];

using FragA = wmma::fragment<wmma::matrix_a, 16, 16, 16, bf16, wmma::row_major>;
using FragB = wmma::fragment<wmma::matrix_b, 16, 16, 16, bf16, wmma::row_major>;
using FragC = wmma::fragment<wmma::accumulator, 16, 16, 16, float>;

__device__ __forceinline__ void split_bf16(float v, bf16& h, bf16& l) {
    h = __float2bfloat16_rn(v);
    l = __float2bfloat16_rn(v - __bfloat162float(h));
}

__device__ __forceinline__ unsigned pack2(bf16 a, bf16 b) {
    unsigned short ra = *reinterpret_cast<unsigned short*>(&a);
    unsigned short rb = *reinterpret_cast<unsigned short*>(&b);
    return (unsigned)ra | ((unsigned)rb << 16);
}

// Copy pre-split weight chunk ([96][LDA] bf16 x2) global(L2-hot) -> smem.
__device__ __forceinline__ void copy_w(const bf16* __restrict__ srch,
                                       const bf16* __restrict__ srcl,
                                       bf16* wsh, bf16* wsl, int t)
{
    const uint4* sh = (const uint4*)srch;
    const uint4* sl = (const uint4*)srcl;
    uint4* dh = (uint4*)wsh;
    uint4* dl = (uint4*)wsl;
    #pragma unroll
    for (int i = 0; i < 5; i++) {
        int j = t + i * 256;
        if (j < 1248) { dh[j] = sh[j]; dl[j] = sl[j]; }
    }
}

// Split-load activations tile [96 ch][64 px] (f32, stride HW) -> smem [96][LDW]
__device__ __forceinline__ void load_act(const float* __restrict__ src,
                                         bf16* xh, bf16* xl, int t)
{
    for (int i = t; i < 768; i += 256) {      // 96 rows x 8 px-groups
        int k = i >> 3, cc = (i & 7) * 8;
        const float* sp = src + (size_t)k * HW + cc;
        float4 v0 = *(const float4*)(sp);
        float4 v1 = *(const float4*)(sp + 4);
        bf16 h0,l0,h1,l1,h2,l2,h3,l3,h4,l4,h5,l5,h6,l6,h7,l7;
        split_bf16(v0.x,h0,l0); split_bf16(v0.y,h1,l1);
        split_bf16(v0.z,h2,l2); split_bf16(v0.w,h3,l3);
        split_bf16(v1.x,h4,l4); split_bf16(v1.y,h5,l5);
        split_bf16(v1.z,h6,l6); split_bf16(v1.w,h7,l7);
        uint2* ph = (uint2*)(xh + k * LDW + cc);
        uint2* pl = (uint2*)(xl + k * LDW + cc);
        ph[0] = make_uint2(pack2(h0,h1), pack2(h2,h3));
        ph[1] = make_uint2(pack2(h4,h5), pack2(h6,h7));
        pl[0] = make_uint2(pack2(l0,l1), pack2(l2,l3));
        pl[1] = make_uint2(pack2(l4,l5), pack2(l6,l7));
    }
}

// 3-pass GEMM: C[96 x 64] += A[96x96] * B[96x64]. 8 warps: wm 0..1, wn 0..3.
__device__ __forceinline__ void gemm3(
    const bf16* ah, const bf16* al, const bf16* bh, const bf16* bl,
    FragC (&acc)[3], int wm, int wn)
{
    #pragma unroll 1
    for (int k = 0; k < 6; k++) {
        FragB b_h, b_l;
        wmma::load_matrix_sync(b_h, bh + (k*16)*LDW + wn*16, LDW);
        wmma::load_matrix_sync(b_l, bl + (k*16)*LDW + wn*16, LDW);
        #pragma unroll
        for (int mf = 0; mf < 3; mf++) {
            FragA a_h, a_l;
            wmma::load_matrix_sync(a_h, ah + (wm*48 + mf*16)*LDA + k*16, LDA);
            wmma::load_matrix_sync(a_l, al + (wm*48 + mf*16)*LDA + k*16, LDA);
            wmma::mma_sync(acc[mf], a_h, b_h, acc[mf]);
            wmma::mma_sync(acc[mf], a_h, b_l, acc[mf]);
            wmma::mma_sync(acc[mf], a_l, b_h, acc[mf]);
        }
    }
}

__device__ __forceinline__ void zero3(FragC (&acc)[3]) {
    #pragma unroll
    for (int mf = 0; mf < 3; mf++) wmma::fill_fragment(acc[mf], 0.f);
}

// smem layout (bytes)
#define S_XSH 0
#define S_XSL 13824
#define S_WSH 27648
#define S_WSL 47616
#define S_PRM 67584
#define S_END (S_PRM + 4608)

// ---------------------------------------------------------------------------
// Weight prep: f32 -> bf16 hi/lo in padded layouts (once per launch, 216 blocks)
// ---------------------------------------------------------------------------
__global__ void k_prep(const float* __restrict__ e0, const float* __restrict__ pj,
                       const float* __restrict__ w1, const float* __restrict__ w2)
{
    int i = blockIdx.x * 256 + threadIdx.x;
    float v; bf16 *dh, *dl; int off;
    if (i < 9216) {
        int m = i / 96, k = i % 96;
        v = e0[i]; dh = g_we0h; dl = g_we0l; off = m * LDA + k;
    } else if (i < 18432) {
        int j = i - 9216; int m = j / 96, k = j % 96;
        v = pj[j]; dh = g_wpjh; dl = g_wpjl; off = m * LDA + k;
    } else if (i < 36864) {
        int j = i - 18432; int m = j / 96, k = j % 96;     // m 0..191
        v = w1[j]; dh = g_w1h; dl = g_w1l;
        off = (m / 96) * 96 * LDA + (m % 96) * LDA + k;
    } else if (i < 55296) {
        int j = i - 36864; int m = j / 192, k = j % 192;   // w2 [96][192]
        v = w2[j]; dh = g_w2h; dl = g_w2l;
        off = (k / 96) * 96 * LDA + m * LDA + (k % 96);
    } else return;
    bf16 h, l; split_bf16(v, h, l);
    dh[off] = h; dl[off] = l;
}

// ---------------------------------------------------------------------------
// Kernel 1: LayerNorm (2-phase global read) + e0 pointwise -> g_xnb, g_e0b
// ---------------------------------------------------------------------------
__global__ __launch_bounds__(256, 3) void k_ln_e0pw(
    const float* __restrict__ x,
    const float* __restrict__ lnw, const float* __restrict__ lnb,
    const float* __restrict__ bias)
{
    extern __shared__ unsigned char smraw[];
    bf16* xsh = (bf16*)(smraw + S_XSH);
    bf16* xsl = (bf16*)(smraw + S_XSL);
    bf16* wsh = (bf16*)(smraw + S_WSH);
    bf16* wsl = (bf16*)(smraw + S_WSL);
    float* stg = (float*)(smraw + S_WSH);        // aliases WSH after GEMM
    float* prm = (float*)(smraw + S_PRM);
    float* psum = prm;            // [8][64]
    float* psq  = prm + 512;      // [8][64]
    float* mu   = prm + 1024;
    float* inv  = prm + 1088;

    const int t = threadIdx.x, wid = t >> 5, lane = t & 31;
    const int b = blockIdx.y, p0 = blockIdx.x * 64;
    const float* xb = x + (size_t)b * C_ * HW + p0;

    copy_w(g_we0h, g_we0l, wsh, wsl, t);

    // stats: warp wid covers rows {wid, wid+8,...}, lane covers 2 px
    {
        const int c2 = lane * 2;
        float s0=0, s1=0, q0=0, q1=0;
        #pragma unroll 1
        for (int it = 0; it < 12; it++) {
            float2 v = *(const float2*)(xb + (size_t)(it * 8 + wid) * HW + c2);
            s0 += v.x; s1 += v.y; q0 += v.x*v.x; q1 += v.y*v.y;
        }
        psum[wid*64 + c2] = s0; psum[wid*64 + c2 + 1] = s1;
        psq [wid*64 + c2] = q0; psq [wid*64 + c2 + 1] = q1;
    }
    __syncthreads();
    if (t < 64) {
        float s = 0.f, q = 0.f;
        #pragma unroll
        for (int g = 0; g < 8; g++) { s += psum[g*64 + t]; q += psq[g*64 + t]; }
        float m = s * (1.f / 96.f);
        mu[t] = m;
        inv[t] = rsqrtf(q * (1.f / 96.f) - m * m + 1e-6f);
    }
    __syncthreads();

    // normalize (L2-hot re-read) + write xn (bf16 uint4) + split to smem
    bf16* xnb = g_xnb + (size_t)b * C_ * HW + p0;
    for (int i = t; i < 768; i += 256) {
        int k = i >> 3, cc = (i & 7) * 8;
        const float* sp = xb + (size_t)k * HW + cc;
        float4 v0 = *(const float4*)(sp);
        float4 v1 = *(const float4*)(sp + 4);
        float lw = __ldg(&lnw[k]), lb = __ldg(&lnb[k]);
        float o0 = (v0.x - mu[cc+0]) * inv[cc+0] * lw + lb;
        float o1 = (v0.y - mu[cc+1]) * inv[cc+1] * lw + lb;
        float o2 = (v0.z - mu[cc+2]) * inv[cc+2] * lw + lb;
        float o3 = (v0.w - mu[cc+3]) * inv[cc+3] * lw + lb;
        float o4 = (v1.x - mu[cc+4]) * inv[cc+4] * lw + lb;
        float o5 = (v1.y - mu[cc+5]) * inv[cc+5] * lw + lb;
        float o6 = (v1.z - mu[cc+6]) * inv[cc+6] * lw + lb;
        float o7 = (v1.w - mu[cc+7]) * inv[cc+7] * lw + lb;
        bf16 h0,l0,h1,l1,h2,l2,h3,l3,h4,l4,h5,l5,h6,l6,h7,l7;
        split_bf16(o0,h0,l0); split_bf16(o1,h1,l1);
        split_bf16(o2,h2,l2); split_bf16(o3,h3,l3);
        split_bf16(o4,h4,l4); split_bf16(o5,h5,l5);
        split_bf16(o6,h6,l6); split_bf16(o7,h7,l7);
        // xn to global as single bf16 (hi part is the rn-rounded value)
        *(uint4*)(xnb + (size_t)k * HW + cc) =
            make_uint4(pack2(h0,h1), pack2(h2,h3), pack2(h4,h5), pack2(h6,h7));
        uint2* ph = (uint2*)(xsh + k * LDW + cc);
        uint2* pl = (uint2*)(xsl + k * LDW + cc);
        ph[0] = make_uint2(pack2(h0,h1), pack2(h2,h3));
        ph[1] = make_uint2(pack2(h4,h5), pack2(h6,h7));
        pl[0] = make_uint2(pack2(l0,l1), pack2(l2,l3));
        pl[1] = make_uint2(pack2(l4,l5), pack2(l6,l7));
    }
    __syncthreads();

    const int wm = wid >> 2, wn = wid & 3;
    FragC acc[3];
    zero3(acc);
    gemm3(wsh, wsl, xsh, xsl, acc, wm, wn);
    __syncthreads();                 // ws dead -> stg alias safe

    float* st = stg + wid * 256;
    bf16* gb = g_e0b + (size_t)b * C_ * HW + p0;
    const int r = lane >> 1, c8 = (lane & 1) * 8;
    #pragma unroll
    for (int mf = 0; mf < 3; mf++) {
        wmma::store_matrix_sync(st, acc[mf], 16, wmma::mem_row_major);
        __syncwarp();
        int mm = wm*48 + mf*16 + r;
        int pp = wn*16 + c8;
        float bb = __ldg(&bias[mm]);
        const float* sp = st + r*16 + c8;
        float4 s0 = *(const float4*)(sp);
        float4 s1 = *(const float4*)(sp + 4);
        bf16 e0 = __float2bfloat16_rn(s0.x+bb), e1 = __float2bfloat16_rn(s0.y+bb);
        bf16 e2 = __float2bfloat16_rn(s0.z+bb), e3 = __float2bfloat16_rn(s0.w+bb);
        bf16 e4 = __float2bfloat16_rn(s1.x+bb), e5 = __float2bfloat16_rn(s1.y+bb);
        bf16 e6 = __float2bfloat16_rn(s1.z+bb), e7 = __float2bfloat16_rn(s1.w+bb);
        *(uint4*)(gb + (size_t)mm * HW + pp) =
            make_uint4(pack2(e0,e1), pack2(e2,e3), pack2(e4,e5), pack2(e6,e7));
        __syncwarp();
    }
}

// ---------------------------------------------------------------------------
// Kernel 2: depthwise experts + mixing (64x64 tiles, 512 thr), bf16 inputs
// ---------------------------------------------------------------------------
__global__ __launch_bounds__(512, 2) void k_dw(
    const float* __restrict__ sw,
    const float* __restrict__ prompt,
    const float* __restrict__ w0, const float* __restrict__ b0,
    const float* __restrict__ w1, const float* __restrict__ b1,
    const float* __restrict__ w2, const float* __restrict__ b2)
{
    __shared__ float xs[76 * 77];
    __shared__ float es[66 * 67];
    __shared__ float kw[43];

    const int t = threadIdx.x;
    int c = blockIdx.y, b = blockIdx.z;
    int ty0 = (blockIdx.x >> 2) * 64;
    int tx0 = (blockIdx.x & 3) * 64;
    const bf16* xn = g_xnb + ((size_t)(b * C_ + c)) * HW;
    const bf16* ep = g_e0b + ((size_t)(b * C_ + c)) * HW;

    for (int i = t; i < 76 * 76; i += 512) {
        int r = i / 76, cc = i % 76;
        int yy = ty0 - 6 + r, xx = tx0 - 6 + cc;
        xs[r * 77 + cc] = (yy >= 0 && yy < H_ && xx >= 0 && xx < W_)
                        ? __bfloat162float(xn[yy * W_ + xx]) : 0.f;
    }
    for (int i = t; i < 66 * 66; i += 512) {
        int r = i / 66, cc = i % 66;
        int yy = ty0 - 1 + r, xx = tx0 - 1 + cc;
        es[r * 67 + cc] = (yy >= 0 && yy < H_ && xx >= 0 && xx < W_)
                        ? __bfloat162float(ep[yy * W_ + xx]) : 0.f;
    }
    if (t < 43) {
        kw[t] = (t < 9) ? __ldg(&w0[c*9 + t])
              : (t < 18) ? __ldg(&w1[c*9 + t - 9])
              : __ldg(&w2[c*25 + t - 18]);
    }
    float bb0 = __ldg(&b0[c]), bb1 = __ldg(&b1[c]), bb2 = __ldg(&b2[c]);
    float s0 = __ldg(&sw[b*3+0]), s1 = __ldg(&sw[b*3+1]), s2 = __ldg(&sw[b*3+2]);
    float pm = 1.f + __ldg(&prompt[b * C_ + c]);
    __syncthreads();

    const int py = t >> 3, px0 = (t & 7) * 8;
    float o[8], r8[8];

    #pragma unroll
    for (int j = 0; j < 8; j++) r8[j] = bb0;
    #pragma unroll
    for (int ky = 0; ky < 3; ky++)
        #pragma unroll
        for (int kx = 0; kx < 3; kx++) {
            float wv = kw[ky*3 + kx];
            const float* rowp = es + (py + ky) * 67 + px0 + kx;
            #pragma unroll
            for (int j = 0; j < 8; j++) r8[j] += wv * rowp[j];
        }
    #pragma unroll
    for (int j = 0; j < 8; j++) o[j] = s0 * r8[j];

    #pragma unroll
    for (int j = 0; j < 8; j++) r8[j] = bb1;
    #pragma unroll
    for (int ky = 0; ky < 3; ky++)
        #pragma unroll
        for (int kx = 0; kx < 3; kx++) {
            float wv = kw[9 + ky*3 + kx];
            const float* rowp = xs + (py + 4 + 2*ky) * 77 + px0 + 4 + 2*kx;
            #pragma unroll
            for (int j = 0; j < 8; j++) r8[j] += wv * rowp[j];
        }
    #pragma unroll
    for (int j = 0; j < 8; j++) o[j] += s1 * r8[j];

    #pragma unroll
    for (int j = 0; j < 8; j++) r8[j] = bb2;
    #pragma unroll
    for (int ky = 0; ky < 5; ky++)
        #pragma unroll
        for (int kx = 0; kx < 5; kx++) {
            float wv = kw[18 + ky*5 + kx];
            const float* rowp = xs + (py + 3*ky) * 77 + px0 + 3*kx;
            #pragma unroll
            for (int j = 0; j < 8; j++) r8[j] += wv * rowp[j];
        }
    #pragma unroll
    for (int j = 0; j < 8; j++) o[j] = (o[j] + s2 * r8[j]) * pm;

    float* outp = g_xa + ((size_t)(b * C_ + c)) * HW + (ty0 + py) * W_ + tx0 + px0;
    *(float4*)(outp)     = make_float4(o[0], o[1], o[2], o[3]);
    *(float4*)(outp + 4) = make_float4(o[4], o[5], o[6], o[7]);
}

// ---------------------------------------------------------------------------
// Kernel 3: x1 = x + proj(xa) -> g_x1
// ---------------------------------------------------------------------------
__global__ __launch_bounds__(256, 3) void k_proj(
    const float* __restrict__ x, const float* __restrict__ bias)
{
    extern __shared__ unsigned char smraw[];
    bf16* xsh = (bf16*)(smraw + S_XSH);
    bf16* xsl = (bf16*)(smraw + S_XSL);
    bf16* wsh = (bf16*)(smraw + S_WSH);
    bf16* wsl = (bf16*)(smraw + S_WSL);
    float* stg = (float*)(smraw + S_WSH);

    const int t = threadIdx.x, wid = t >> 5, lane = t & 31;
    const int b = blockIdx.y, p0 = blockIdx.x * 64;

    load_act(g_xa + (size_t)b * C_ * HW + p0, xsh, xsl, t);
    copy_w(g_wpjh, g_wpjl, wsh, wsl, t);
    __syncthreads();

    const int wm = wid >> 2, wn = wid & 3;
    FragC acc[3];
    zero3(acc);
    gemm3(wsh, wsl, xsh, xsl, acc, wm, wn);
    __syncthreads();

    float* st = stg + wid * 256;
    const float* rb = x   + (size_t)b * C_ * HW + p0;
    float* gb = g_x1 + (size_t)b * C_ * HW + p0;
    const int r = lane >> 1, c8 = (lane & 1) * 8;
    #pragma unroll
    for (int mf = 0; mf < 3; mf++) {
        wmma::store_matrix_sync(st, acc[mf], 16, wmma::mem_row_major);
        __syncwarp();
        int mm = wm*48 + mf*16 + r;
        int pp = wn*16 + c8;
        float bb = __ldg(&bias[mm]);
        const float* sp = st + r*16 + c8;
        const float* rp = rb + (size_t)mm * HW + pp;
        float4 s0 = *(const float4*)(sp);
        float4 s1 = *(const float4*)(sp + 4);
        float4 r0 = *(const float4*)(rp);
        float4 r1 = *(const float4*)(rp + 4);
        float* gp = gb + (size_t)mm * HW + pp;
        *(float4*)(gp)     = make_float4(s0.x+bb+r0.x, s0.y+bb+r0.y, s0.z+bb+r0.z, s0.w+bb+r0.w);
        *(float4*)(gp + 4) = make_float4(s1.x+bb+r1.x, s1.y+bb+r1.y, s1.z+bb+r1.z, s1.w+bb+r1.w);
        __syncwarp();
    }
}

// ---------------------------------------------------------------------------
// Kernel 4: h = gelu(ffn1(x1) + b1) -> g_h (f32, float4 stores)
// ---------------------------------------------------------------------------
__global__ __launch_bounds__(256, 3) void k_ffn1(const float* __restrict__ b1v)
{
    extern __shared__ unsigned char smraw[];
    bf16* xsh = (bf16*)(smraw + S_XSH);
    bf16* xsl = (bf16*)(smraw + S_XSL);
    bf16* wsh = (bf16*)(smraw + S_WSH);
    bf16* wsl = (bf16*)(smraw + S_WSL);
    float* stg = (float*)(smraw + S_WSH);

    const int t = threadIdx.x, wid = t >> 5, lane = t & 31;
    const int b = blockIdx.y, p0 = blockIdx.x * 64;

    load_act(g_x1 + (size_t)b * C_ * HW + p0, xsh, xsl, t);

    const int wm = wid >> 2, wn = wid & 3;
    const int r = lane >> 1, c8 = (lane & 1) * 8;
    float* st = stg + wid * 256;
    float* hb = g_h + (size_t)b * 192 * HW + p0;

    #pragma unroll 1
    for (int oc = 0; oc < 2; oc++) {
        __syncthreads();                       // xs ready / stg readers done
        copy_w(g_w1h + oc * 96 * LDA, g_w1l + oc * 96 * LDA, wsh, wsl, t);
        __syncthreads();

        FragC acc[3];
        zero3(acc);
        gemm3(wsh, wsl, xsh, xsl, acc, wm, wn);
        __syncthreads();                       // ws dead -> stg alias

        #pragma unroll
        for (int mf = 0; mf < 3; mf++) {
            wmma::store_matrix_sync(st, acc[mf], 16, wmma::mem_row_major);
            __syncwarp();
            int k2 = oc*96 + wm*48 + mf*16 + r;
            int pp = wn*16 + c8;
            float bb = __ldg(&b1v[k2]);
            const float* sp = st + r*16 + c8;
            float4 s0 = *(const float4*)(sp);
            float4 s1 = *(const float4*)(sp + 4);
            float h0 = s0.x+bb, h1 = s0.y+bb, h2 = s0.z+bb, h3 = s0.w+bb;
            float h4 = s1.x+bb, h5 = s1.y+bb, h6 = s1.z+bb, h7 = s1.w+bb;
            float* gp = hb + (size_t)k2 * HW + pp;
            *(float4*)(gp)     = make_float4(h0*normcdff(h0), h1*normcdff(h1),
                                             h2*normcdff(h2), h3*normcdff(h3));
            *(float4*)(gp + 4) = make_float4(h4*normcdff(h4), h5*normcdff(h5),
                                             h6*normcdff(h6), h7*normcdff(h7));
            __syncwarp();
        }
    }
}

// ---------------------------------------------------------------------------
// Kernel 5: out = x1 + ffn2(h) + b2   (K=192 in two chunks)
// ---------------------------------------------------------------------------
__global__ __launch_bounds__(256, 3) void k_ffn2(
    const float* __restrict__ b2v, float* __restrict__ out)
{
    extern __shared__ unsigned char smraw[];
    bf16* hsh = (bf16*)(smraw + S_XSH);
    bf16* hsl = (bf16*)(smraw + S_XSL);
    bf16* wsh = (bf16*)(smraw + S_WSH);
    bf16* wsl = (bf16*)(smraw + S_WSL);
    float* stg = (float*)(smraw + S_WSH);

    const int t = threadIdx.x, wid = t >> 5, lane = t & 31;
    const int b = blockIdx.y, p0 = blockIdx.x * 64;
    const float* hb = g_h + (size_t)b * 192 * HW + p0;

    const int wm = wid >> 2, wn = wid & 3;
    FragC acc[3];
    zero3(acc);

    #pragma unroll 1
    for (int kc = 0; kc < 2; kc++) {
        if (kc) __syncthreads();               // prior readers done
        load_act(hb + (size_t)kc * 96 * HW, hsh, hsl, t);
        copy_w(g_w2h + kc * 96 * LDA, g_w2l + kc * 96 * LDA, wsh, wsl, t);
        __syncthreads();
        gemm3(wsh, wsl, hsh, hsl, acc, wm, wn);
    }
    __syncthreads();                           // ws dead -> stg alias

    float* st = stg + wid * 256;
    const float* x1b = g_x1 + (size_t)b * C_ * HW + p0;
    float* ob = out + (size_t)b * C_ * HW + p0;
    const int r = lane >> 1, c8 = (lane & 1) * 8;
    #pragma unroll
    for (int mf = 0; mf < 3; mf++) {
        wmma::store_matrix_sync(st, acc[mf], 16, wmma::mem_row_major);
        __syncwarp();
        int mm = wm*48 + mf*16 + r;
        int pp = wn*16 + c8;
        float bb = __ldg(&b2v[mm]);
        const float* sp = st + r*16 + c8;
        const float* rp = x1b + (size_t)mm * HW + pp;
        float4 s0 = *(const float4*)(sp);
        float4 s1 = *(const float4*)(sp + 4);
        float4 r0 = *(const float4*)(rp);
        float4 r1 = *(const float4*)(rp + 4);
        float* gp = ob + (size_t)mm * HW + pp;
        *(float4*)(gp)     = make_float4(s0.x+bb+r0.x, s0.y+bb+r0.y, s0.z+bb+r0.z, s0.w+bb+r0.w);
        *(float4*)(gp + 4) = make_float4(s1.x+bb+r1.x, s1.y+bb+r1.y, s1.z+bb+r1.z, s1.w+bb+r1.w);
        __syncwarp();
    }
}

// ---------------------------------------------------------------------------
extern "C" void kernel_launch(void* const* d_in, const int* in_sizes, int n_in,
                              void* d_out, int out_size)
{
    const float* x       = (const float*)d_in[0];
    const float* prompt  = (const float*)d_in[1];
    const float* sweights= (const float*)d_in[2];
    const float* ln_w    = (const float*)d_in[3];
    const float* ln_b    = (const float*)d_in[4];
    const float* e0_pw_w = (const float*)d_in[5];
    const float* e0_pw_b = (const float*)d_in[6];
    const float* e0_dw_w = (const float*)d_in[7];
    const float* e0_dw_b = (const float*)d_in[8];
    const float* e1_dw_w = (const float*)d_in[9];
    const float* e1_dw_b = (const float*)d_in[10];
    const float* e2_dw_w = (const float*)d_in[11];
    const float* e2_dw_b = (const float*)d_in[12];
    const float* proj_w  = (const float*)d_in[13];
    const float* proj_b  = (const float*)d_in[14];
    const float* ffn1_w  = (const float*)d_in[15];
    const float* ffn1_b  = (const float*)d_in[16];
    const float* ffn2_w  = (const float*)d_in[17];
    const float* ffn2_b  = (const float*)d_in[18];
    float* out = (float*)d_out;

    cudaFuncSetAttribute(k_ln_e0pw, cudaFuncAttributeMaxDynamicSharedMemorySize, S_END);
    cudaFuncSetAttribute(k_proj,    cudaFuncAttributeMaxDynamicSharedMemorySize, S_END);
    cudaFuncSetAttribute(k_ffn1,    cudaFuncAttributeMaxDynamicSharedMemorySize, S_END);
    cudaFuncSetAttribute(k_ffn2,    cudaFuncAttributeMaxDynamicSharedMemorySize, S_END);

    dim3 gg(HW / 64, B_);

    k_prep<<<216, 256>>>(e0_pw_w, proj_w, ffn1_w, ffn2_w);

    k_ln_e0pw<<<gg, 256, S_END>>>(x, ln_w, ln_b, e0_pw_b);

    dim3 gdw(16, C_, B_);
    k_dw<<<gdw, 512>>>(sweights, prompt,
                       e0_dw_w, e0_dw_b, e1_dw_w, e1_dw_b, e2_dw_w, e2_dw_b);

    k_proj<<<gg, 256, S_END>>>(x, proj_b);

    k_ffn1<<<gg, 256, S_END>>>(ffn1_b);

    k_ffn2<<<gg, 256, S_END>>>(ffn2_b, out);
}

// round 12
// speedup vs baseline: 1.6787x; 1.0437x over previous
#include <cuda_runtime.h>
#include <cuda_bf16.h>
#include <mma.h>
#include <math.h>
#include <stdint.h>

using namespace nvcuda;

#define B_ 4
#define C_ 96
#define H_ 256
#define W_ 256
#define HW (H_*W_)
#define LDA 104
#define LDW 72        // 64-px tile B row stride (bf16)

typedef __nv_bfloat16 bf16;

// Scratch (allocation-free rule: __device__ globals)
__device__ bf16  g_xnb[B_*C_*HW];   // layernorm output (bf16, dw-only consumer)
__device__ bf16  g_e0b[B_*C_*HW];   // e0 pre-activation (bf16, dw-only consumer)
__device__ float g_xa[B_*C_*HW];
__device__ float g_x1[B_*C_*HW];
__device__ bf16  g_hb[B_*192*HW];   // gelu(h), single bf16

// Pre-split weights (hi/lo) in padded [96][LDA] smem-image layout
__device__ __align__(16) bf16 g_we0h[96*LDA],  g_we0l[96*LDA];
__device__ __align__(16) bf16 g_wpjh[96*LDA],  g_wpjl[96*LDA];
__device__ __align__(16) bf16 g_w1h[2*96*LDA], g_w1l[2*96*LDA];
__device__ __align__(16) bf16 g_w2h[2*96*LDA], g_w2l[2*96*LDA];

using FragA = wmma::fragment<wmma::matrix_a, 16, 16, 16, bf16, wmma::row_major>;
using FragB = wmma::fragment<wmma::matrix_b, 16, 16, 16, bf16, wmma::row_major>;
using FragC = wmma::fragment<wmma::accumulator, 16, 16, 16, float>;

__device__ __forceinline__ void split_bf16(float v, bf16& h, bf16& l) {
    h = __float2bfloat16_rn(v);
    l = __float2bfloat16_rn(v - __bfloat162float(h));
}

__device__ __forceinline__ unsigned pack2(bf16 a, bf16 b) {
    unsigned short ra = *reinterpret_cast<unsigned short*>(&a);
    unsigned short rb = *reinterpret_cast<unsigned short*>(&b);
    return (unsigned)ra | ((unsigned)rb << 16);
}

// Copy pre-split weight chunk ([96][LDA] bf16 x2) global(L2-hot) -> smem.
__device__ __forceinline__ void copy_w(const bf16* __restrict__ srch,
                                       const bf16* __restrict__ srcl,
                                       bf16* wsh, bf16* wsl, int t)
{
    const uint4* sh = (const uint4*)srch;
    const uint4* sl = (const uint4*)srcl;
    uint4* dh = (uint4*)wsh;
    uint4* dl = (uint4*)wsl;
    #pragma unroll
    for (int i = 0; i < 5; i++) {
        int j = t + i * 256;
        if (j < 1248) { dh[j] = sh[j]; dl[j] = sl[j]; }
    }
}

// Split-load activations tile [96 ch][64 px] (f32, stride HW) -> smem [96][LDW]
__device__ __forceinline__ void load_act(const float* __restrict__ src,
                                         bf16* xh, bf16* xl, int t)
{
    for (int i = t; i < 768; i += 256) {      // 96 rows x 8 px-groups
        int k = i >> 3, cc = (i & 7) * 8;
        const float* sp = src + (size_t)k * HW + cc;
        float4 v0 = *(const float4*)(sp);
        float4 v1 = *(const float4*)(sp + 4);
        bf16 h0,l0,h1,l1,h2,l2,h3,l3,h4,l4,h5,l5,h6,l6,h7,l7;
        split_bf16(v0.x,h0,l0); split_bf16(v0.y,h1,l1);
        split_bf16(v0.z,h2,l2); split_bf16(v0.w,h3,l3);
        split_bf16(v1.x,h4,l4); split_bf16(v1.y,h5,l5);
        split_bf16(v1.z,h6,l6); split_bf16(v1.w,h7,l7);
        uint2* ph = (uint2*)(xh + k * LDW + cc);
        uint2* pl = (uint2*)(xl + k * LDW + cc);
        ph[0] = make_uint2(pack2(h0,h1), pack2(h2,h3));
        ph[1] = make_uint2(pack2(h4,h5), pack2(h6,h7));
        pl[0] = make_uint2(pack2(l0,l1), pack2(l2,l3));
        pl[1] = make_uint2(pack2(l4,l5), pack2(l6,l7));
    }
}

// 3-pass GEMM: C[96 x 64] += A[96x96] * B[96x64]. 8 warps: wm 0..1, wn 0..3.
__device__ __forceinline__ void gemm3(
    const bf16* ah, const bf16* al, const bf16* bh, const bf16* bl,
    FragC (&acc)[3], int wm, int wn)
{
    #pragma unroll 1
    for (int k = 0; k < 6; k++) {
        FragB b_h, b_l;
        wmma::load_matrix_sync(b_h, bh + (k*16)*LDW + wn*16, LDW);
        wmma::load_matrix_sync(b_l, bl + (k*16)*LDW + wn*16, LDW);
        #pragma unroll
        for (int mf = 0; mf < 3; mf++) {
            FragA a_h, a_l;
            wmma::load_matrix_sync(a_h, ah + (wm*48 + mf*16)*LDA + k*16, LDA);
            wmma::load_matrix_sync(a_l, al + (wm*48 + mf*16)*LDA + k*16, LDA);
            wmma::mma_sync(acc[mf], a_h, b_h, acc[mf]);
            wmma::mma_sync(acc[mf], a_h, b_l, acc[mf]);
            wmma::mma_sync(acc[mf], a_l, b_h, acc[mf]);
        }
    }
}

// 2-pass GEMM (B single-plane): C += (Ah + Al) * B
__device__ __forceinline__ void gemm2(
    const bf16* ah, const bf16* al, const bf16* b,
    FragC (&acc)[3], int wm, int wn)
{
    #pragma unroll 1
    for (int k = 0; k < 6; k++) {
        FragB bf;
        wmma::load_matrix_sync(bf, b + (k*16)*LDW + wn*16, LDW);
        #pragma unroll
        for (int mf = 0; mf < 3; mf++) {
            FragA a_h, a_l;
            wmma::load_matrix_sync(a_h, ah + (wm*48 + mf*16)*LDA + k*16, LDA);
            wmma::load_matrix_sync(a_l, al + (wm*48 + mf*16)*LDA + k*16, LDA);
            wmma::mma_sync(acc[mf], a_h, bf, acc[mf]);
            wmma::mma_sync(acc[mf], a_l, bf, acc[mf]);
        }
    }
}

__device__ __forceinline__ void zero3(FragC (&acc)[3]) {
    #pragma unroll
    for (int mf = 0; mf < 3; mf++) wmma::fill_fragment(acc[mf], 0.f);
}

// smem layout (bytes)
#define S_XSH 0
#define S_XSL 13824
#define S_WSH 27648
#define S_WSL 47616
#define S_PRM 67584
#define S_END (S_PRM + 4608)

// ---------------------------------------------------------------------------
// Weight prep: f32 -> bf16 hi/lo in padded layouts (once per launch)
// ---------------------------------------------------------------------------
__global__ void k_prep(const float* __restrict__ e0, const float* __restrict__ pj,
                       const float* __restrict__ w1, const float* __restrict__ w2)
{
    int i = blockIdx.x * 256 + threadIdx.x;
    float v; bf16 *dh, *dl; int off;
    if (i < 9216) {
        int m = i / 96, k = i % 96;
        v = e0[i]; dh = g_we0h; dl = g_we0l; off = m * LDA + k;
    } else if (i < 18432) {
        int j = i - 9216; int m = j / 96, k = j % 96;
        v = pj[j]; dh = g_wpjh; dl = g_wpjl; off = m * LDA + k;
    } else if (i < 36864) {
        int j = i - 18432; int m = j / 96, k = j % 96;     // m 0..191
        v = w1[j]; dh = g_w1h; dl = g_w1l;
        off = (m / 96) * 96 * LDA + (m % 96) * LDA + k;
    } else if (i < 55296) {
        int j = i - 36864; int m = j / 192, k = j % 192;   // w2 [96][192]
        v = w2[j]; dh = g_w2h; dl = g_w2l;
        off = (k / 96) * 96 * LDA + m * LDA + (k % 96);
    } else return;
    bf16 h, l; split_bf16(v, h, l);
    dh[off] = h; dl[off] = l;
}

// ---------------------------------------------------------------------------
// Kernel 1: LayerNorm (2-phase global read) + e0 pointwise -> g_xnb, g_e0b
// ---------------------------------------------------------------------------
__global__ __launch_bounds__(256, 3) void k_ln_e0pw(
    const float* __restrict__ x,
    const float* __restrict__ lnw, const float* __restrict__ lnb,
    const float* __restrict__ bias)
{
    extern __shared__ unsigned char smraw[];
    bf16* xsh = (bf16*)(smraw + S_XSH);
    bf16* xsl = (bf16*)(smraw + S_XSL);
    bf16* wsh = (bf16*)(smraw + S_WSH);
    bf16* wsl = (bf16*)(smraw + S_WSL);
    float* stg = (float*)(smraw + S_WSH);        // aliases WSH after GEMM
    float* prm = (float*)(smraw + S_PRM);
    float* psum = prm;            // [8][64]
    float* psq  = prm + 512;      // [8][64]
    float* mu   = prm + 1024;
    float* inv  = prm + 1088;

    const int t = threadIdx.x, wid = t >> 5, lane = t & 31;
    const int b = blockIdx.y, p0 = blockIdx.x * 64;
    const float* xb = x + (size_t)b * C_ * HW + p0;

    copy_w(g_we0h, g_we0l, wsh, wsl, t);

    // stats: warp wid covers rows {wid, wid+8,...}, lane covers 2 px
    {
        const int c2 = lane * 2;
        float s0=0, s1=0, q0=0, q1=0;
        #pragma unroll 1
        for (int it = 0; it < 12; it++) {
            float2 v = *(const float2*)(xb + (size_t)(it * 8 + wid) * HW + c2);
            s0 += v.x; s1 += v.y; q0 += v.x*v.x; q1 += v.y*v.y;
        }
        psum[wid*64 + c2] = s0; psum[wid*64 + c2 + 1] = s1;
        psq [wid*64 + c2] = q0; psq [wid*64 + c2 + 1] = q1;
    }
    __syncthreads();
    if (t < 64) {
        float s = 0.f, q = 0.f;
        #pragma unroll
        for (int g = 0; g < 8; g++) { s += psum[g*64 + t]; q += psq[g*64 + t]; }
        float m = s * (1.f / 96.f);
        mu[t] = m;
        inv[t] = rsqrtf(q * (1.f / 96.f) - m * m + 1e-6f);
    }
    __syncthreads();

    // normalize (L2-hot re-read) + write xn (bf16 uint4) + split to smem
    bf16* xnb = g_xnb + (size_t)b * C_ * HW + p0;
    for (int i = t; i < 768; i += 256) {
        int k = i >> 3, cc = (i & 7) * 8;
        const float* sp = xb + (size_t)k * HW + cc;
        float4 v0 = *(const float4*)(sp);
        float4 v1 = *(const float4*)(sp + 4);
        float lw = __ldg(&lnw[k]), lb = __ldg(&lnb[k]);
        float o0 = (v0.x - mu[cc+0]) * inv[cc+0] * lw + lb;
        float o1 = (v0.y - mu[cc+1]) * inv[cc+1] * lw + lb;
        float o2 = (v0.z - mu[cc+2]) * inv[cc+2] * lw + lb;
        float o3 = (v0.w - mu[cc+3]) * inv[cc+3] * lw + lb;
        float o4 = (v1.x - mu[cc+4]) * inv[cc+4] * lw + lb;
        float o5 = (v1.y - mu[cc+5]) * inv[cc+5] * lw + lb;
        float o6 = (v1.z - mu[cc+6]) * inv[cc+6] * lw + lb;
        float o7 = (v1.w - mu[cc+7]) * inv[cc+7] * lw + lb;
        bf16 h0,l0,h1,l1,h2,l2,h3,l3,h4,l4,h5,l5,h6,l6,h7,l7;
        split_bf16(o0,h0,l0); split_bf16(o1,h1,l1);
        split_bf16(o2,h2,l2); split_bf16(o3,h3,l3);
        split_bf16(o4,h4,l4); split_bf16(o5,h5,l5);
        split_bf16(o6,h6,l6); split_bf16(o7,h7,l7);
        *(uint4*)(xnb + (size_t)k * HW + cc) =
            make_uint4(pack2(h0,h1), pack2(h2,h3), pack2(h4,h5), pack2(h6,h7));
        uint2* ph = (uint2*)(xsh + k * LDW + cc);
        uint2* pl = (uint2*)(xsl + k * LDW + cc);
        ph[0] = make_uint2(pack2(h0,h1), pack2(h2,h3));
        ph[1] = make_uint2(pack2(h4,h5), pack2(h6,h7));
        pl[0] = make_uint2(pack2(l0,l1), pack2(l2,l3));
        pl[1] = make_uint2(pack2(l4,l5), pack2(l6,l7));
    }
    __syncthreads();

    const int wm = wid >> 2, wn = wid & 3;
    FragC acc[3];
    zero3(acc);
    gemm3(wsh, wsl, xsh, xsl, acc, wm, wn);
    __syncthreads();                 // ws dead -> stg alias safe

    float* st = stg + wid * 256;
    bf16* gb = g_e0b + (size_t)b * C_ * HW + p0;
    const int r = lane >> 1, c8 = (lane & 1) * 8;
    #pragma unroll
    for (int mf = 0; mf < 3; mf++) {
        wmma::store_matrix_sync(st, acc[mf], 16, wmma::mem_row_major);
        __syncwarp();
        int mm = wm*48 + mf*16 + r;
        int pp = wn*16 + c8;
        float bb = __ldg(&bias[mm]);
        const float* sp = st + r*16 + c8;
        float4 s0 = *(const float4*)(sp);
        float4 s1 = *(const float4*)(sp + 4);
        bf16 e0 = __float2bfloat16_rn(s0.x+bb), e1 = __float2bfloat16_rn(s0.y+bb);
        bf16 e2 = __float2bfloat16_rn(s0.z+bb), e3 = __float2bfloat16_rn(s0.w+bb);
        bf16 e4 = __float2bfloat16_rn(s1.x+bb), e5 = __float2bfloat16_rn(s1.y+bb);
        bf16 e6 = __float2bfloat16_rn(s1.z+bb), e7 = __float2bfloat16_rn(s1.w+bb);
        *(uint4*)(gb + (size_t)mm * HW + pp) =
            make_uint4(pack2(e0,e1), pack2(e2,e3), pack2(e4,e5), pack2(e6,e7));
        __syncwarp();
    }
}

// ---------------------------------------------------------------------------
// Kernel 2: depthwise experts + mixing (64x64 tiles, 512 thr), bf16 inputs
// ---------------------------------------------------------------------------
__global__ __launch_bounds__(512, 2) void k_dw(
    const float* __restrict__ sw,
    const float* __restrict__ prompt,
    const float* __restrict__ w0, const float* __restrict__ b0,
    const float* __restrict__ w1, const float* __restrict__ b1,
    const float* __restrict__ w2, const float* __restrict__ b2)
{
    __shared__ float xs[76 * 77];
    __shared__ float es[66 * 67];
    __shared__ float kw[43];

    const int t = threadIdx.x;
    int c = blockIdx.y, b = blockIdx.z;
    int ty0 = (blockIdx.x >> 2) * 64;
    int tx0 = (blockIdx.x & 3) * 64;
    const bf16* xn = g_xnb + ((size_t)(b * C_ + c)) * HW;
    const bf16* ep = g_e0b + ((size_t)(b * C_ + c)) * HW;

    for (int i = t; i < 76 * 76; i += 512) {
        int r = i / 76, cc = i % 76;
        int yy = ty0 - 6 + r, xx = tx0 - 6 + cc;
        xs[r * 77 + cc] = (yy >= 0 && yy < H_ && xx >= 0 && xx < W_)
                        ? __bfloat162float(xn[yy * W_ + xx]) : 0.f;
    }
    for (int i = t; i < 66 * 66; i += 512) {
        int r = i / 66, cc = i % 66;
        int yy = ty0 - 1 + r, xx = tx0 - 1 + cc;
        es[r * 67 + cc] = (yy >= 0 && yy < H_ && xx >= 0 && xx < W_)
                        ? __bfloat162float(ep[yy * W_ + xx]) : 0.f;
    }
    if (t < 43) {
        kw[t] = (t < 9) ? __ldg(&w0[c*9 + t])
              : (t < 18) ? __ldg(&w1[c*9 + t - 9])
              : __ldg(&w2[c*25 + t - 18]);
    }
    float bb0 = __ldg(&b0[c]), bb1 = __ldg(&b1[c]), bb2 = __ldg(&b2[c]);
    float s0 = __ldg(&sw[b*3+0]), s1 = __ldg(&sw[b*3+1]), s2 = __ldg(&sw[b*3+2]);
    float pm = 1.f + __ldg(&prompt[b * C_ + c]);
    __syncthreads();

    const int py = t >> 3, px0 = (t & 7) * 8;
    float o[8], r8[8];

    #pragma unroll
    for (int j = 0; j < 8; j++) r8[j] = bb0;
    #pragma unroll
    for (int ky = 0; ky < 3; ky++)
        #pragma unroll
        for (int kx = 0; kx < 3; kx++) {
            float wv = kw[ky*3 + kx];
            const float* rowp = es + (py + ky) * 67 + px0 + kx;
            #pragma unroll
            for (int j = 0; j < 8; j++) r8[j] += wv * rowp[j];
        }
    #pragma unroll
    for (int j = 0; j < 8; j++) o[j] = s0 * r8[j];

    #pragma unroll
    for (int j = 0; j < 8; j++) r8[j] = bb1;
    #pragma unroll
    for (int ky = 0; ky < 3; ky++)
        #pragma unroll
        for (int kx = 0; kx < 3; kx++) {
            float wv = kw[9 + ky*3 + kx];
            const float* rowp = xs + (py + 4 + 2*ky) * 77 + px0 + 4 + 2*kx;
            #pragma unroll
            for (int j = 0; j < 8; j++) r8[j] += wv * rowp[j];
        }
    #pragma unroll
    for (int j = 0; j < 8; j++) o[j] += s1 * r8[j];

    #pragma unroll
    for (int j = 0; j < 8; j++) r8[j] = bb2;
    #pragma unroll
    for (int ky = 0; ky < 5; ky++)
        #pragma unroll
        for (int kx = 0; kx < 5; kx++) {
            float wv = kw[18 + ky*5 + kx];
            const float* rowp = xs + (py + 3*ky) * 77 + px0 + 3*kx;
            #pragma unroll
            for (int j = 0; j < 8; j++) r8[j] += wv * rowp[j];
        }
    #pragma unroll
    for (int j = 0; j < 8; j++) o[j] = (o[j] + s2 * r8[j]) * pm;

    float* outp = g_xa + ((size_t)(b * C_ + c)) * HW + (ty0 + py) * W_ + tx0 + px0;
    *(float4*)(outp)     = make_float4(o[0], o[1], o[2], o[3]);
    *(float4*)(outp + 4) = make_float4(o[4], o[5], o[6], o[7]);
}

// ---------------------------------------------------------------------------
// Kernel 3: x1 = x + proj(xa) -> g_x1
// ---------------------------------------------------------------------------
__global__ __launch_bounds__(256, 3) void k_proj(
    const float* __restrict__ x, const float* __restrict__ bias)
{
    extern __shared__ unsigned char smraw[];
    bf16* xsh = (bf16*)(smraw + S_XSH);
    bf16* xsl = (bf16*)(smraw + S_XSL);
    bf16* wsh = (bf16*)(smraw + S_WSH);
    bf16* wsl = (bf16*)(smraw + S_WSL);
    float* stg = (float*)(smraw + S_WSH);

    const int t = threadIdx.x, wid = t >> 5, lane = t & 31;
    const int b = blockIdx.y, p0 = blockIdx.x * 64;

    load_act(g_xa + (size_t)b * C_ * HW + p0, xsh, xsl, t);
    copy_w(g_wpjh, g_wpjl, wsh, wsl, t);
    __syncthreads();

    const int wm = wid >> 2, wn = wid & 3;
    FragC acc[3];
    zero3(acc);
    gemm3(wsh, wsl, xsh, xsl, acc, wm, wn);
    __syncthreads();

    float* st = stg + wid * 256;
    const float* rb = x   + (size_t)b * C_ * HW + p0;
    float* gb = g_x1 + (size_t)b * C_ * HW + p0;
    const int r = lane >> 1, c8 = (lane & 1) * 8;
    #pragma unroll
    for (int mf = 0; mf < 3; mf++) {
        wmma::store_matrix_sync(st, acc[mf], 16, wmma::mem_row_major);
        __syncwarp();
        int mm = wm*48 + mf*16 + r;
        int pp = wn*16 + c8;
        float bb = __ldg(&bias[mm]);
        const float* sp = st + r*16 + c8;
        const float* rp = rb + (size_t)mm * HW + pp;
        float4 s0 = *(const float4*)(sp);
        float4 s1 = *(const float4*)(sp + 4);
        float4 r0 = *(const float4*)(rp);
        float4 r1 = *(const float4*)(rp + 4);
        float* gp = gb + (size_t)mm * HW + pp;
        *(float4*)(gp)     = make_float4(s0.x+bb+r0.x, s0.y+bb+r0.y, s0.z+bb+r0.z, s0.w+bb+r0.w);
        *(float4*)(gp + 4) = make_float4(s1.x+bb+r1.x, s1.y+bb+r1.y, s1.z+bb+r1.z, s1.w+bb+r1.w);
        __syncwarp();
    }
}

// ---------------------------------------------------------------------------
// Kernel 4: h = gelu(ffn1(x1) + b1) -> g_hb (single bf16, uint4 stores)
// ---------------------------------------------------------------------------
__global__ __launch_bounds__(256, 3) void k_ffn1(const float* __restrict__ b1v)
{
    extern __shared__ unsigned char smraw[];
    bf16* xsh = (bf16*)(smraw + S_XSH);
    bf16* xsl = (bf16*)(smraw + S_XSL);
    bf16* wsh = (bf16*)(smraw + S_WSH);
    bf16* wsl = (bf16*)(smraw + S_WSL);
    float* stg = (float*)(smraw + S_WSH);

    const int t = threadIdx.x, wid = t >> 5, lane = t & 31;
    const int b = blockIdx.y, p0 = blockIdx.x * 64;

    load_act(g_x1 + (size_t)b * C_ * HW + p0, xsh, xsl, t);

    const int wm = wid >> 2, wn = wid & 3;
    const int r = lane >> 1, c8 = (lane & 1) * 8;
    float* st = stg + wid * 256;
    bf16* hb = g_hb + (size_t)b * 192 * HW + p0;

    #pragma unroll 1
    for (int oc = 0; oc < 2; oc++) {
        __syncthreads();                       // xs ready / stg readers done
        copy_w(g_w1h + oc * 96 * LDA, g_w1l + oc * 96 * LDA, wsh, wsl, t);
        __syncthreads();

        FragC acc[3];
        zero3(acc);
        gemm3(wsh, wsl, xsh, xsl, acc, wm, wn);
        __syncthreads();                       // ws dead -> stg alias

        #pragma unroll
        for (int mf = 0; mf < 3; mf++) {
            wmma::store_matrix_sync(st, acc[mf], 16, wmma::mem_row_major);
            __syncwarp();
            int k2 = oc*96 + wm*48 + mf*16 + r;
            int pp = wn*16 + c8;
            float bb = __ldg(&b1v[k2]);
            const float* sp = st + r*16 + c8;
            float4 s0 = *(const float4*)(sp);
            float4 s1 = *(const float4*)(sp + 4);
            float h0 = s0.x+bb, h1 = s0.y+bb, h2 = s0.z+bb, h3 = s0.w+bb;
            float h4 = s1.x+bb, h5 = s1.y+bb, h6 = s1.z+bb, h7 = s1.w+bb;
            bf16 g0 = __float2bfloat16_rn(h0*normcdff(h0));
            bf16 g1 = __float2bfloat16_rn(h1*normcdff(h1));
            bf16 g2 = __float2bfloat16_rn(h2*normcdff(h2));
            bf16 g3 = __float2bfloat16_rn(h3*normcdff(h3));
            bf16 g4 = __float2bfloat16_rn(h4*normcdff(h4));
            bf16 g5 = __float2bfloat16_rn(h5*normcdff(h5));
            bf16 g6 = __float2bfloat16_rn(h6*normcdff(h6));
            bf16 g7 = __float2bfloat16_rn(h7*normcdff(h7));
            *(uint4*)(hb + (size_t)k2 * HW + pp) =
                make_uint4(pack2(g0,g1), pack2(g2,g3), pack2(g4,g5), pack2(g6,g7));
            __syncwarp();
        }
    }
}

// ---------------------------------------------------------------------------
// Kernel 5: out = x1 + ffn2(h) + b2   (K=192, h single-plane, 2-pass GEMM)
// ---------------------------------------------------------------------------
__global__ __launch_bounds__(256, 3) void k_ffn2(
    const float* __restrict__ b2v, float* __restrict__ out)
{
    extern __shared__ unsigned char smraw[];
    bf16* hs  = (bf16*)(smraw + S_XSH);    // single plane [96][LDW]
    bf16* wsh = (bf16*)(smraw + S_WSH);
    bf16* wsl = (bf16*)(smraw + S_WSL);
    float* stg = (float*)(smraw + S_WSH);

    const int t = threadIdx.x, wid = t >> 5, lane = t & 31;
    const int b = blockIdx.y, p0 = blockIdx.x * 64;
    const bf16* hb = g_hb + (size_t)b * 192 * HW + p0;

    const int wm = wid >> 2, wn = wid & 3;
    FragC acc[3];
    zero3(acc);

    #pragma unroll 1
    for (int kc = 0; kc < 2; kc++) {
        if (kc) __syncthreads();               // prior readers done
        // copy h chunk: pure uint4 copies, no conversion
        for (int i = t; i < 768; i += 256) {   // 96 rows x 8 px-groups
            int r = i >> 3, cc = (i & 7) * 8;
            *(uint4*)(hs + r * LDW + cc) =
                *(const uint4*)(hb + (size_t)(kc * 96 + r) * HW + cc);
        }
        copy_w(g_w2h + kc * 96 * LDA, g_w2l + kc * 96 * LDA, wsh, wsl, t);
        __syncthreads();
        gemm2(wsh, wsl, hs, acc, wm, wn);
    }
    __syncthreads();                           // ws dead -> stg alias

    float* st = stg + wid * 256;
    const float* x1b = g_x1 + (size_t)b * C_ * HW + p0;
    float* ob = out + (size_t)b * C_ * HW + p0;
    const int r = lane >> 1, c8 = (lane & 1) * 8;
    #pragma unroll
    for (int mf = 0; mf < 3; mf++) {
        wmma::store_matrix_sync(st, acc[mf], 16, wmma::mem_row_major);
        __syncwarp();
        int mm = wm*48 + mf*16 + r;
        int pp = wn*16 + c8;
        float bb = __ldg(&b2v[mm]);
        const float* sp = st + r*16 + c8;
        const float* rp = x1b + (size_t)mm * HW + pp;
        float4 s0 = *(const float4*)(sp);
        float4 s1 = *(const float4*)(sp + 4);
        float4 r0 = *(const float4*)(rp);
        float4 r1 = *(const float4*)(rp + 4);
        float* gp = ob + (size_t)mm * HW + pp;
        *(float4*)(gp)     = make_float4(s0.x+bb+r0.x, s0.y+bb+r0.y, s0.z+bb+r0.z, s0.w+bb+r0.w);
        *(float4*)(gp + 4) = make_float4(s1.x+bb+r1.x, s1.y+bb+r1.y, s1.z+bb+r1.z, s1.w+bb+r1.w);
        __syncwarp();
    }
}

// ---------------------------------------------------------------------------
extern "C" void kernel_launch(void* const* d_in, const int* in_sizes, int n_in,
                              void* d_out, int out_size)
{
    const float* x       = (const float*)d_in[0];
    const float* prompt  = (const float*)d_in[1];
    const float* sweights= (const float*)d_in[2];
    const float* ln_w    = (const float*)d_in[3];
    const float* ln_b    = (const float*)d_in[4];
    const float* e0_pw_w = (const float*)d_in[5];
    const float* e0_pw_b = (const float*)d_in[6];
    const float* e0_dw_w = (const float*)d_in[7];
    const float* e0_dw_b = (const float*)d_in[8];
    const float* e1_dw_w = (const float*)d_in[9];
    const float* e1_dw_b = (const float*)d_in[10];
    const float* e2_dw_w = (const float*)d_in[11];
    const float* e2_dw_b = (const float*)d_in[12];
    const float* proj_w  = (const float*)d_in[13];
    const float* proj_b  = (const float*)d_in[14];
    const float* ffn1_w  = (const float*)d_in[15];
    const float* ffn1_b  = (const float*)d_in[16];
    const float* ffn2_w  = (const float*)d_in[17];
    const float* ffn2_b  = (const float*)d_in[18];
    float* out = (float*)d_out;

    cudaFuncSetAttribute(k_ln_e0pw, cudaFuncAttributeMaxDynamicSharedMemorySize, S_END);
    cudaFuncSetAttribute(k_proj,    cudaFuncAttributeMaxDynamicSharedMemorySize, S_END);
    cudaFuncSetAttribute(k_ffn1,    cudaFuncAttributeMaxDynamicSharedMemorySize, S_END);
    cudaFuncSetAttribute(k_ffn2,    cudaFuncAttributeMaxDynamicSharedMemorySize, S_END);

    dim3 gg(HW / 64, B_);

    k_prep<<<216, 256>>>(e0_pw_w, proj_w, ffn1_w, ffn2_w);

    k_ln_e0pw<<<gg, 256, S_END>>>(x, ln_w, ln_b, e0_pw_b);

    dim3 gdw(16, C_, B_);
    k_dw<<<gdw, 512>>>(sweights, prompt,
                       e0_dw_w, e0_dw_b, e1_dw_w, e1_dw_b, e2_dw_w, e2_dw_b);

    k_proj<<<gg, 256, S_END>>>(x, proj_b);

    k_ffn1<<<gg, 256, S_END>>>(ffn1_b);

    k_ffn2<<<gg, 256, S_END>>>(ffn2_b, out);
}

// round 13
// speedup vs baseline: 1.6935x; 1.0088x over previous
#include <cuda_runtime.h>
#include <cuda_bf16.h>
#include <mma.h>
#include <math.h>
#include <stdint.h>

using namespace nvcuda;

#define B_ 4
#define C_ 96
#define H_ 256
#define W_ 256
#define HW (H_*W_)
#define LDA 104
#define LDW 72        // 64-px tile B row stride (bf16)

typedef __nv_bfloat16 bf16;

// Scratch (allocation-free rule: __device__ globals)
__device__ bf16  g_xnb[B_*C_*HW];   // layernorm output (bf16)
__device__ bf16  g_e0b[B_*C_*HW];   // e0 pre-activation (bf16)
__device__ bf16  g_xah[B_*C_*HW];   // x_adaptive hi plane
__device__ bf16  g_xal[B_*C_*HW];   // x_adaptive lo plane
__device__ float g_x1[B_*C_*HW];    // x1 (f32, ffn2 residual)
__device__ bf16  g_hb[B_*192*HW];   // gelu(h), single bf16

// Pre-split weights (hi/lo) in padded [96][LDA] smem-image layout
__device__ __align__(16) bf16 g_we0h[96*LDA],  g_we0l[96*LDA];
__device__ __align__(16) bf16 g_wpjh[96*LDA],  g_wpjl[96*LDA];
__device__ __align__(16) bf16 g_w1h[2*96*LDA], g_w1l[2*96*LDA];
__device__ __align__(16) bf16 g_w2h[2*96*LDA], g_w2l[2*96*LDA];

using FragA = wmma::fragment<wmma::matrix_a, 16, 16, 16, bf16, wmma::row_major>;
using FragB = wmma::fragment<wmma::matrix_b, 16, 16, 16, bf16, wmma::row_major>;
using FragC = wmma::fragment<wmma::accumulator, 16, 16, 16, float>;

__device__ __forceinline__ void split_bf16(float v, bf16& h, bf16& l) {
    h = __float2bfloat16_rn(v);
    l = __float2bfloat16_rn(v - __bfloat162float(h));
}

__device__ __forceinline__ unsigned pack2(bf16 a, bf16 b) {
    unsigned short ra = *reinterpret_cast<unsigned short*>(&a);
    unsigned short rb = *reinterpret_cast<unsigned short*>(&b);
    return (unsigned)ra | ((unsigned)rb << 16);
}

// Copy pre-split weight chunk ([96][LDA] bf16 x2) global(L2-hot) -> smem.
__device__ __forceinline__ void copy_w(const bf16* __restrict__ srch,
                                       const bf16* __restrict__ srcl,
                                       bf16* wsh, bf16* wsl, int t)
{
    const uint4* sh = (const uint4*)srch;
    const uint4* sl = (const uint4*)srcl;
    uint4* dh = (uint4*)wsh;
    uint4* dl = (uint4*)wsl;
    #pragma unroll
    for (int i = 0; i < 5; i++) {
        int j = t + i * 256;
        if (j < 1248) { dh[j] = sh[j]; dl[j] = sl[j]; }
    }
}

// Copy bf16 hi/lo activation planes tile [96 ch][64 px] -> smem (pure uint4)
__device__ __forceinline__ void copy_act2(const bf16* __restrict__ srch,
                                          const bf16* __restrict__ srcl,
                                          bf16* xh, bf16* xl, int t)
{
    for (int i = t; i < 768; i += 256) {   // 96 rows x 8 px-groups
        int k = i >> 3, cc = (i & 7) * 8;
        size_t go = (size_t)k * HW + cc;
        *(uint4*)(xh + k * LDW + cc) = *(const uint4*)(srch + go);
        *(uint4*)(xl + k * LDW + cc) = *(const uint4*)(srcl + go);
    }
}

// 3-pass GEMM: C[96 x 64] += A[96x96] * B[96x64]. 8 warps: wm 0..1, wn 0..3.
__device__ __forceinline__ void gemm3(
    const bf16* ah, const bf16* al, const bf16* bh, const bf16* bl,
    FragC (&acc)[3], int wm, int wn)
{
    #pragma unroll 1
    for (int k = 0; k < 6; k++) {
        FragB b_h, b_l;
        wmma::load_matrix_sync(b_h, bh + (k*16)*LDW + wn*16, LDW);
        wmma::load_matrix_sync(b_l, bl + (k*16)*LDW + wn*16, LDW);
        #pragma unroll
        for (int mf = 0; mf < 3; mf++) {
            FragA a_h, a_l;
            wmma::load_matrix_sync(a_h, ah + (wm*48 + mf*16)*LDA + k*16, LDA);
            wmma::load_matrix_sync(a_l, al + (wm*48 + mf*16)*LDA + k*16, LDA);
            wmma::mma_sync(acc[mf], a_h, b_h, acc[mf]);
            wmma::mma_sync(acc[mf], a_h, b_l, acc[mf]);
            wmma::mma_sync(acc[mf], a_l, b_h, acc[mf]);
        }
    }
}

// 2-pass GEMM (B single-plane): C += (Ah + Al) * B
__device__ __forceinline__ void gemm2(
    const bf16* ah, const bf16* al, const bf16* b,
    FragC (&acc)[3], int wm, int wn)
{
    #pragma unroll 1
    for (int k = 0; k < 6; k++) {
        FragB bf;
        wmma::load_matrix_sync(bf, b + (k*16)*LDW + wn*16, LDW);
        #pragma unroll
        for (int mf = 0; mf < 3; mf++) {
            FragA a_h, a_l;
            wmma::load_matrix_sync(a_h, ah + (wm*48 + mf*16)*LDA + k*16, LDA);
            wmma::load_matrix_sync(a_l, al + (wm*48 + mf*16)*LDA + k*16, LDA);
            wmma::mma_sync(acc[mf], a_h, bf, acc[mf]);
            wmma::mma_sync(acc[mf], a_l, bf, acc[mf]);
        }
    }
}

__device__ __forceinline__ void zero3(FragC (&acc)[3]) {
    #pragma unroll
    for (int mf = 0; mf < 3; mf++) wmma::fill_fragment(acc[mf], 0.f);
}

// smem layout (bytes)
#define S_XSH 0
#define S_XSL 13824
#define S_WSH 27648
#define S_WSL 47616
#define S_PRM 67584
#define S_END (S_PRM + 4608)

// ---------------------------------------------------------------------------
// Weight prep: f32 -> bf16 hi/lo in padded layouts (once per launch)
// ---------------------------------------------------------------------------
__global__ void k_prep(const float* __restrict__ e0, const float* __restrict__ pj,
                       const float* __restrict__ w1, const float* __restrict__ w2)
{
    int i = blockIdx.x * 256 + threadIdx.x;
    float v; bf16 *dh, *dl; int off;
    if (i < 9216) {
        int m = i / 96, k = i % 96;
        v = e0[i]; dh = g_we0h; dl = g_we0l; off = m * LDA + k;
    } else if (i < 18432) {
        int j = i - 9216; int m = j / 96, k = j % 96;
        v = pj[j]; dh = g_wpjh; dl = g_wpjl; off = m * LDA + k;
    } else if (i < 36864) {
        int j = i - 18432; int m = j / 96, k = j % 96;     // m 0..191
        v = w1[j]; dh = g_w1h; dl = g_w1l;
        off = (m / 96) * 96 * LDA + (m % 96) * LDA + k;
    } else if (i < 55296) {
        int j = i - 36864; int m = j / 192, k = j % 192;   // w2 [96][192]
        v = w2[j]; dh = g_w2h; dl = g_w2l;
        off = (k / 96) * 96 * LDA + m * LDA + (k % 96);
    } else return;
    bf16 h, l; split_bf16(v, h, l);
    dh[off] = h; dl[off] = l;
}

// ---------------------------------------------------------------------------
// Kernel 1: LayerNorm (2-phase global read) + e0 pointwise -> g_xnb, g_e0b
// ---------------------------------------------------------------------------
__global__ __launch_bounds__(256, 3) void k_ln_e0pw(
    const float* __restrict__ x,
    const float* __restrict__ lnw, const float* __restrict__ lnb,
    const float* __restrict__ bias)
{
    extern __shared__ unsigned char smraw[];
    bf16* xsh = (bf16*)(smraw + S_XSH);
    bf16* xsl = (bf16*)(smraw + S_XSL);
    bf16* wsh = (bf16*)(smraw + S_WSH);
    bf16* wsl = (bf16*)(smraw + S_WSL);
    float* stg = (float*)(smraw + S_WSH);        // aliases WSH after GEMM
    float* prm = (float*)(smraw + S_PRM);
    float* psum = prm;            // [8][64]
    float* psq  = prm + 512;      // [8][64]
    float* mu   = prm + 1024;
    float* inv  = prm + 1088;

    const int t = threadIdx.x, wid = t >> 5, lane = t & 31;
    const int b = blockIdx.y, p0 = blockIdx.x * 64;
    const float* xb = x + (size_t)b * C_ * HW + p0;

    copy_w(g_we0h, g_we0l, wsh, wsl, t);

    {
        const int c2 = lane * 2;
        float s0=0, s1=0, q0=0, q1=0;
        #pragma unroll 1
        for (int it = 0; it < 12; it++) {
            float2 v = *(const float2*)(xb + (size_t)(it * 8 + wid) * HW + c2);
            s0 += v.x; s1 += v.y; q0 += v.x*v.x; q1 += v.y*v.y;
        }
        psum[wid*64 + c2] = s0; psum[wid*64 + c2 + 1] = s1;
        psq [wid*64 + c2] = q0; psq [wid*64 + c2 + 1] = q1;
    }
    __syncthreads();
    if (t < 64) {
        float s = 0.f, q = 0.f;
        #pragma unroll
        for (int g = 0; g < 8; g++) { s += psum[g*64 + t]; q += psq[g*64 + t]; }
        float m = s * (1.f / 96.f);
        mu[t] = m;
        inv[t] = rsqrtf(q * (1.f / 96.f) - m * m + 1e-6f);
    }
    __syncthreads();

    bf16* xnb = g_xnb + (size_t)b * C_ * HW + p0;
    for (int i = t; i < 768; i += 256) {
        int k = i >> 3, cc = (i & 7) * 8;
        const float* sp = xb + (size_t)k * HW + cc;
        float4 v0 = *(const float4*)(sp);
        float4 v1 = *(const float4*)(sp + 4);
        float lw = __ldg(&lnw[k]), lb = __ldg(&lnb[k]);
        float o0 = (v0.x - mu[cc+0]) * inv[cc+0] * lw + lb;
        float o1 = (v0.y - mu[cc+1]) * inv[cc+1] * lw + lb;
        float o2 = (v0.z - mu[cc+2]) * inv[cc+2] * lw + lb;
        float o3 = (v0.w - mu[cc+3]) * inv[cc+3] * lw + lb;
        float o4 = (v1.x - mu[cc+4]) * inv[cc+4] * lw + lb;
        float o5 = (v1.y - mu[cc+5]) * inv[cc+5] * lw + lb;
        float o6 = (v1.z - mu[cc+6]) * inv[cc+6] * lw + lb;
        float o7 = (v1.w - mu[cc+7]) * inv[cc+7] * lw + lb;
        bf16 h0,l0,h1,l1,h2,l2,h3,l3,h4,l4,h5,l5,h6,l6,h7,l7;
        split_bf16(o0,h0,l0); split_bf16(o1,h1,l1);
        split_bf16(o2,h2,l2); split_bf16(o3,h3,l3);
        split_bf16(o4,h4,l4); split_bf16(o5,h5,l5);
        split_bf16(o6,h6,l6); split_bf16(o7,h7,l7);
        *(uint4*)(xnb + (size_t)k * HW + cc) =
            make_uint4(pack2(h0,h1), pack2(h2,h3), pack2(h4,h5), pack2(h6,h7));
        uint2* ph = (uint2*)(xsh + k * LDW + cc);
        uint2* pl = (uint2*)(xsl + k * LDW + cc);
        ph[0] = make_uint2(pack2(h0,h1), pack2(h2,h3));
        ph[1] = make_uint2(pack2(h4,h5), pack2(h6,h7));
        pl[0] = make_uint2(pack2(l0,l1), pack2(l2,l3));
        pl[1] = make_uint2(pack2(l4,l5), pack2(l6,l7));
    }
    __syncthreads();

    const int wm = wid >> 2, wn = wid & 3;
    FragC acc[3];
    zero3(acc);
    gemm3(wsh, wsl, xsh, xsl, acc, wm, wn);
    __syncthreads();                 // ws dead -> stg alias safe

    float* st = stg + wid * 256;
    bf16* gb = g_e0b + (size_t)b * C_ * HW + p0;
    const int r = lane >> 1, c8 = (lane & 1) * 8;
    #pragma unroll
    for (int mf = 0; mf < 3; mf++) {
        wmma::store_matrix_sync(st, acc[mf], 16, wmma::mem_row_major);
        __syncwarp();
        int mm = wm*48 + mf*16 + r;
        int pp = wn*16 + c8;
        float bb = __ldg(&bias[mm]);
        const float* sp = st + r*16 + c8;
        float4 s0 = *(const float4*)(sp);
        float4 s1 = *(const float4*)(sp + 4);
        bf16 e0 = __float2bfloat16_rn(s0.x+bb), e1 = __float2bfloat16_rn(s0.y+bb);
        bf16 e2 = __float2bfloat16_rn(s0.z+bb), e3 = __float2bfloat16_rn(s0.w+bb);
        bf16 e4 = __float2bfloat16_rn(s1.x+bb), e5 = __float2bfloat16_rn(s1.y+bb);
        bf16 e6 = __float2bfloat16_rn(s1.z+bb), e7 = __float2bfloat16_rn(s1.w+bb);
        *(uint4*)(gb + (size_t)mm * HW + pp) =
            make_uint4(pack2(e0,e1), pack2(e2,e3), pack2(e4,e5), pack2(e6,e7));
        __syncwarp();
    }
}

// ---------------------------------------------------------------------------
// Kernel 2: depthwise experts + mixing -> xa as bf16 hi/lo planes
// ---------------------------------------------------------------------------
__global__ __launch_bounds__(512, 2) void k_dw(
    const float* __restrict__ sw,
    const float* __restrict__ prompt,
    const float* __restrict__ w0, const float* __restrict__ b0,
    const float* __restrict__ w1, const float* __restrict__ b1,
    const float* __restrict__ w2, const float* __restrict__ b2)
{
    __shared__ float xs[76 * 77];
    __shared__ float es[66 * 67];
    __shared__ float kw[43];

    const int t = threadIdx.x;
    int c = blockIdx.y, b = blockIdx.z;
    int ty0 = (blockIdx.x >> 2) * 64;
    int tx0 = (blockIdx.x & 3) * 64;
    const bf16* xn = g_xnb + ((size_t)(b * C_ + c)) * HW;
    const bf16* ep = g_e0b + ((size_t)(b * C_ + c)) * HW;

    for (int i = t; i < 76 * 76; i += 512) {
        int r = i / 76, cc = i % 76;
        int yy = ty0 - 6 + r, xx = tx0 - 6 + cc;
        xs[r * 77 + cc] = (yy >= 0 && yy < H_ && xx >= 0 && xx < W_)
                        ? __bfloat162float(xn[yy * W_ + xx]) : 0.f;
    }
    for (int i = t; i < 66 * 66; i += 512) {
        int r = i / 66, cc = i % 66;
        int yy = ty0 - 1 + r, xx = tx0 - 1 + cc;
        es[r * 67 + cc] = (yy >= 0 && yy < H_ && xx >= 0 && xx < W_)
                        ? __bfloat162float(ep[yy * W_ + xx]) : 0.f;
    }
    if (t < 43) {
        kw[t] = (t < 9) ? __ldg(&w0[c*9 + t])
              : (t < 18) ? __ldg(&w1[c*9 + t - 9])
              : __ldg(&w2[c*25 + t - 18]);
    }
    float bb0 = __ldg(&b0[c]), bb1 = __ldg(&b1[c]), bb2 = __ldg(&b2[c]);
    float s0 = __ldg(&sw[b*3+0]), s1 = __ldg(&sw[b*3+1]), s2 = __ldg(&sw[b*3+2]);
    float pm = 1.f + __ldg(&prompt[b * C_ + c]);
    __syncthreads();

    const int py = t >> 3, px0 = (t & 7) * 8;
    float o[8], r8[8];

    #pragma unroll
    for (int j = 0; j < 8; j++) r8[j] = bb0;
    #pragma unroll
    for (int ky = 0; ky < 3; ky++)
        #pragma unroll
        for (int kx = 0; kx < 3; kx++) {
            float wv = kw[ky*3 + kx];
            const float* rowp = es + (py + ky) * 67 + px0 + kx;
            #pragma unroll
            for (int j = 0; j < 8; j++) r8[j] += wv * rowp[j];
        }
    #pragma unroll
    for (int j = 0; j < 8; j++) o[j] = s0 * r8[j];

    #pragma unroll
    for (int j = 0; j < 8; j++) r8[j] = bb1;
    #pragma unroll
    for (int ky = 0; ky < 3; ky++)
        #pragma unroll
        for (int kx = 0; kx < 3; kx++) {
            float wv = kw[9 + ky*3 + kx];
            const float* rowp = xs + (py + 4 + 2*ky) * 77 + px0 + 4 + 2*kx;
            #pragma unroll
            for (int j = 0; j < 8; j++) r8[j] += wv * rowp[j];
        }
    #pragma unroll
    for (int j = 0; j < 8; j++) o[j] += s1 * r8[j];

    #pragma unroll
    for (int j = 0; j < 8; j++) r8[j] = bb2;
    #pragma unroll
    for (int ky = 0; ky < 5; ky++)
        #pragma unroll
        for (int kx = 0; kx < 5; kx++) {
            float wv = kw[18 + ky*5 + kx];
            const float* rowp = xs + (py + 3*ky) * 77 + px0 + 3*kx;
            #pragma unroll
            for (int j = 0; j < 8; j++) r8[j] += wv * rowp[j];
        }
    #pragma unroll
    for (int j = 0; j < 8; j++) o[j] = (o[j] + s2 * r8[j]) * pm;

    size_t go = ((size_t)(b * C_ + c)) * HW + (ty0 + py) * W_ + tx0 + px0;
    bf16 h0,l0,h1,l1,h2,l2,h3,l3,h4,l4,h5,l5,h6,l6,h7,l7;
    split_bf16(o[0],h0,l0); split_bf16(o[1],h1,l1);
    split_bf16(o[2],h2,l2); split_bf16(o[3],h3,l3);
    split_bf16(o[4],h4,l4); split_bf16(o[5],h5,l5);
    split_bf16(o[6],h6,l6); split_bf16(o[7],h7,l7);
    *(uint4*)(g_xah + go) = make_uint4(pack2(h0,h1), pack2(h2,h3), pack2(h4,h5), pack2(h6,h7));
    *(uint4*)(g_xal + go) = make_uint4(pack2(l0,l1), pack2(l2,l3), pack2(l4,l5), pack2(l6,l7));
}

// ---------------------------------------------------------------------------
// Kernel 3 (fused): x1 = x + proj(xa) + pb  (write g_x1, keep split in smem)
//                   h  = gelu(ffn1(x1) + b1) -> g_hb
// ---------------------------------------------------------------------------
__global__ __launch_bounds__(256, 3) void k_projffn1(
    const float* __restrict__ x, const float* __restrict__ pbias,
    const float* __restrict__ b1v)
{
    extern __shared__ unsigned char smraw[];
    bf16* xsh = (bf16*)(smraw + S_XSH);   // xa planes, then x1 planes
    bf16* xsl = (bf16*)(smraw + S_XSL);
    bf16* wsh = (bf16*)(smraw + S_WSH);
    bf16* wsl = (bf16*)(smraw + S_WSL);
    float* stg = (float*)(smraw + S_WSH);

    const int t = threadIdx.x, wid = t >> 5, lane = t & 31;
    const int b = blockIdx.y, p0 = blockIdx.x * 64;
    const size_t base = (size_t)b * C_ * HW + p0;

    copy_act2(g_xah + base, g_xal + base, xsh, xsl, t);
    copy_w(g_wpjh, g_wpjl, wsh, wsl, t);
    __syncthreads();

    const int wm = wid >> 2, wn = wid & 3;
    const int r = lane >> 1, c8 = (lane & 1) * 8;
    float* st = stg + wid * 256;

    // ---- proj GEMM ----
    FragC acc[3];
    zero3(acc);
    gemm3(wsh, wsl, xsh, xsl, acc, wm, wn);
    __syncthreads();      // xa planes + wproj dead

    // epilogue: x1 = acc + pb + x -> global f32 + smem hi/lo planes (in place)
    const float* rb = x + base;
    float* x1g = g_x1 + base;
    #pragma unroll
    for (int mf = 0; mf < 3; mf++) {
        wmma::store_matrix_sync(st, acc[mf], 16, wmma::mem_row_major);
        __syncwarp();
        int mm = wm*48 + mf*16 + r;
        int pp = wn*16 + c8;
        float bb = __ldg(&pbias[mm]);
        const float* sp = st + r*16 + c8;
        const float* rp = rb + (size_t)mm * HW + pp;
        float4 s0 = *(const float4*)(sp);
        float4 s1 = *(const float4*)(sp + 4);
        float4 r0 = *(const float4*)(rp);
        float4 r1 = *(const float4*)(rp + 4);
        float v0 = s0.x+bb+r0.x, v1 = s0.y+bb+r0.y, v2 = s0.z+bb+r0.z, v3 = s0.w+bb+r0.w;
        float v4 = s1.x+bb+r1.x, v5 = s1.y+bb+r1.y, v6 = s1.z+bb+r1.z, v7 = s1.w+bb+r1.w;
        float* gp = x1g + (size_t)mm * HW + pp;
        *(float4*)(gp)     = make_float4(v0, v1, v2, v3);
        *(float4*)(gp + 4) = make_float4(v4, v5, v6, v7);
        bf16 h0,l0,h1,l1,h2,l2,h3,l3,h4,l4,h5,l5,h6,l6,h7,l7;
        split_bf16(v0,h0,l0); split_bf16(v1,h1,l1);
        split_bf16(v2,h2,l2); split_bf16(v3,h3,l3);
        split_bf16(v4,h4,l4); split_bf16(v5,h5,l5);
        split_bf16(v6,h6,l6); split_bf16(v7,h7,l7);
        uint2* ph = (uint2*)(xsh + mm * LDW + pp);
        uint2* pl = (uint2*)(xsl + mm * LDW + pp);
        ph[0] = make_uint2(pack2(h0,h1), pack2(h2,h3));
        ph[1] = make_uint2(pack2(h4,h5), pack2(h6,h7));
        pl[0] = make_uint2(pack2(l0,l1), pack2(l2,l3));
        pl[1] = make_uint2(pack2(l4,l5), pack2(l6,l7));
        __syncwarp();
    }

    // ---- ffn1: two 96-row chunks from the in-smem x1 planes ----
    bf16* hb = g_hb + (size_t)b * 192 * HW + p0;
    #pragma unroll 1
    for (int oc = 0; oc < 2; oc++) {
        __syncthreads();                       // x1 planes ready / stg readers done
        copy_w(g_w1h + oc * 96 * LDA, g_w1l + oc * 96 * LDA, wsh, wsl, t);
        __syncthreads();

        FragC a1[3];
        zero3(a1);
        gemm3(wsh, wsl, xsh, xsl, a1, wm, wn);
        __syncthreads();                       // ws dead -> stg alias

        #pragma unroll
        for (int mf = 0; mf < 3; mf++) {
            wmma::store_matrix_sync(st, a1[mf], 16, wmma::mem_row_major);
            __syncwarp();
            int k2 = oc*96 + wm*48 + mf*16 + r;
            int pp = wn*16 + c8;
            float bb = __ldg(&b1v[k2]);
            const float* sp = st + r*16 + c8;
            float4 s0 = *(const float4*)(sp);
            float4 s1 = *(const float4*)(sp + 4);
            float h0 = s0.x+bb, h1 = s0.y+bb, h2 = s0.z+bb, h3 = s0.w+bb;
            float h4 = s1.x+bb, h5 = s1.y+bb, h6 = s1.z+bb, h7 = s1.w+bb;
            bf16 g0 = __float2bfloat16_rn(h0*normcdff(h0));
            bf16 g1 = __float2bfloat16_rn(h1*normcdff(h1));
            bf16 g2 = __float2bfloat16_rn(h2*normcdff(h2));
            bf16 g3 = __float2bfloat16_rn(h3*normcdff(h3));
            bf16 g4 = __float2bfloat16_rn(h4*normcdff(h4));
            bf16 g5 = __float2bfloat16_rn(h5*normcdff(h5));
            bf16 g6 = __float2bfloat16_rn(h6*normcdff(h6));
            bf16 g7 = __float2bfloat16_rn(h7*normcdff(h7));
            *(uint4*)(hb + (size_t)k2 * HW + pp) =
                make_uint4(pack2(g0,g1), pack2(g2,g3), pack2(g4,g5), pack2(g6,g7));
            __syncwarp();
        }
    }
}

// ---------------------------------------------------------------------------
// Kernel 4: out = x1 + ffn2(h) + b2   (K=192, h single-plane, 2-pass GEMM)
// ---------------------------------------------------------------------------
__global__ __launch_bounds__(256, 3) void k_ffn2(
    const float* __restrict__ b2v, float* __restrict__ out)
{
    extern __shared__ unsigned char smraw[];
    bf16* hs  = (bf16*)(smraw + S_XSH);    // single plane [96][LDW]
    bf16* wsh = (bf16*)(smraw + S_WSH);
    bf16* wsl = (bf16*)(smraw + S_WSL);
    float* stg = (float*)(smraw + S_WSH);

    const int t = threadIdx.x, wid = t >> 5, lane = t & 31;
    const int b = blockIdx.y, p0 = blockIdx.x * 64;
    const bf16* hb = g_hb + (size_t)b * 192 * HW + p0;

    const int wm = wid >> 2, wn = wid & 3;
    FragC acc[3];
    zero3(acc);

    #pragma unroll 1
    for (int kc = 0; kc < 2; kc++) {
        if (kc) __syncthreads();               // prior readers done
        for (int i = t; i < 768; i += 256) {   // pure uint4 copies
            int r = i >> 3, cc = (i & 7) * 8;
            *(uint4*)(hs + r * LDW + cc) =
                *(const uint4*)(hb + (size_t)(kc * 96 + r) * HW + cc);
        }
        copy_w(g_w2h + kc * 96 * LDA, g_w2l + kc * 96 * LDA, wsh, wsl, t);
        __syncthreads();
        gemm2(wsh, wsl, hs, acc, wm, wn);
    }
    __syncthreads();                           // ws dead -> stg alias

    float* st = stg + wid * 256;
    const float* x1b = g_x1 + (size_t)b * C_ * HW + p0;
    float* ob = out + (size_t)b * C_ * HW + p0;
    const int r = lane >> 1, c8 = (lane & 1) * 8;
    #pragma unroll
    for (int mf = 0; mf < 3; mf++) {
        wmma::store_matrix_sync(st, acc[mf], 16, wmma::mem_row_major);
        __syncwarp();
        int mm = wm*48 + mf*16 + r;
        int pp = wn*16 + c8;
        float bb = __ldg(&b2v[mm]);
        const float* sp = st + r*16 + c8;
        const float* rp = x1b + (size_t)mm * HW + pp;
        float4 s0 = *(const float4*)(sp);
        float4 s1 = *(const float4*)(sp + 4);
        float4 r0 = *(const float4*)(rp);
        float4 r1 = *(const float4*)(rp + 4);
        float* gp = ob + (size_t)mm * HW + pp;
        *(float4*)(gp)     = make_float4(s0.x+bb+r0.x, s0.y+bb+r0.y, s0.z+bb+r0.z, s0.w+bb+r0.w);
        *(float4*)(gp + 4) = make_float4(s1.x+bb+r1.x, s1.y+bb+r1.y, s1.z+bb+r1.z, s1.w+bb+r1.w);
        __syncwarp();
    }
}

// ---------------------------------------------------------------------------
extern "C" void kernel_launch(void* const* d_in, const int* in_sizes, int n_in,
                              void* d_out, int out_size)
{
    const float* x       = (const float*)d_in[0];
    const float* prompt  = (const float*)d_in[1];
    const float* sweights= (const float*)d_in[2];
    const float* ln_w    = (const float*)d_in[3];
    const float* ln_b    = (const float*)d_in[4];
    const float* e0_pw_w = (const float*)d_in[5];
    const float* e0_pw_b = (const float*)d_in[6];
    const float* e0_dw_w = (const float*)d_in[7];
    const float* e0_dw_b = (const float*)d_in[8];
    const float* e1_dw_w = (const float*)d_in[9];
    const float* e1_dw_b = (const float*)d_in[10];
    const float* e2_dw_w = (const float*)d_in[11];
    const float* e2_dw_b = (const float*)d_in[12];
    const float* proj_w  = (const float*)d_in[13];
    const float* proj_b  = (const float*)d_in[14];
    const float* ffn1_w  = (const float*)d_in[15];
    const float* ffn1_b  = (const float*)d_in[16];
    const float* ffn2_w  = (const float*)d_in[17];
    const float* ffn2_b  = (const float*)d_in[18];
    float* out = (float*)d_out;

    cudaFuncSetAttribute(k_ln_e0pw,  cudaFuncAttributeMaxDynamicSharedMemorySize, S_END);
    cudaFuncSetAttribute(k_projffn1, cudaFuncAttributeMaxDynamicSharedMemorySize, S_END);
    cudaFuncSetAttribute(k_ffn2,     cudaFuncAttributeMaxDynamicSharedMemorySize, S_END);

    dim3 gg(HW / 64, B_);

    k_prep<<<216, 256>>>(e0_pw_w, proj_w, ffn1_w, ffn2_w);

    k_ln_e0pw<<<gg, 256, S_END>>>(x, ln_w, ln_b, e0_pw_b);

    dim3 gdw(16, C_, B_);
    k_dw<<<gdw, 512>>>(sweights, prompt,
                       e0_dw_w, e0_dw_b, e1_dw_w, e1_dw_b, e2_dw_w, e2_dw_b);

    k_projffn1<<<gg, 256, S_END>>>(x, proj_b, ffn1_b);

    k_ffn2<<<gg, 256, S_END>>>(ffn2_b, out);
}

// round 15
// speedup vs baseline: 1.8988x; 1.1212x over previous
#include <cuda_runtime.h>
#include <cuda_bf16.h>
#include <mma.h>
#include <math.h>
#include <stdint.h>

using namespace nvcuda;

#define B_ 4
#define C_ 96
#define H_ 256
#define W_ 256
#define HW (H_*W_)
#define LDA 104
#define LDW 72        // 64-px tile B row stride (bf16)

typedef __nv_bfloat16 bf16;

// Scratch (allocation-free rule: __device__ globals)
__device__ bf16  g_xnb[B_*C_*HW];   // layernorm output (bf16)
__device__ bf16  g_e0b[B_*C_*HW];   // e0 pre-activation (bf16)
__device__ bf16  g_xah[B_*C_*HW];   // x_adaptive hi plane
__device__ bf16  g_xal[B_*C_*HW];   // x_adaptive lo plane
__device__ float g_x1[B_*C_*HW];    // x1 (f32, ffn2 residual)
__device__ bf16  g_hb[B_*192*HW];   // gelu(h), single bf16

// Pre-split weights (hi/lo) in padded [96][LDA] smem-image layout
__device__ __align__(16) bf16 g_we0h[96*LDA],  g_we0l[96*LDA];
__device__ __align__(16) bf16 g_wpjh[96*LDA],  g_wpjl[96*LDA];
__device__ __align__(16) bf16 g_w1h[2*96*LDA], g_w1l[2*96*LDA];
__device__ __align__(16) bf16 g_w2h[2*96*LDA], g_w2l[2*96*LDA];

using FragA = wmma::fragment<wmma::matrix_a, 16, 16, 16, bf16, wmma::row_major>;
using FragB = wmma::fragment<wmma::matrix_b, 16, 16, 16, bf16, wmma::row_major>;
using FragC = wmma::fragment<wmma::accumulator, 16, 16, 16, float>;

__device__ __forceinline__ void split_bf16(float v, bf16& h, bf16& l) {
    h = __float2bfloat16_rn(v);
    l = __float2bfloat16_rn(v - __bfloat162float(h));
}

__device__ __forceinline__ unsigned pack2(bf16 a, bf16 b) {
    unsigned short ra = *reinterpret_cast<unsigned short*>(&a);
    unsigned short rb = *reinterpret_cast<unsigned short*>(&b);
    return (unsigned)ra | ((unsigned)rb << 16);
}

__device__ __forceinline__ float2 unp2(unsigned u) {
    __nv_bfloat162 b = *reinterpret_cast<__nv_bfloat162*>(&u);
    return __bfloat1622float2(b);
}

// Copy pre-split weight chunk ([96][LDA] bf16 x2) global(L2-hot) -> smem.
__device__ __forceinline__ void copy_w(const bf16* __restrict__ srch,
                                       const bf16* __restrict__ srcl,
                                       bf16* wsh, bf16* wsl, int t)
{
    const uint4* sh = (const uint4*)srch;
    const uint4* sl = (const uint4*)srcl;
    uint4* dh = (uint4*)wsh;
    uint4* dl = (uint4*)wsl;
    #pragma unroll
    for (int i = 0; i < 5; i++) {
        int j = t + i * 256;
        if (j < 1248) { dh[j] = sh[j]; dl[j] = sl[j]; }
    }
}

// Copy bf16 hi/lo activation planes tile [96 ch][64 px] -> smem (pure uint4)
__device__ __forceinline__ void copy_act2(const bf16* __restrict__ srch,
                                          const bf16* __restrict__ srcl,
                                          bf16* xh, bf16* xl, int t)
{
    for (int i = t; i < 768; i += 256) {   // 96 rows x 8 px-groups
        int k = i >> 3, cc = (i & 7) * 8;
        size_t go = (size_t)k * HW + cc;
        *(uint4*)(xh + k * LDW + cc) = *(const uint4*)(srch + go);
        *(uint4*)(xl + k * LDW + cc) = *(const uint4*)(srcl + go);
    }
}

// 3-pass GEMM: C[96 x 64] += A[96x96] * B[96x64]. 8 warps: wm 0..1, wn 0..3.
__device__ __forceinline__ void gemm3(
    const bf16* ah, const bf16* al, const bf16* bh, const bf16* bl,
    FragC (&acc)[3], int wm, int wn)
{
    #pragma unroll 1
    for (int k = 0; k < 6; k++) {
        FragB b_h, b_l;
        wmma::load_matrix_sync(b_h, bh + (k*16)*LDW + wn*16, LDW);
        wmma::load_matrix_sync(b_l, bl + (k*16)*LDW + wn*16, LDW);
        #pragma unroll
        for (int mf = 0; mf < 3; mf++) {
            FragA a_h, a_l;
            wmma::load_matrix_sync(a_h, ah + (wm*48 + mf*16)*LDA + k*16, LDA);
            wmma::load_matrix_sync(a_l, al + (wm*48 + mf*16)*LDA + k*16, LDA);
            wmma::mma_sync(acc[mf], a_h, b_h, acc[mf]);
            wmma::mma_sync(acc[mf], a_h, b_l, acc[mf]);
            wmma::mma_sync(acc[mf], a_l, b_h, acc[mf]);
        }
    }
}

// 2-pass GEMM (B single-plane): C += (Ah + Al) * B
__device__ __forceinline__ void gemm2(
    const bf16* ah, const bf16* al, const bf16* b,
    FragC (&acc)[3], int wm, int wn)
{
    #pragma unroll 1
    for (int k = 0; k < 6; k++) {
        FragB bf;
        wmma::load_matrix_sync(bf, b + (k*16)*LDW + wn*16, LDW);
        #pragma unroll
        for (int mf = 0; mf < 3; mf++) {
            FragA a_h, a_l;
            wmma::load_matrix_sync(a_h, ah + (wm*48 + mf*16)*LDA + k*16, LDA);
            wmma::load_matrix_sync(a_l, al + (wm*48 + mf*16)*LDA + k*16, LDA);
            wmma::mma_sync(acc[mf], a_h, bf, acc[mf]);
            wmma::mma_sync(acc[mf], a_l, bf, acc[mf]);
        }
    }
}

__device__ __forceinline__ void zero3(FragC (&acc)[3]) {
    #pragma unroll
    for (int mf = 0; mf < 3; mf++) wmma::fill_fragment(acc[mf], 0.f);
}

// smem layout (bytes)
#define S_XSH 0
#define S_XSL 13824
#define S_WSH 27648
#define S_WSL 47616
#define S_PRM 67584
#define S_END (S_PRM + 4608)

// ---------------------------------------------------------------------------
// Weight prep: f32 -> bf16 hi/lo in padded layouts (once per launch)
// ---------------------------------------------------------------------------
__global__ void k_prep(const float* __restrict__ e0, const float* __restrict__ pj,
                       const float* __restrict__ w1, const float* __restrict__ w2)
{
    int i = blockIdx.x * 256 + threadIdx.x;
    float v; bf16 *dh, *dl; int off;
    if (i < 9216) {
        int m = i / 96, k = i % 96;
        v = e0[i]; dh = g_we0h; dl = g_we0l; off = m * LDA + k;
    } else if (i < 18432) {
        int j = i - 9216; int m = j / 96, k = j % 96;
        v = pj[j]; dh = g_wpjh; dl = g_wpjl; off = m * LDA + k;
    } else if (i < 36864) {
        int j = i - 18432; int m = j / 96, k = j % 96;     // m 0..191
        v = w1[j]; dh = g_w1h; dl = g_w1l;
        off = (m / 96) * 96 * LDA + (m % 96) * LDA + k;
    } else if (i < 55296) {
        int j = i - 36864; int m = j / 192, k = j % 192;   // w2 [96][192]
        v = w2[j]; dh = g_w2h; dl = g_w2l;
        off = (k / 96) * 96 * LDA + m * LDA + (k % 96);
    } else return;
    bf16 h, l; split_bf16(v, h, l);
    dh[off] = h; dl[off] = l;
}

// ---------------------------------------------------------------------------
// Kernel 1: LayerNorm (2-phase global read) + e0 pointwise -> g_xnb, g_e0b
// ---------------------------------------------------------------------------
__global__ __launch_bounds__(256, 3) void k_ln_e0pw(
    const float* __restrict__ x,
    const float* __restrict__ lnw, const float* __restrict__ lnb,
    const float* __restrict__ bias)
{
    extern __shared__ unsigned char smraw[];
    bf16* xsh = (bf16*)(smraw + S_XSH);
    bf16* xsl = (bf16*)(smraw + S_XSL);
    bf16* wsh = (bf16*)(smraw + S_WSH);
    bf16* wsl = (bf16*)(smraw + S_WSL);
    float* stg = (float*)(smraw + S_WSH);        // aliases WSH after GEMM
    float* prm = (float*)(smraw + S_PRM);
    float* psum = prm;            // [8][64]
    float* psq  = prm + 512;      // [8][64]
    float* mu   = prm + 1024;
    float* inv  = prm + 1088;

    const int t = threadIdx.x, wid = t >> 5, lane = t & 31;
    const int b = blockIdx.y, p0 = blockIdx.x * 64;
    const float* xb = x + (size_t)b * C_ * HW + p0;

    copy_w(g_we0h, g_we0l, wsh, wsl, t);

    {
        const int c2 = lane * 2;
        float s0=0, s1=0, q0=0, q1=0;
        #pragma unroll 1
        for (int it = 0; it < 12; it++) {
            float2 v = *(const float2*)(xb + (size_t)(it * 8 + wid) * HW + c2);
            s0 += v.x; s1 += v.y; q0 += v.x*v.x; q1 += v.y*v.y;
        }
        psum[wid*64 + c2] = s0; psum[wid*64 + c2 + 1] = s1;
        psq [wid*64 + c2] = q0; psq [wid*64 + c2 + 1] = q1;
    }
    __syncthreads();
    if (t < 64) {
        float s = 0.f, q = 0.f;
        #pragma unroll
        for (int g = 0; g < 8; g++) { s += psum[g*64 + t]; q += psq[g*64 + t]; }
        float m = s * (1.f / 96.f);
        mu[t] = m;
        inv[t] = rsqrtf(q * (1.f / 96.f) - m * m + 1e-6f);
    }
    __syncthreads();

    bf16* xnb = g_xnb + (size_t)b * C_ * HW + p0;
    for (int i = t; i < 768; i += 256) {
        int k = i >> 3, cc = (i & 7) * 8;
        const float* sp = xb + (size_t)k * HW + cc;
        float4 v0 = *(const float4*)(sp);
        float4 v1 = *(const float4*)(sp + 4);
        float lw = __ldg(&lnw[k]), lb = __ldg(&lnb[k]);
        float o0 = (v0.x - mu[cc+0]) * inv[cc+0] * lw + lb;
        float o1 = (v0.y - mu[cc+1]) * inv[cc+1] * lw + lb;
        float o2 = (v0.z - mu[cc+2]) * inv[cc+2] * lw + lb;
        float o3 = (v0.w - mu[cc+3]) * inv[cc+3] * lw + lb;
        float o4 = (v1.x - mu[cc+4]) * inv[cc+4] * lw + lb;
        float o5 = (v1.y - mu[cc+5]) * inv[cc+5] * lw + lb;
        float o6 = (v1.z - mu[cc+6]) * inv[cc+6] * lw + lb;
        float o7 = (v1.w - mu[cc+7]) * inv[cc+7] * lw + lb;
        bf16 h0,l0,h1,l1,h2,l2,h3,l3,h4,l4,h5,l5,h6,l6,h7,l7;
        split_bf16(o0,h0,l0); split_bf16(o1,h1,l1);
        split_bf16(o2,h2,l2); split_bf16(o3,h3,l3);
        split_bf16(o4,h4,l4); split_bf16(o5,h5,l5);
        split_bf16(o6,h6,l6); split_bf16(o7,h7,l7);
        *(uint4*)(xnb + (size_t)k * HW + cc) =
            make_uint4(pack2(h0,h1), pack2(h2,h3), pack2(h4,h5), pack2(h6,h7));
        uint2* ph = (uint2*)(xsh + k * LDW + cc);
        uint2* pl = (uint2*)(xsl + k * LDW + cc);
        ph[0] = make_uint2(pack2(h0,h1), pack2(h2,h3));
        ph[1] = make_uint2(pack2(h4,h5), pack2(h6,h7));
        pl[0] = make_uint2(pack2(l0,l1), pack2(l2,l3));
        pl[1] = make_uint2(pack2(l4,l5), pack2(l6,l7));
    }
    __syncthreads();

    const int wm = wid >> 2, wn = wid & 3;
    FragC acc[3];
    zero3(acc);
    gemm3(wsh, wsl, xsh, xsl, acc, wm, wn);
    __syncthreads();                 // ws dead -> stg alias safe

    float* st = stg + wid * 256;
    bf16* gb = g_e0b + (size_t)b * C_ * HW + p0;
    const int r = lane >> 1, c8 = (lane & 1) * 8;
    #pragma unroll
    for (int mf = 0; mf < 3; mf++) {
        wmma::store_matrix_sync(st, acc[mf], 16, wmma::mem_row_major);
        __syncwarp();
        int mm = wm*48 + mf*16 + r;
        int pp = wn*16 + c8;
        float bb = __ldg(&bias[mm]);
        const float* sp = st + r*16 + c8;
        float4 s0 = *(const float4*)(sp);
        float4 s1 = *(const float4*)(sp + 4);
        bf16 e0 = __float2bfloat16_rn(s0.x+bb), e1 = __float2bfloat16_rn(s0.y+bb);
        bf16 e2 = __float2bfloat16_rn(s0.z+bb), e3 = __float2bfloat16_rn(s0.w+bb);
        bf16 e4 = __float2bfloat16_rn(s1.x+bb), e5 = __float2bfloat16_rn(s1.y+bb);
        bf16 e6 = __float2bfloat16_rn(s1.z+bb), e7 = __float2bfloat16_rn(s1.w+bb);
        *(uint4*)(gb + (size_t)mm * HW + pp) =
            make_uint4(pack2(e0,e1), pack2(e2,e3), pack2(e4,e5), pack2(e6,e7));
        __syncwarp();
    }
}

// ---------------------------------------------------------------------------
// Kernel 2: depthwise experts + mixing -> xa bf16 hi/lo planes.
// Vectorized fills: column halo widened to 8 (aligned), groups fully in/out.
// W_=256 is a multiple of 8, so every 8-group is entirely in [0,W_) or not.
// ---------------------------------------------------------------------------
__global__ __launch_bounds__(512, 2) void k_dw(
    const float* __restrict__ sw,
    const float* __restrict__ prompt,
    const float* __restrict__ w0, const float* __restrict__ b0,
    const float* __restrict__ w1, const float* __restrict__ b1,
    const float* __restrict__ w2, const float* __restrict__ b2)
{
    __shared__ float xs[76 * 88];
    __shared__ float es[66 * 88];
    __shared__ float kw[43];

    const int t = threadIdx.x;
    int c = blockIdx.y, b = blockIdx.z;
    int ty0 = (blockIdx.x >> 2) * 64;
    int tx0 = (blockIdx.x & 3) * 64;
    const bf16* xn = g_xnb + ((size_t)(b * C_ + c)) * HW;
    const bf16* ep = g_e0b + ((size_t)(b * C_ + c)) * HW;

    // xs fill: 76 rows x 10 groups of 8
    for (int i = t; i < 760; i += 512) {
        int r = i / 10, g = i % 10;
        int yy = ty0 - 6 + r;
        int xx = tx0 - 8 + g * 8;
        float4 f0, f1;
        if (yy >= 0 && yy < H_ && xx >= 0 && xx < W_) {
            uint4 v = *(const uint4*)(xn + yy * W_ + xx);
            float2 a0 = unp2(v.x), a1 = unp2(v.y), a2 = unp2(v.z), a3 = unp2(v.w);
            f0 = make_float4(a0.x, a0.y, a1.x, a1.y);
            f1 = make_float4(a2.x, a2.y, a3.x, a3.y);
        } else {
            f0 = make_float4(0.f, 0.f, 0.f, 0.f);
            f1 = f0;
        }
        float* d = xs + r * 88 + g * 8;
        *(float4*)(d)     = f0;
        *(float4*)(d + 4) = f1;
    }
    // es fill: 66 rows x 10 groups of 8
    for (int i = t; i < 660; i += 512) {
        int r = i / 10, g = i % 10;
        int yy = ty0 - 1 + r;
        int xx = tx0 - 8 + g * 8;
        float4 f0, f1;
        if (yy >= 0 && yy < H_ && xx >= 0 && xx < W_) {
            uint4 v = *(const uint4*)(ep + yy * W_ + xx);
            float2 a0 = unp2(v.x), a1 = unp2(v.y), a2 = unp2(v.z), a3 = unp2(v.w);
            f0 = make_float4(a0.x, a0.y, a1.x, a1.y);
            f1 = make_float4(a2.x, a2.y, a3.x, a3.y);
        } else {
            f0 = make_float4(0.f, 0.f, 0.f, 0.f);
            f1 = f0;
        }
        float* d = es + r * 88 + g * 8;
        *(float4*)(d)     = f0;
        *(float4*)(d + 4) = f1;
    }
    if (t < 43) {
        kw[t] = (t < 9) ? __ldg(&w0[c*9 + t])
              : (t < 18) ? __ldg(&w1[c*9 + t - 9])
              : __ldg(&w2[c*25 + t - 18]);
    }
    float bb0 = __ldg(&b0[c]), bb1 = __ldg(&b1[c]), bb2 = __ldg(&b2[c]);
    float s0 = __ldg(&sw[b*3+0]), s1 = __ldg(&sw[b*3+1]), s2 = __ldg(&sw[b*3+2]);
    float pm = 1.f + __ldg(&prompt[b * C_ + c]);
    __syncthreads();

    const int py = t >> 3, px0 = (t & 7) * 8;
    float o[8], r8[8];

    // e0: 3x3 dil1 on e0_pre; tap (py+ky, px+kx+7)
    #pragma unroll
    for (int j = 0; j < 8; j++) r8[j] = bb0;
    #pragma unroll
    for (int ky = 0; ky < 3; ky++)
        #pragma unroll
        for (int kx = 0; kx < 3; kx++) {
            float wv = kw[ky*3 + kx];
            const float* rowp = es + (py + ky) * 88 + px0 + kx + 7;
            #pragma unroll
            for (int j = 0; j < 8; j++) r8[j] += wv * rowp[j];
        }
    #pragma unroll
    for (int j = 0; j < 8; j++) o[j] = s0 * r8[j];

    // e1: 3x3 dil2; tap (py+4+2ky, px+2kx+6)
    #pragma unroll
    for (int j = 0; j < 8; j++) r8[j] = bb1;
    #pragma unroll
    for (int ky = 0; ky < 3; ky++)
        #pragma unroll
        for (int kx = 0; kx < 3; kx++) {
            float wv = kw[9 + ky*3 + kx];
            const float* rowp = xs + (py + 4 + 2*ky) * 88 + px0 + 2*kx + 6;
            #pragma unroll
            for (int j = 0; j < 8; j++) r8[j] += wv * rowp[j];
        }
    #pragma unroll
    for (int j = 0; j < 8; j++) o[j] += s1 * r8[j];

    // e2: 5x5 dil3; tap (py+3ky, px+3kx+2)
    #pragma unroll
    for (int j = 0; j < 8; j++) r8[j] = bb2;
    #pragma unroll
    for (int ky = 0; ky < 5; ky++)
        #pragma unroll
        for (int kx = 0; kx < 5; kx++) {
            float wv = kw[18 + ky*5 + kx];
            const float* rowp = xs + (py + 3*ky) * 88 + px0 + 3*kx + 2;
            #pragma unroll
            for (int j = 0; j < 8; j++) r8[j] += wv * rowp[j];
        }
    #pragma unroll
    for (int j = 0; j < 8; j++) o[j] = (o[j] + s2 * r8[j]) * pm;

    size_t go = ((size_t)(b * C_ + c)) * HW + (ty0 + py) * W_ + tx0 + px0;
    bf16 h0,l0,h1,l1,h2,l2,h3,l3,h4,l4,h5,l5,h6,l6,h7,l7;
    split_bf16(o[0],h0,l0); split_bf16(o[1],h1,l1);
    split_bf16(o[2],h2,l2); split_bf16(o[3],h3,l3);
    split_bf16(o[4],h4,l4); split_bf16(o[5],h5,l5);
    split_bf16(o[6],h6,l6); split_bf16(o[7],h7,l7);
    *(uint4*)(g_xah + go) = make_uint4(pack2(h0,h1), pack2(h2,h3), pack2(h4,h5), pack2(h6,h7));
    *(uint4*)(g_xal + go) = make_uint4(pack2(l0,l1), pack2(l2,l3), pack2(l4,l5), pack2(l6,l7));
}

// ---------------------------------------------------------------------------
// Kernel 3 (fused): x1 = x + proj(xa) + pb ; h = gelu(ffn1(x1) + b1) -> g_hb
// ---------------------------------------------------------------------------
__global__ __launch_bounds__(256, 3) void k_projffn1(
    const float* __restrict__ x, const float* __restrict__ pbias,
    const float* __restrict__ b1v)
{
    extern __shared__ unsigned char smraw[];
    bf16* xsh = (bf16*)(smraw + S_XSH);   // xa planes, then x1 planes
    bf16* xsl = (bf16*)(smraw + S_XSL);
    bf16* wsh = (bf16*)(smraw + S_WSH);
    bf16* wsl = (bf16*)(smraw + S_WSL);
    float* stg = (float*)(smraw + S_WSH);

    const int t = threadIdx.x, wid = t >> 5, lane = t & 31;
    const int b = blockIdx.y, p0 = blockIdx.x * 64;
    const size_t base = (size_t)b * C_ * HW + p0;

    copy_act2(g_xah + base, g_xal + base, xsh, xsl, t);
    copy_w(g_wpjh, g_wpjl, wsh, wsl, t);
    __syncthreads();

    const int wm = wid >> 2, wn = wid & 3;
    const int r = lane >> 1, c8 = (lane & 1) * 8;
    float* st = stg + wid * 256;

    // ---- proj GEMM ----
    FragC acc[3];
    zero3(acc);
    gemm3(wsh, wsl, xsh, xsl, acc, wm, wn);
    __syncthreads();      // xa planes + wproj dead

    // epilogue: x1 = acc + pb + x -> global f32 + smem hi/lo planes (in place)
    const float* rb = x + base;
    float* x1g = g_x1 + base;
    #pragma unroll
    for (int mf = 0; mf < 3; mf++) {
        wmma::store_matrix_sync(st, acc[mf], 16, wmma::mem_row_major);
        __syncwarp();
        int mm = wm*48 + mf*16 + r;
        int pp = wn*16 + c8;
        float bb = __ldg(&pbias[mm]);
        const float* sp = st + r*16 + c8;
        const float* rp = rb + (size_t)mm * HW + pp;
        float4 s0 = *(const float4*)(sp);
        float4 s1 = *(const float4*)(sp + 4);
        float4 r0 = *(const float4*)(rp);
        float4 r1 = *(const float4*)(rp + 4);
        float v0 = s0.x+bb+r0.x, v1 = s0.y+bb+r0.y, v2 = s0.z+bb+r0.z, v3 = s0.w+bb+r0.w;
        float v4 = s1.x+bb+r1.x, v5 = s1.y+bb+r1.y, v6 = s1.z+bb+r1.z, v7 = s1.w+bb+r1.w;
        float* gp = x1g + (size_t)mm * HW + pp;
        *(float4*)(gp)     = make_float4(v0, v1, v2, v3);
        *(float4*)(gp + 4) = make_float4(v4, v5, v6, v7);
        bf16 h0,l0,h1,l1,h2,l2,h3,l3,h4,l4,h5,l5,h6,l6,h7,l7;
        split_bf16(v0,h0,l0); split_bf16(v1,h1,l1);
        split_bf16(v2,h2,l2); split_bf16(v3,h3,l3);
        split_bf16(v4,h4,l4); split_bf16(v5,h5,l5);
        split_bf16(v6,h6,l6); split_bf16(v7,h7,l7);
        uint2* ph = (uint2*)(xsh + mm * LDW + pp);
        uint2* pl = (uint2*)(xsl + mm * LDW + pp);
        ph[0] = make_uint2(pack2(h0,h1), pack2(h2,h3));
        ph[1] = make_uint2(pack2(h4,h5), pack2(h6,h7));
        pl[0] = make_uint2(pack2(l0,l1), pack2(l2,l3));
        pl[1] = make_uint2(pack2(l4,l5), pack2(l6,l7));
        __syncwarp();
    }

    // ---- ffn1: two 96-row chunks from the in-smem x1 planes ----
    bf16* hb = g_hb + (size_t)b * 192 * HW + p0;
    #pragma unroll 1
    for (int oc = 0; oc < 2; oc++) {
        __syncthreads();                       // x1 planes ready / stg readers done
        copy_w(g_w1h + oc * 96 * LDA, g_w1l + oc * 96 * LDA, wsh, wsl, t);
        __syncthreads();

        FragC a1[3];
        zero3(a1);
        gemm3(wsh, wsl, xsh, xsl, a1, wm, wn);
        __syncthreads();                       // ws dead -> stg alias

        #pragma unroll
        for (int mf = 0; mf < 3; mf++) {
            wmma::store_matrix_sync(st, a1[mf], 16, wmma::mem_row_major);
            __syncwarp();
            int k2 = oc*96 + wm*48 + mf*16 + r;
            int pp = wn*16 + c8;
            float bb = __ldg(&b1v[k2]);
            const float* sp = st + r*16 + c8;
            float4 s0 = *(const float4*)(sp);
            float4 s1 = *(const float4*)(sp + 4);
            float h0 = s0.x+bb, h1 = s0.y+bb, h2 = s0.z+bb, h3 = s0.w+bb;
            float h4 = s1.x+bb, h5 = s1.y+bb, h6 = s1.z+bb, h7 = s1.w+bb;
            bf16 g0 = __float2bfloat16_rn(h0*normcdff(h0));
            bf16 g1 = __float2bfloat16_rn(h1*normcdff(h1));
            bf16 g2 = __float2bfloat16_rn(h2*normcdff(h2));
            bf16 g3 = __float2bfloat16_rn(h3*normcdff(h3));
            bf16 g4 = __float2bfloat16_rn(h4*normcdff(h4));
            bf16 g5 = __float2bfloat16_rn(h5*normcdff(h5));
            bf16 g6 = __float2bfloat16_rn(h6*normcdff(h6));
            bf16 g7 = __float2bfloat16_rn(h7*normcdff(h7));
            *(uint4*)(hb + (size_t)k2 * HW + pp) =
                make_uint4(pack2(g0,g1), pack2(g2,g3), pack2(g4,g5), pack2(g6,g7));
            __syncwarp();
        }
    }
}

// ---------------------------------------------------------------------------
// Kernel 4: out = x1 + ffn2(h) + b2   (K=192, h single-plane, 2-pass GEMM)
// ---------------------------------------------------------------------------
__global__ __launch_bounds__(256, 3) void k_ffn2(
    const float* __restrict__ b2v, float* __restrict__ out)
{
    extern __shared__ unsigned char smraw[];
    bf16* hs  = (bf16*)(smraw + S_XSH);    // single plane [96][LDW]
    bf16* wsh = (bf16*)(smraw + S_WSH);
    bf16* wsl = (bf16*)(smraw + S_WSL);
    float* stg = (float*)(smraw + S_WSH);

    const int t = threadIdx.x, wid = t >> 5, lane = t & 31;
    const int b = blockIdx.y, p0 = blockIdx.x * 64;
    const bf16* hb = g_hb + (size_t)b * 192 * HW + p0;

    const int wm = wid >> 2, wn = wid & 3;
    FragC acc[3];
    zero3(acc);

    #pragma unroll 1
    for (int kc = 0; kc < 2; kc++) {
        if (kc) __syncthreads();               // prior readers done
        for (int i = t; i < 768; i += 256) {   // pure uint4 copies
            int r = i >> 3, cc = (i & 7) * 8;
            *(uint4*)(hs + r * LDW + cc) =
                *(const uint4*)(hb + (size_t)(kc * 96 + r) * HW + cc);
        }
        copy_w(g_w2h + kc * 96 * LDA, g_w2l + kc * 96 * LDA, wsh, wsl, t);
        __syncthreads();
        gemm2(wsh, wsl, hs, acc, wm, wn);
    }
    __syncthreads();                           // ws dead -> stg alias

    float* st = stg + wid * 256;
    const float* x1b = g_x1 + (size_t)b * C_ * HW + p0;
    float* ob = out + (size_t)b * C_ * HW + p0;
    const int r = lane >> 1, c8 = (lane & 1) * 8;
    #pragma unroll
    for (int mf = 0; mf < 3; mf++) {
        wmma::store_matrix_sync(st, acc[mf], 16, wmma::mem_row_major);
        __syncwarp();
        int mm = wm*48 + mf*16 + r;
        int pp = wn*16 + c8;
        float bb = __ldg(&b2v[mm]);
        const float* sp = st + r*16 + c8;
        const float* rp = x1b + (size_t)mm * HW + pp;
        float4 s0 = *(const float4*)(sp);
        float4 s1 = *(const float4*)(sp + 4);
        float4 r0 = *(const float4*)(rp);
        float4 r1 = *(const float4*)(rp + 4);
        float* gp = ob + (size_t)mm * HW + pp;
        *(float4*)(gp)     = make_float4(s0.x+bb+r0.x, s0.y+bb+r0.y, s0.z+bb+r0.z, s0.w+bb+r0.w);
        *(float4*)(gp + 4) = make_float4(s1.x+bb+r1.x, s1.y+bb+r1.y, s1.z+bb+r1.z, s1.w+bb+r1.w);
        __syncwarp();
    }
}

// ---------------------------------------------------------------------------
extern "C" void kernel_launch(void* const* d_in, const int* in_sizes, int n_in,
                              void* d_out, int out_size)
{
    const float* x       = (const float*)d_in[0];
    const float* prompt  = (const float*)d_in[1];
    const float* sweights= (const float*)d_in[2];
    const float* ln_w    = (const float*)d_in[3];
    const float* ln_b    = (const float*)d_in[4];
    const float* e0_pw_w = (const float*)d_in[5];
    const float* e0_pw_b = (const float*)d_in[6];
    const float* e0_dw_w = (const float*)d_in[7];
    const float* e0_dw_b = (const float*)d_in[8];
    const float* e1_dw_w = (const float*)d_in[9];
    const float* e1_dw_b = (const float*)d_in[10];
    const float* e2_dw_w = (const float*)d_in[11];
    const float* e2_dw_b = (const float*)d_in[12];
    const float* proj_w  = (const float*)d_in[13];
    const float* proj_b  = (const float*)d_in[14];
    const float* ffn1_w  = (const float*)d_in[15];
    const float* ffn1_b  = (const float*)d_in[16];
    const float* ffn2_w  = (const float*)d_in[17];
    const float* ffn2_b  = (const float*)d_in[18];
    float* out = (float*)d_out;

    cudaFuncSetAttribute(k_ln_e0pw,  cudaFuncAttributeMaxDynamicSharedMemorySize, S_END);
    cudaFuncSetAttribute(k_projffn1, cudaFuncAttributeMaxDynamicSharedMemorySize, S_END);
    cudaFuncSetAttribute(k_ffn2,     cudaFuncAttributeMaxDynamicSharedMemorySize, S_END);

    dim3 gg(HW / 64, B_);

    k_prep<<<216, 256>>>(e0_pw_w, proj_w, ffn1_w, ffn2_w);

    k_ln_e0pw<<<gg, 256, S_END>>>(x, ln_w, ln_b, e0_pw_b);

    dim3 gdw(16, C_, B_);
    k_dw<<<gdw, 512>>>(sweights, prompt,
                       e0_dw_w, e0_dw_b, e1_dw_w, e1_dw_b, e2_dw_w, e2_dw_b);

    k_projffn1<<<gg, 256, S_END>>>(x, proj_b, ffn1_b);

    k_ffn2<<<gg, 256, S_END>>>(ffn2_b, out);
}

// round 16
// speedup vs baseline: 2.1129x; 1.1128x over previous
#include <cuda_runtime.h>
#include <cuda_bf16.h>
#include <mma.h>
#include <math.h>
#include <stdint.h>

using namespace nvcuda;

#define B_ 4
#define C_ 96
#define H_ 256
#define W_ 256
#define HW (H_*W_)
#define LDA 104
#define LDW 72        // 64-px tile B row stride (bf16)

typedef __nv_bfloat16 bf16;

// Scratch (allocation-free rule: __device__ globals)
__device__ bf16  g_xnb[B_*C_*HW];   // layernorm output (bf16)
__device__ bf16  g_e0b[B_*C_*HW];   // e0 pre-activation (bf16)
__device__ bf16  g_xah[B_*C_*HW];   // x_adaptive hi plane
__device__ bf16  g_xal[B_*C_*HW];   // x_adaptive lo plane
__device__ float g_x1[B_*C_*HW];    // x1 (f32, ffn2 residual)
__device__ bf16  g_hb[B_*192*HW];   // gelu(h), single bf16

// Pre-split weights (hi/lo) in padded [96][LDA] smem-image layout
__device__ __align__(16) bf16 g_we0h[96*LDA],  g_we0l[96*LDA];
__device__ __align__(16) bf16 g_wpjh[96*LDA],  g_wpjl[96*LDA];
__device__ __align__(16) bf16 g_w1h[2*96*LDA], g_w1l[2*96*LDA];
__device__ __align__(16) bf16 g_w2h[2*96*LDA], g_w2l[2*96*LDA];

using FragA = wmma::fragment<wmma::matrix_a, 16, 16, 16, bf16, wmma::row_major>;
using FragB = wmma::fragment<wmma::matrix_b, 16, 16, 16, bf16, wmma::row_major>;
using FragC = wmma::fragment<wmma::accumulator, 16, 16, 16, float>;

__device__ __forceinline__ void split_bf16(float v, bf16& h, bf16& l) {
    h = __float2bfloat16_rn(v);
    l = __float2bfloat16_rn(v - __bfloat162float(h));
}

__device__ __forceinline__ unsigned pack2(bf16 a, bf16 b) {
    unsigned short ra = *reinterpret_cast<unsigned short*>(&a);
    unsigned short rb = *reinterpret_cast<unsigned short*>(&b);
    return (unsigned)ra | ((unsigned)rb << 16);
}

__device__ __forceinline__ float2 unp2(unsigned u) {
    __nv_bfloat162 b = *reinterpret_cast<__nv_bfloat162*>(&u);
    return __bfloat1622float2(b);
}

// Fast GELU: tanh formulation with HW tanh.approx (MUFU.TANH).
// Deviation from exact gelu ~3e-4 abs + MUFU ~2^-11 — both far below the
// bf16 rounding applied to h immediately after.
__device__ __forceinline__ float gelu_fast(float h) {
    float u = 0.7978845608f * fmaf(0.044715f * h, h * h, h);
    float t;
    asm("tanh.approx.f32 %0, %1;" : "=f"(t) : "f"(u));
    return 0.5f * h * (1.f + t);
}

// Copy pre-split weight chunk ([96][LDA] bf16 x2) global(L2-hot) -> smem.
__device__ __forceinline__ void copy_w(const bf16* __restrict__ srch,
                                       const bf16* __restrict__ srcl,
                                       bf16* wsh, bf16* wsl, int t)
{
    const uint4* sh = (const uint4*)srch;
    const uint4* sl = (const uint4*)srcl;
    uint4* dh = (uint4*)wsh;
    uint4* dl = (uint4*)wsl;
    #pragma unroll
    for (int i = 0; i < 5; i++) {
        int j = t + i * 256;
        if (j < 1248) { dh[j] = sh[j]; dl[j] = sl[j]; }
    }
}

// Copy bf16 hi/lo activation planes tile [96 ch][64 px] -> smem (pure uint4)
__device__ __forceinline__ void copy_act2(const bf16* __restrict__ srch,
                                          const bf16* __restrict__ srcl,
                                          bf16* xh, bf16* xl, int t)
{
    for (int i = t; i < 768; i += 256) {   // 96 rows x 8 px-groups
        int k = i >> 3, cc = (i & 7) * 8;
        size_t go = (size_t)k * HW + cc;
        *(uint4*)(xh + k * LDW + cc) = *(const uint4*)(srch + go);
        *(uint4*)(xl + k * LDW + cc) = *(const uint4*)(srcl + go);
    }
}

// 3-pass GEMM: C[96 x 64] += A[96x96] * B[96x64]. 8 warps: wm 0..1, wn 0..3.
__device__ __forceinline__ void gemm3(
    const bf16* ah, const bf16* al, const bf16* bh, const bf16* bl,
    FragC (&acc)[3], int wm, int wn)
{
    #pragma unroll 1
    for (int k = 0; k < 6; k++) {
        FragB b_h, b_l;
        wmma::load_matrix_sync(b_h, bh + (k*16)*LDW + wn*16, LDW);
        wmma::load_matrix_sync(b_l, bl + (k*16)*LDW + wn*16, LDW);
        #pragma unroll
        for (int mf = 0; mf < 3; mf++) {
            FragA a_h, a_l;
            wmma::load_matrix_sync(a_h, ah + (wm*48 + mf*16)*LDA + k*16, LDA);
            wmma::load_matrix_sync(a_l, al + (wm*48 + mf*16)*LDA + k*16, LDA);
            wmma::mma_sync(acc[mf], a_h, b_h, acc[mf]);
            wmma::mma_sync(acc[mf], a_h, b_l, acc[mf]);
            wmma::mma_sync(acc[mf], a_l, b_h, acc[mf]);
        }
    }
}

// 2-pass GEMM (B single-plane): C += (Ah + Al) * B
__device__ __forceinline__ void gemm2(
    const bf16* ah, const bf16* al, const bf16* b,
    FragC (&acc)[3], int wm, int wn)
{
    #pragma unroll 1
    for (int k = 0; k < 6; k++) {
        FragB bf;
        wmma::load_matrix_sync(bf, b + (k*16)*LDW + wn*16, LDW);
        #pragma unroll
        for (int mf = 0; mf < 3; mf++) {
            FragA a_h, a_l;
            wmma::load_matrix_sync(a_h, ah + (wm*48 + mf*16)*LDA + k*16, LDA);
            wmma::load_matrix_sync(a_l, al + (wm*48 + mf*16)*LDA + k*16, LDA);
            wmma::mma_sync(acc[mf], a_h, bf, acc[mf]);
            wmma::mma_sync(acc[mf], a_l, bf, acc[mf]);
        }
    }
}

__device__ __forceinline__ void zero3(FragC (&acc)[3]) {
    #pragma unroll
    for (int mf = 0; mf < 3; mf++) wmma::fill_fragment(acc[mf], 0.f);
}

// smem layout (bytes)
#define S_XSH 0
#define S_XSL 13824
#define S_WSH 27648
#define S_WSL 47616
#define S_PRM 67584
#define S_END (S_PRM + 4608)

// ---------------------------------------------------------------------------
// Weight prep: f32 -> bf16 hi/lo in padded layouts (once per launch)
// ---------------------------------------------------------------------------
__global__ void k_prep(const float* __restrict__ e0, const float* __restrict__ pj,
                       const float* __restrict__ w1, const float* __restrict__ w2)
{
    int i = blockIdx.x * 256 + threadIdx.x;
    float v; bf16 *dh, *dl; int off;
    if (i < 9216) {
        int m = i / 96, k = i % 96;
        v = e0[i]; dh = g_we0h; dl = g_we0l; off = m * LDA + k;
    } else if (i < 18432) {
        int j = i - 9216; int m = j / 96, k = j % 96;
        v = pj[j]; dh = g_wpjh; dl = g_wpjl; off = m * LDA + k;
    } else if (i < 36864) {
        int j = i - 18432; int m = j / 96, k = j % 96;     // m 0..191
        v = w1[j]; dh = g_w1h; dl = g_w1l;
        off = (m / 96) * 96 * LDA + (m % 96) * LDA + k;
    } else if (i < 55296) {
        int j = i - 36864; int m = j / 192, k = j % 192;   // w2 [96][192]
        v = w2[j]; dh = g_w2h; dl = g_w2l;
        off = (k / 96) * 96 * LDA + m * LDA + (k % 96);
    } else return;
    bf16 h, l; split_bf16(v, h, l);
    dh[off] = h; dl[off] = l;
}

// ---------------------------------------------------------------------------
// Kernel 1: LayerNorm (2-phase global read) + e0 pointwise -> g_xnb, g_e0b
// ---------------------------------------------------------------------------
__global__ __launch_bounds__(256, 3) void k_ln_e0pw(
    const float* __restrict__ x,
    const float* __restrict__ lnw, const float* __restrict__ lnb,
    const float* __restrict__ bias)
{
    extern __shared__ unsigned char smraw[];
    bf16* xsh = (bf16*)(smraw + S_XSH);
    bf16* xsl = (bf16*)(smraw + S_XSL);
    bf16* wsh = (bf16*)(smraw + S_WSH);
    bf16* wsl = (bf16*)(smraw + S_WSL);
    float* stg = (float*)(smraw + S_WSH);        // aliases WSH after GEMM
    float* prm = (float*)(smraw + S_PRM);
    float* psum = prm;            // [8][64]
    float* psq  = prm + 512;      // [8][64]
    float* mu   = prm + 1024;
    float* inv  = prm + 1088;

    const int t = threadIdx.x, wid = t >> 5, lane = t & 31;
    const int b = blockIdx.y, p0 = blockIdx.x * 64;
    const float* xb = x + (size_t)b * C_ * HW + p0;

    copy_w(g_we0h, g_we0l, wsh, wsl, t);

    {
        const int c2 = lane * 2;
        float s0=0, s1=0, q0=0, q1=0;
        #pragma unroll 1
        for (int it = 0; it < 12; it++) {
            float2 v = *(const float2*)(xb + (size_t)(it * 8 + wid) * HW + c2);
            s0 += v.x; s1 += v.y; q0 += v.x*v.x; q1 += v.y*v.y;
        }
        psum[wid*64 + c2] = s0; psum[wid*64 + c2 + 1] = s1;
        psq [wid*64 + c2] = q0; psq [wid*64 + c2 + 1] = q1;
    }
    __syncthreads();
    if (t < 64) {
        float s = 0.f, q = 0.f;
        #pragma unroll
        for (int g = 0; g < 8; g++) { s += psum[g*64 + t]; q += psq[g*64 + t]; }
        float m = s * (1.f / 96.f);
        mu[t] = m;
        inv[t] = rsqrtf(q * (1.f / 96.f) - m * m + 1e-6f);
    }
    __syncthreads();

    bf16* xnb = g_xnb + (size_t)b * C_ * HW + p0;
    for (int i = t; i < 768; i += 256) {
        int k = i >> 3, cc = (i & 7) * 8;
        const float* sp = xb + (size_t)k * HW + cc;
        float4 v0 = *(const float4*)(sp);
        float4 v1 = *(const float4*)(sp + 4);
        float lw = __ldg(&lnw[k]), lb = __ldg(&lnb[k]);
        float o0 = (v0.x - mu[cc+0]) * inv[cc+0] * lw + lb;
        float o1 = (v0.y - mu[cc+1]) * inv[cc+1] * lw + lb;
        float o2 = (v0.z - mu[cc+2]) * inv[cc+2] * lw + lb;
        float o3 = (v0.w - mu[cc+3]) * inv[cc+3] * lw + lb;
        float o4 = (v1.x - mu[cc+4]) * inv[cc+4] * lw + lb;
        float o5 = (v1.y - mu[cc+5]) * inv[cc+5] * lw + lb;
        float o6 = (v1.z - mu[cc+6]) * inv[cc+6] * lw + lb;
        float o7 = (v1.w - mu[cc+7]) * inv[cc+7] * lw + lb;
        bf16 h0,l0,h1,l1,h2,l2,h3,l3,h4,l4,h5,l5,h6,l6,h7,l7;
        split_bf16(o0,h0,l0); split_bf16(o1,h1,l1);
        split_bf16(o2,h2,l2); split_bf16(o3,h3,l3);
        split_bf16(o4,h4,l4); split_bf16(o5,h5,l5);
        split_bf16(o6,h6,l6); split_bf16(o7,h7,l7);
        *(uint4*)(xnb + (size_t)k * HW + cc) =
            make_uint4(pack2(h0,h1), pack2(h2,h3), pack2(h4,h5), pack2(h6,h7));
        uint2* ph = (uint2*)(xsh + k * LDW + cc);
        uint2* pl = (uint2*)(xsl + k * LDW + cc);
        ph[0] = make_uint2(pack2(h0,h1), pack2(h2,h3));
        ph[1] = make_uint2(pack2(h4,h5), pack2(h6,h7));
        pl[0] = make_uint2(pack2(l0,l1), pack2(l2,l3));
        pl[1] = make_uint2(pack2(l4,l5), pack2(l6,l7));
    }
    __syncthreads();

    const int wm = wid >> 2, wn = wid & 3;
    FragC acc[3];
    zero3(acc);
    gemm3(wsh, wsl, xsh, xsl, acc, wm, wn);
    __syncthreads();                 // ws dead -> stg alias safe

    float* st = stg + wid * 256;
    bf16* gb = g_e0b + (size_t)b * C_ * HW + p0;
    const int r = lane >> 1, c8 = (lane & 1) * 8;
    #pragma unroll
    for (int mf = 0; mf < 3; mf++) {
        wmma::store_matrix_sync(st, acc[mf], 16, wmma::mem_row_major);
        __syncwarp();
        int mm = wm*48 + mf*16 + r;
        int pp = wn*16 + c8;
        float bb = __ldg(&bias[mm]);
        const float* sp = st + r*16 + c8;
        float4 s0 = *(const float4*)(sp);
        float4 s1 = *(const float4*)(sp + 4);
        bf16 e0 = __float2bfloat16_rn(s0.x+bb), e1 = __float2bfloat16_rn(s0.y+bb);
        bf16 e2 = __float2bfloat16_rn(s0.z+bb), e3 = __float2bfloat16_rn(s0.w+bb);
        bf16 e4 = __float2bfloat16_rn(s1.x+bb), e5 = __float2bfloat16_rn(s1.y+bb);
        bf16 e6 = __float2bfloat16_rn(s1.z+bb), e7 = __float2bfloat16_rn(s1.w+bb);
        *(uint4*)(gb + (size_t)mm * HW + pp) =
            make_uint4(pack2(e0,e1), pack2(e2,e3), pack2(e4,e5), pack2(e6,e7));
        __syncwarp();
    }
}

// ---------------------------------------------------------------------------
// Kernel 2: depthwise experts + mixing -> xa bf16 hi/lo planes (vector fills)
// ---------------------------------------------------------------------------
__global__ __launch_bounds__(512, 2) void k_dw(
    const float* __restrict__ sw,
    const float* __restrict__ prompt,
    const float* __restrict__ w0, const float* __restrict__ b0,
    const float* __restrict__ w1, const float* __restrict__ b1,
    const float* __restrict__ w2, const float* __restrict__ b2)
{
    __shared__ float xs[76 * 88];
    __shared__ float es[66 * 88];
    __shared__ float kw[43];

    const int t = threadIdx.x;
    int c = blockIdx.y, b = blockIdx.z;
    int ty0 = (blockIdx.x >> 2) * 64;
    int tx0 = (blockIdx.x & 3) * 64;
    const bf16* xn = g_xnb + ((size_t)(b * C_ + c)) * HW;
    const bf16* ep = g_e0b + ((size_t)(b * C_ + c)) * HW;

    for (int i = t; i < 760; i += 512) {
        int r = i / 10, g = i % 10;
        int yy = ty0 - 6 + r;
        int xx = tx0 - 8 + g * 8;
        float4 f0, f1;
        if (yy >= 0 && yy < H_ && xx >= 0 && xx < W_) {
            uint4 v = *(const uint4*)(xn + yy * W_ + xx);
            float2 a0 = unp2(v.x), a1 = unp2(v.y), a2 = unp2(v.z), a3 = unp2(v.w);
            f0 = make_float4(a0.x, a0.y, a1.x, a1.y);
            f1 = make_float4(a2.x, a2.y, a3.x, a3.y);
        } else {
            f0 = make_float4(0.f, 0.f, 0.f, 0.f);
            f1 = f0;
        }
        float* d = xs + r * 88 + g * 8;
        *(float4*)(d)     = f0;
        *(float4*)(d + 4) = f1;
    }
    for (int i = t; i < 660; i += 512) {
        int r = i / 10, g = i % 10;
        int yy = ty0 - 1 + r;
        int xx = tx0 - 8 + g * 8;
        float4 f0, f1;
        if (yy >= 0 && yy < H_ && xx >= 0 && xx < W_) {
            uint4 v = *(const uint4*)(ep + yy * W_ + xx);
            float2 a0 = unp2(v.x), a1 = unp2(v.y), a2 = unp2(v.z), a3 = unp2(v.w);
            f0 = make_float4(a0.x, a0.y, a1.x, a1.y);
            f1 = make_float4(a2.x, a2.y, a3.x, a3.y);
        } else {
            f0 = make_float4(0.f, 0.f, 0.f, 0.f);
            f1 = f0;
        }
        float* d = es + r * 88 + g * 8;
        *(float4*)(d)     = f0;
        *(float4*)(d + 4) = f1;
    }
    if (t < 43) {
        kw[t] = (t < 9) ? __ldg(&w0[c*9 + t])
              : (t < 18) ? __ldg(&w1[c*9 + t - 9])
              : __ldg(&w2[c*25 + t - 18]);
    }
    float bb0 = __ldg(&b0[c]), bb1 = __ldg(&b1[c]), bb2 = __ldg(&b2[c]);
    float s0 = __ldg(&sw[b*3+0]), s1 = __ldg(&sw[b*3+1]), s2 = __ldg(&sw[b*3+2]);
    float pm = 1.f + __ldg(&prompt[b * C_ + c]);
    __syncthreads();

    const int py = t >> 3, px0 = (t & 7) * 8;
    float o[8], r8[8];

    #pragma unroll
    for (int j = 0; j < 8; j++) r8[j] = bb0;
    #pragma unroll
    for (int ky = 0; ky < 3; ky++)
        #pragma unroll
        for (int kx = 0; kx < 3; kx++) {
            float wv = kw[ky*3 + kx];
            const float* rowp = es + (py + ky) * 88 + px0 + kx + 7;
            #pragma unroll
            for (int j = 0; j < 8; j++) r8[j] += wv * rowp[j];
        }
    #pragma unroll
    for (int j = 0; j < 8; j++) o[j] = s0 * r8[j];

    #pragma unroll
    for (int j = 0; j < 8; j++) r8[j] = bb1;
    #pragma unroll
    for (int ky = 0; ky < 3; ky++)
        #pragma unroll
        for (int kx = 0; kx < 3; kx++) {
            float wv = kw[9 + ky*3 + kx];
            const float* rowp = xs + (py + 4 + 2*ky) * 88 + px0 + 2*kx + 6;
            #pragma unroll
            for (int j = 0; j < 8; j++) r8[j] += wv * rowp[j];
        }
    #pragma unroll
    for (int j = 0; j < 8; j++) o[j] += s1 * r8[j];

    #pragma unroll
    for (int j = 0; j < 8; j++) r8[j] = bb2;
    #pragma unroll
    for (int ky = 0; ky < 5; ky++)
        #pragma unroll
        for (int kx = 0; kx < 5; kx++) {
            float wv = kw[18 + ky*5 + kx];
            const float* rowp = xs + (py + 3*ky) * 88 + px0 + 3*kx + 2;
            #pragma unroll
            for (int j = 0; j < 8; j++) r8[j] += wv * rowp[j];
        }
    #pragma unroll
    for (int j = 0; j < 8; j++) o[j] = (o[j] + s2 * r8[j]) * pm;

    size_t go = ((size_t)(b * C_ + c)) * HW + (ty0 + py) * W_ + tx0 + px0;
    bf16 h0,l0,h1,l1,h2,l2,h3,l3,h4,l4,h5,l5,h6,l6,h7,l7;
    split_bf16(o[0],h0,l0); split_bf16(o[1],h1,l1);
    split_bf16(o[2],h2,l2); split_bf16(o[3],h3,l3);
    split_bf16(o[4],h4,l4); split_bf16(o[5],h5,l5);
    split_bf16(o[6],h6,l6); split_bf16(o[7],h7,l7);
    *(uint4*)(g_xah + go) = make_uint4(pack2(h0,h1), pack2(h2,h3), pack2(h4,h5), pack2(h6,h7));
    *(uint4*)(g_xal + go) = make_uint4(pack2(l0,l1), pack2(l2,l3), pack2(l4,l5), pack2(l6,l7));
}

// ---------------------------------------------------------------------------
// Kernel 3 (fused): x1 = x + proj(xa) + pb (f32 to global, single bf16 plane
// in smem) ; h = gelu(ffn1(x1) + b1) via 2-pass GEMM -> g_hb
// ---------------------------------------------------------------------------
__global__ __launch_bounds__(256, 3) void k_projffn1(
    const float* __restrict__ x, const float* __restrict__ pbias,
    const float* __restrict__ b1v)
{
    extern __shared__ unsigned char smraw[];
    bf16* xsh = (bf16*)(smraw + S_XSH);   // xa hi, then x1 single plane
    bf16* xsl = (bf16*)(smraw + S_XSL);   // xa lo (dead after proj GEMM)
    bf16* wsh = (bf16*)(smraw + S_WSH);
    bf16* wsl = (bf16*)(smraw + S_WSL);
    float* stg = (float*)(smraw + S_WSH);

    const int t = threadIdx.x, wid = t >> 5, lane = t & 31;
    const int b = blockIdx.y, p0 = blockIdx.x * 64;
    const size_t base = (size_t)b * C_ * HW + p0;

    copy_act2(g_xah + base, g_xal + base, xsh, xsl, t);
    copy_w(g_wpjh, g_wpjl, wsh, wsl, t);
    __syncthreads();

    const int wm = wid >> 2, wn = wid & 3;
    const int r = lane >> 1, c8 = (lane & 1) * 8;
    float* st = stg + wid * 256;

    // ---- proj GEMM (3-pass, full precision path) ----
    FragC acc[3];
    zero3(acc);
    gemm3(wsh, wsl, xsh, xsl, acc, wm, wn);
    __syncthreads();      // xa planes + wproj dead

    // epilogue: x1 = acc + pb + x -> global f32 + smem single bf16 plane
    const float* rb = x + base;
    float* x1g = g_x1 + base;
    #pragma unroll
    for (int mf = 0; mf < 3; mf++) {
        wmma::store_matrix_sync(st, acc[mf], 16, wmma::mem_row_major);
        __syncwarp();
        int mm = wm*48 + mf*16 + r;
        int pp = wn*16 + c8;
        float bb = __ldg(&pbias[mm]);
        const float* sp = st + r*16 + c8;
        const float* rp = rb + (size_t)mm * HW + pp;
        float4 s0 = *(const float4*)(sp);
        float4 s1 = *(const float4*)(sp + 4);
        float4 r0 = *(const float4*)(rp);
        float4 r1 = *(const float4*)(rp + 4);
        float v0 = s0.x+bb+r0.x, v1 = s0.y+bb+r0.y, v2 = s0.z+bb+r0.z, v3 = s0.w+bb+r0.w;
        float v4 = s1.x+bb+r1.x, v5 = s1.y+bb+r1.y, v6 = s1.z+bb+r1.z, v7 = s1.w+bb+r1.w;
        float* gp = x1g + (size_t)mm * HW + pp;
        *(float4*)(gp)     = make_float4(v0, v1, v2, v3);
        *(float4*)(gp + 4) = make_float4(v4, v5, v6, v7);
        bf16 h0 = __float2bfloat16_rn(v0), h1 = __float2bfloat16_rn(v1);
        bf16 h2 = __float2bfloat16_rn(v2), h3 = __float2bfloat16_rn(v3);
        bf16 h4 = __float2bfloat16_rn(v4), h5 = __float2bfloat16_rn(v5);
        bf16 h6 = __float2bfloat16_rn(v6), h7 = __float2bfloat16_rn(v7);
        uint2* ph = (uint2*)(xsh + mm * LDW + pp);
        ph[0] = make_uint2(pack2(h0,h1), pack2(h2,h3));
        ph[1] = make_uint2(pack2(h4,h5), pack2(h6,h7));
        __syncwarp();
    }

    // ---- ffn1: two 96-row chunks, 2-pass GEMM on single-plane x1 ----
    bf16* hb = g_hb + (size_t)b * 192 * HW + p0;
    #pragma unroll 1
    for (int oc = 0; oc < 2; oc++) {
        __syncthreads();                       // x1 plane ready / stg readers done
        copy_w(g_w1h + oc * 96 * LDA, g_w1l + oc * 96 * LDA, wsh, wsl, t);
        __syncthreads();

        FragC a1[3];
        zero3(a1);
        gemm2(wsh, wsl, xsh, a1, wm, wn);
        __syncthreads();                       // ws dead -> stg alias

        #pragma unroll
        for (int mf = 0; mf < 3; mf++) {
            wmma::store_matrix_sync(st, a1[mf], 16, wmma::mem_row_major);
            __syncwarp();
            int k2 = oc*96 + wm*48 + mf*16 + r;
            int pp = wn*16 + c8;
            float bb = __ldg(&b1v[k2]);
            const float* sp = st + r*16 + c8;
            float4 s0 = *(const float4*)(sp);
            float4 s1 = *(const float4*)(sp + 4);
            bf16 g0 = __float2bfloat16_rn(gelu_fast(s0.x+bb));
            bf16 g1 = __float2bfloat16_rn(gelu_fast(s0.y+bb));
            bf16 g2 = __float2bfloat16_rn(gelu_fast(s0.z+bb));
            bf16 g3 = __float2bfloat16_rn(gelu_fast(s0.w+bb));
            bf16 g4 = __float2bfloat16_rn(gelu_fast(s1.x+bb));
            bf16 g5 = __float2bfloat16_rn(gelu_fast(s1.y+bb));
            bf16 g6 = __float2bfloat16_rn(gelu_fast(s1.z+bb));
            bf16 g7 = __float2bfloat16_rn(gelu_fast(s1.w+bb));
            *(uint4*)(hb + (size_t)k2 * HW + pp) =
                make_uint4(pack2(g0,g1), pack2(g2,g3), pack2(g4,g5), pack2(g6,g7));
            __syncwarp();
        }
    }
}

// ---------------------------------------------------------------------------
// Kernel 4: out = x1 + ffn2(h) + b2   (K=192, h single-plane, 2-pass GEMM)
// ---------------------------------------------------------------------------
__global__ __launch_bounds__(256, 3) void k_ffn2(
    const float* __restrict__ b2v, float* __restrict__ out)
{
    extern __shared__ unsigned char smraw[];
    bf16* hs  = (bf16*)(smraw + S_XSH);    // single plane [96][LDW]
    bf16* wsh = (bf16*)(smraw + S_WSH);
    bf16* wsl = (bf16*)(smraw + S_WSL);
    float* stg = (float*)(smraw + S_WSH);

    const int t = threadIdx.x, wid = t >> 5, lane = t & 31;
    const int b = blockIdx.y, p0 = blockIdx.x * 64;
    const bf16* hb = g_hb + (size_t)b * 192 * HW + p0;

    const int wm = wid >> 2, wn = wid & 3;
    FragC acc[3];
    zero3(acc);

    #pragma unroll 1
    for (int kc = 0; kc < 2; kc++) {
        if (kc) __syncthreads();               // prior readers done
        for (int i = t; i < 768; i += 256) {   // pure uint4 copies
            int r = i >> 3, cc = (i & 7) * 8;
            *(uint4*)(hs + r * LDW + cc) =
                *(const uint4*)(hb + (size_t)(kc * 96 + r) * HW + cc);
        }
        copy_w(g_w2h + kc * 96 * LDA, g_w2l + kc * 96 * LDA, wsh, wsl, t);
        __syncthreads();
        gemm2(wsh, wsl, hs, acc, wm, wn);
    }
    __syncthreads();                           // ws dead -> stg alias

    float* st = stg + wid * 256;
    const float* x1b = g_x1 + (size_t)b * C_ * HW + p0;
    float* ob = out + (size_t)b * C_ * HW + p0;
    const int r = lane >> 1, c8 = (lane & 1) * 8;
    #pragma unroll
    for (int mf = 0; mf < 3; mf++) {
        wmma::store_matrix_sync(st, acc[mf], 16, wmma::mem_row_major);
        __syncwarp();
        int mm = wm*48 + mf*16 + r;
        int pp = wn*16 + c8;
        float bb = __ldg(&b2v[mm]);
        const float* sp = st + r*16 + c8;
        const float* rp = x1b + (size_t)mm * HW + pp;
        float4 s0 = *(const float4*)(sp);
        float4 s1 = *(const float4*)(sp + 4);
        float4 r0 = *(const float4*)(rp);
        float4 r1 = *(const float4*)(rp + 4);
        float* gp = ob + (size_t)mm * HW + pp;
        *(float4*)(gp)     = make_float4(s0.x+bb+r0.x, s0.y+bb+r0.y, s0.z+bb+r0.z, s0.w+bb+r0.w);
        *(float4*)(gp + 4) = make_float4(s1.x+bb+r1.x, s1.y+bb+r1.y, s1.z+bb+r1.z, s1.w+bb+r1.w);
        __syncwarp();
    }
}

// ---------------------------------------------------------------------------
extern "C" void kernel_launch(void* const* d_in, const int* in_sizes, int n_in,
                              void* d_out, int out_size)
{
    const float* x       = (const float*)d_in[0];
    const float* prompt  = (const float*)d_in[1];
    const float* sweights= (const float*)d_in[2];
    const float* ln_w    = (const float*)d_in[3];
    const float* ln_b    = (const float*)d_in[4];
    const float* e0_pw_w = (const float*)d_in[5];
    const float* e0_pw_b = (const float*)d_in[6];
    const float* e0_dw_w = (const float*)d_in[7];
    const float* e0_dw_b = (const float*)d_in[8];
    const float* e1_dw_w = (const float*)d_in[9];
    const float* e1_dw_b = (const float*)d_in[10];
    const float* e2_dw_w = (const float*)d_in[11];
    const float* e2_dw_b = (const float*)d_in[12];
    const float* proj_w  = (const float*)d_in[13];
    const float* proj_b  = (const float*)d_in[14];
    const float* ffn1_w  = (const float*)d_in[15];
    const float* ffn1_b  = (const float*)d_in[16];
    const float* ffn2_w  = (const float*)d_in[17];
    const float* ffn2_b  = (const float*)d_in[18];
    float* out = (float*)d_out;

    cudaFuncSetAttribute(k_ln_e0pw,  cudaFuncAttributeMaxDynamicSharedMemorySize, S_END);
    cudaFuncSetAttribute(k_projffn1, cudaFuncAttributeMaxDynamicSharedMemorySize, S_END);
    cudaFuncSetAttribute(k_ffn2,     cudaFuncAttributeMaxDynamicSharedMemorySize, S_END);

    dim3 gg(HW / 64, B_);

    k_prep<<<216, 256>>>(e0_pw_w, proj_w, ffn1_w, ffn2_w);

    k_ln_e0pw<<<gg, 256, S_END>>>(x, ln_w, ln_b, e0_pw_b);

    dim3 gdw(16, C_, B_);
    k_dw<<<gdw, 512>>>(sweights, prompt,
                       e0_dw_w, e0_dw_b, e1_dw_w, e1_dw_b, e2_dw_w, e2_dw_b);

    k_projffn1<<<gg, 256, S_END>>>(x, proj_b, ffn1_b);

    k_ffn2<<<gg, 256, S_END>>>(ffn2_b, out);
}

// round 17
// speedup vs baseline: 2.2459x; 1.0629x over previous
#include <cuda_runtime.h>
#include <cuda_bf16.h>
#include <mma.h>
#include <math.h>
#include <stdint.h>

using namespace nvcuda;

#define B_ 4
#define C_ 96
#define H_ 256
#define W_ 256
#define HW (H_*W_)
#define LDA 104
#define LDW 72        // 64-px tile B row stride (bf16)

typedef __nv_bfloat16 bf16;

// Scratch (allocation-free rule: __device__ globals)
__device__ bf16  g_xnb[B_*C_*HW];   // layernorm output (bf16)
__device__ bf16  g_e0b[B_*C_*HW];   // e0 pre-activation (bf16)
__device__ bf16  g_xah[B_*C_*HW];   // x_adaptive hi plane
__device__ bf16  g_xal[B_*C_*HW];   // x_adaptive lo plane

// Pre-split weights (hi/lo) in padded [96][LDA] smem-image layout
__device__ __align__(16) bf16 g_we0h[96*LDA],  g_we0l[96*LDA];
__device__ __align__(16) bf16 g_wpjh[96*LDA],  g_wpjl[96*LDA];
__device__ __align__(16) bf16 g_w1h[2*96*LDA], g_w1l[2*96*LDA];
__device__ __align__(16) bf16 g_w2h[2*96*LDA], g_w2l[2*96*LDA];

using FragA = wmma::fragment<wmma::matrix_a, 16, 16, 16, bf16, wmma::row_major>;
using FragB = wmma::fragment<wmma::matrix_b, 16, 16, 16, bf16, wmma::row_major>;
using FragC = wmma::fragment<wmma::accumulator, 16, 16, 16, float>;

__device__ __forceinline__ void split_bf16(float v, bf16& h, bf16& l) {
    h = __float2bfloat16_rn(v);
    l = __float2bfloat16_rn(v - __bfloat162float(h));
}

__device__ __forceinline__ unsigned pack2(bf16 a, bf16 b) {
    unsigned short ra = *reinterpret_cast<unsigned short*>(&a);
    unsigned short rb = *reinterpret_cast<unsigned short*>(&b);
    return (unsigned)ra | ((unsigned)rb << 16);
}

__device__ __forceinline__ float2 unp2(unsigned u) {
    __nv_bfloat162 b = *reinterpret_cast<__nv_bfloat162*>(&u);
    return __bfloat1622float2(b);
}

// Fast GELU: tanh formulation with HW tanh.approx (MUFU.TANH).
__device__ __forceinline__ float gelu_fast(float h) {
    float u = 0.7978845608f * fmaf(0.044715f * h, h * h, h);
    float t;
    asm("tanh.approx.f32 %0, %1;" : "=f"(t) : "f"(u));
    return 0.5f * h * (1.f + t);
}

// Copy pre-split weight chunk ([96][LDA] bf16 x2) global(L2-hot) -> smem.
__device__ __forceinline__ void copy_w(const bf16* __restrict__ srch,
                                       const bf16* __restrict__ srcl,
                                       bf16* wsh, bf16* wsl, int t)
{
    const uint4* sh = (const uint4*)srch;
    const uint4* sl = (const uint4*)srcl;
    uint4* dh = (uint4*)wsh;
    uint4* dl = (uint4*)wsl;
    #pragma unroll
    for (int i = 0; i < 5; i++) {
        int j = t + i * 256;
        if (j < 1248) { dh[j] = sh[j]; dl[j] = sl[j]; }
    }
}

// Copy bf16 hi/lo activation planes tile [96 ch][64 px] -> smem (pure uint4)
__device__ __forceinline__ void copy_act2(const bf16* __restrict__ srch,
                                          const bf16* __restrict__ srcl,
                                          bf16* xh, bf16* xl, int t)
{
    for (int i = t; i < 768; i += 256) {   // 96 rows x 8 px-groups
        int k = i >> 3, cc = (i & 7) * 8;
        size_t go = (size_t)k * HW + cc;
        *(uint4*)(xh + k * LDW + cc) = *(const uint4*)(srch + go);
        *(uint4*)(xl + k * LDW + cc) = *(const uint4*)(srcl + go);
    }
}

// 3-pass GEMM: C[96 x 64] += A[96x96] * B[96x64]. 8 warps: wm 0..1, wn 0..3.
__device__ __forceinline__ void gemm3(
    const bf16* ah, const bf16* al, const bf16* bh, const bf16* bl,
    FragC (&acc)[3], int wm, int wn)
{
    #pragma unroll 1
    for (int k = 0; k < 6; k++) {
        FragB b_h, b_l;
        wmma::load_matrix_sync(b_h, bh + (k*16)*LDW + wn*16, LDW);
        wmma::load_matrix_sync(b_l, bl + (k*16)*LDW + wn*16, LDW);
        #pragma unroll
        for (int mf = 0; mf < 3; mf++) {
            FragA a_h, a_l;
            wmma::load_matrix_sync(a_h, ah + (wm*48 + mf*16)*LDA + k*16, LDA);
            wmma::load_matrix_sync(a_l, al + (wm*48 + mf*16)*LDA + k*16, LDA);
            wmma::mma_sync(acc[mf], a_h, b_h, acc[mf]);
            wmma::mma_sync(acc[mf], a_h, b_l, acc[mf]);
            wmma::mma_sync(acc[mf], a_l, b_h, acc[mf]);
        }
    }
}

// 2-pass GEMM (B single-plane): C += (Ah + Al) * B
__device__ __forceinline__ void gemm2(
    const bf16* ah, const bf16* al, const bf16* b,
    FragC (&acc)[3], int wm, int wn)
{
    #pragma unroll 1
    for (int k = 0; k < 6; k++) {
        FragB bf;
        wmma::load_matrix_sync(bf, b + (k*16)*LDW + wn*16, LDW);
        #pragma unroll
        for (int mf = 0; mf < 3; mf++) {
            FragA a_h, a_l;
            wmma::load_matrix_sync(a_h, ah + (wm*48 + mf*16)*LDA + k*16, LDA);
            wmma::load_matrix_sync(a_l, al + (wm*48 + mf*16)*LDA + k*16, LDA);
            wmma::mma_sync(acc[mf], a_h, bf, acc[mf]);
            wmma::mma_sync(acc[mf], a_l, bf, acc[mf]);
        }
    }
}

__device__ __forceinline__ void zero3(FragC (&acc)[3]) {
    #pragma unroll
    for (int mf = 0; mf < 3; mf++) wmma::fill_fragment(acc[mf], 0.f);
}

// smem layout for ln kernel (bytes)
#define S_XSH 0
#define S_XSL 13824
#define S_WSH 27648
#define S_WSL 47616
#define S_PRM 67584
#define S_END (S_PRM + 4608)

// smem layout for fused proj+ffn kernel (bytes)
#define F_A    0        /* xa hi/lo (13824+13824), later x1 f32 [96][72] */
#define F_X1B  27648    /* x1 bf16 plane [96][LDW] : 13824 */
#define F_H    41472    /* h bf16 plane  [96][LDW] : 13824 */
#define F_WSH  55296    /* 19968 (stage aliases here) */
#define F_WSL  75264    /* 19968 */
#define F_END  95232

// ---------------------------------------------------------------------------
// Weight prep: f32 -> bf16 hi/lo in padded layouts (once per launch)
// ---------------------------------------------------------------------------
__global__ void k_prep(const float* __restrict__ e0, const float* __restrict__ pj,
                       const float* __restrict__ w1, const float* __restrict__ w2)
{
    int i = blockIdx.x * 256 + threadIdx.x;
    float v; bf16 *dh, *dl; int off;
    if (i < 9216) {
        int m = i / 96, k = i % 96;
        v = e0[i]; dh = g_we0h; dl = g_we0l; off = m * LDA + k;
    } else if (i < 18432) {
        int j = i - 9216; int m = j / 96, k = j % 96;
        v = pj[j]; dh = g_wpjh; dl = g_wpjl; off = m * LDA + k;
    } else if (i < 36864) {
        int j = i - 18432; int m = j / 96, k = j % 96;     // m 0..191
        v = w1[j]; dh = g_w1h; dl = g_w1l;
        off = (m / 96) * 96 * LDA + (m % 96) * LDA + k;
    } else if (i < 55296) {
        int j = i - 36864; int m = j / 192, k = j % 192;   // w2 [96][192]
        v = w2[j]; dh = g_w2h; dl = g_w2l;
        off = (k / 96) * 96 * LDA + m * LDA + (k % 96);
    } else return;
    bf16 h, l; split_bf16(v, h, l);
    dh[off] = h; dl[off] = l;
}

// ---------------------------------------------------------------------------
// Kernel 1: LayerNorm (2-phase global read) + e0 pointwise -> g_xnb, g_e0b
// ---------------------------------------------------------------------------
__global__ __launch_bounds__(256, 3) void k_ln_e0pw(
    const float* __restrict__ x,
    const float* __restrict__ lnw, const float* __restrict__ lnb,
    const float* __restrict__ bias)
{
    extern __shared__ unsigned char smraw[];
    bf16* xsh = (bf16*)(smraw + S_XSH);
    bf16* xsl = (bf16*)(smraw + S_XSL);
    bf16* wsh = (bf16*)(smraw + S_WSH);
    bf16* wsl = (bf16*)(smraw + S_WSL);
    float* stg = (float*)(smraw + S_WSH);        // aliases WSH after GEMM
    float* prm = (float*)(smraw + S_PRM);
    float* psum = prm;            // [8][64]
    float* psq  = prm + 512;      // [8][64]
    float* mu   = prm + 1024;
    float* inv  = prm + 1088;

    const int t = threadIdx.x, wid = t >> 5, lane = t & 31;
    const int b = blockIdx.y, p0 = blockIdx.x * 64;
    const float* xb = x + (size_t)b * C_ * HW + p0;

    copy_w(g_we0h, g_we0l, wsh, wsl, t);

    {
        const int c2 = lane * 2;
        float s0=0, s1=0, q0=0, q1=0;
        #pragma unroll 1
        for (int it = 0; it < 12; it++) {
            float2 v = *(const float2*)(xb + (size_t)(it * 8 + wid) * HW + c2);
            s0 += v.x; s1 += v.y; q0 += v.x*v.x; q1 += v.y*v.y;
        }
        psum[wid*64 + c2] = s0; psum[wid*64 + c2 + 1] = s1;
        psq [wid*64 + c2] = q0; psq [wid*64 + c2 + 1] = q1;
    }
    __syncthreads();
    if (t < 64) {
        float s = 0.f, q = 0.f;
        #pragma unroll
        for (int g = 0; g < 8; g++) { s += psum[g*64 + t]; q += psq[g*64 + t]; }
        float m = s * (1.f / 96.f);
        mu[t] = m;
        inv[t] = rsqrtf(q * (1.f / 96.f) - m * m + 1e-6f);
    }
    __syncthreads();

    bf16* xnb = g_xnb + (size_t)b * C_ * HW + p0;
    for (int i = t; i < 768; i += 256) {
        int k = i >> 3, cc = (i & 7) * 8;
        const float* sp = xb + (size_t)k * HW + cc;
        float4 v0 = *(const float4*)(sp);
        float4 v1 = *(const float4*)(sp + 4);
        float lw = __ldg(&lnw[k]), lb = __ldg(&lnb[k]);
        float o0 = (v0.x - mu[cc+0]) * inv[cc+0] * lw + lb;
        float o1 = (v0.y - mu[cc+1]) * inv[cc+1] * lw + lb;
        float o2 = (v0.z - mu[cc+2]) * inv[cc+2] * lw + lb;
        float o3 = (v0.w - mu[cc+3]) * inv[cc+3] * lw + lb;
        float o4 = (v1.x - mu[cc+4]) * inv[cc+4] * lw + lb;
        float o5 = (v1.y - mu[cc+5]) * inv[cc+5] * lw + lb;
        float o6 = (v1.z - mu[cc+6]) * inv[cc+6] * lw + lb;
        float o7 = (v1.w - mu[cc+7]) * inv[cc+7] * lw + lb;
        bf16 h0,l0,h1,l1,h2,l2,h3,l3,h4,l4,h5,l5,h6,l6,h7,l7;
        split_bf16(o0,h0,l0); split_bf16(o1,h1,l1);
        split_bf16(o2,h2,l2); split_bf16(o3,h3,l3);
        split_bf16(o4,h4,l4); split_bf16(o5,h5,l5);
        split_bf16(o6,h6,l6); split_bf16(o7,h7,l7);
        *(uint4*)(xnb + (size_t)k * HW + cc) =
            make_uint4(pack2(h0,h1), pack2(h2,h3), pack2(h4,h5), pack2(h6,h7));
        uint2* ph = (uint2*)(xsh + k * LDW + cc);
        uint2* pl = (uint2*)(xsl + k * LDW + cc);
        ph[0] = make_uint2(pack2(h0,h1), pack2(h2,h3));
        ph[1] = make_uint2(pack2(h4,h5), pack2(h6,h7));
        pl[0] = make_uint2(pack2(l0,l1), pack2(l2,l3));
        pl[1] = make_uint2(pack2(l4,l5), pack2(l6,l7));
    }
    __syncthreads();

    const int wm = wid >> 2, wn = wid & 3;
    FragC acc[3];
    zero3(acc);
    gemm3(wsh, wsl, xsh, xsl, acc, wm, wn);
    __syncthreads();                 // ws dead -> stg alias safe

    float* st = stg + wid * 256;
    bf16* gb = g_e0b + (size_t)b * C_ * HW + p0;
    const int r = lane >> 1, c8 = (lane & 1) * 8;
    #pragma unroll
    for (int mf = 0; mf < 3; mf++) {
        wmma::store_matrix_sync(st, acc[mf], 16, wmma::mem_row_major);
        __syncwarp();
        int mm = wm*48 + mf*16 + r;
        int pp = wn*16 + c8;
        float bb = __ldg(&bias[mm]);
        const float* sp = st + r*16 + c8;
        float4 s0 = *(const float4*)(sp);
        float4 s1 = *(const float4*)(sp + 4);
        bf16 e0 = __float2bfloat16_rn(s0.x+bb), e1 = __float2bfloat16_rn(s0.y+bb);
        bf16 e2 = __float2bfloat16_rn(s0.z+bb), e3 = __float2bfloat16_rn(s0.w+bb);
        bf16 e4 = __float2bfloat16_rn(s1.x+bb), e5 = __float2bfloat16_rn(s1.y+bb);
        bf16 e6 = __float2bfloat16_rn(s1.z+bb), e7 = __float2bfloat16_rn(s1.w+bb);
        *(uint4*)(gb + (size_t)mm * HW + pp) =
            make_uint4(pack2(e0,e1), pack2(e2,e3), pack2(e4,e5), pack2(e6,e7));
        __syncwarp();
    }
}

// ---------------------------------------------------------------------------
// Kernel 2: depthwise experts + mixing -> xa bf16 hi/lo planes (vector fills)
// ---------------------------------------------------------------------------
__global__ __launch_bounds__(512, 2) void k_dw(
    const float* __restrict__ sw,
    const float* __restrict__ prompt,
    const float* __restrict__ w0, const float* __restrict__ b0,
    const float* __restrict__ w1, const float* __restrict__ b1,
    const float* __restrict__ w2, const float* __restrict__ b2)
{
    __shared__ float xs[76 * 88];
    __shared__ float es[66 * 88];
    __shared__ float kw[43];

    const int t = threadIdx.x;
    int c = blockIdx.y, b = blockIdx.z;
    int ty0 = (blockIdx.x >> 2) * 64;
    int tx0 = (blockIdx.x & 3) * 64;
    const bf16* xn = g_xnb + ((size_t)(b * C_ + c)) * HW;
    const bf16* ep = g_e0b + ((size_t)(b * C_ + c)) * HW;

    for (int i = t; i < 760; i += 512) {
        int r = i / 10, g = i % 10;
        int yy = ty0 - 6 + r;
        int xx = tx0 - 8 + g * 8;
        float4 f0, f1;
        if (yy >= 0 && yy < H_ && xx >= 0 && xx < W_) {
            uint4 v = *(const uint4*)(xn + yy * W_ + xx);
            float2 a0 = unp2(v.x), a1 = unp2(v.y), a2 = unp2(v.z), a3 = unp2(v.w);
            f0 = make_float4(a0.x, a0.y, a1.x, a1.y);
            f1 = make_float4(a2.x, a2.y, a3.x, a3.y);
        } else {
            f0 = make_float4(0.f, 0.f, 0.f, 0.f);
            f1 = f0;
        }
        float* d = xs + r * 88 + g * 8;
        *(float4*)(d)     = f0;
        *(float4*)(d + 4) = f1;
    }
    for (int i = t; i < 660; i += 512) {
        int r = i / 10, g = i % 10;
        int yy = ty0 - 1 + r;
        int xx = tx0 - 8 + g * 8;
        float4 f0, f1;
        if (yy >= 0 && yy < H_ && xx >= 0 && xx < W_) {
            uint4 v = *(const uint4*)(ep + yy * W_ + xx);
            float2 a0 = unp2(v.x), a1 = unp2(v.y), a2 = unp2(v.z), a3 = unp2(v.w);
            f0 = make_float4(a0.x, a0.y, a1.x, a1.y);
            f1 = make_float4(a2.x, a2.y, a3.x, a3.y);
        } else {
            f0 = make_float4(0.f, 0.f, 0.f, 0.f);
            f1 = f0;
        }
        float* d = es + r * 88 + g * 8;
        *(float4*)(d)     = f0;
        *(float4*)(d + 4) = f1;
    }
    if (t < 43) {
        kw[t] = (t < 9) ? __ldg(&w0[c*9 + t])
              : (t < 18) ? __ldg(&w1[c*9 + t - 9])
              : __ldg(&w2[c*25 + t - 18]);
    }
    float bb0 = __ldg(&b0[c]), bb1 = __ldg(&b1[c]), bb2 = __ldg(&b2[c]);
    float s0 = __ldg(&sw[b*3+0]), s1 = __ldg(&sw[b*3+1]), s2 = __ldg(&sw[b*3+2]);
    float pm = 1.f + __ldg(&prompt[b * C_ + c]);
    __syncthreads();

    const int py = t >> 3, px0 = (t & 7) * 8;
    float o[8], r8[8];

    #pragma unroll
    for (int j = 0; j < 8; j++) r8[j] = bb0;
    #pragma unroll
    for (int ky = 0; ky < 3; ky++)
        #pragma unroll
        for (int kx = 0; kx < 3; kx++) {
            float wv = kw[ky*3 + kx];
            const float* rowp = es + (py + ky) * 88 + px0 + kx + 7;
            #pragma unroll
            for (int j = 0; j < 8; j++) r8[j] += wv * rowp[j];
        }
    #pragma unroll
    for (int j = 0; j < 8; j++) o[j] = s0 * r8[j];

    #pragma unroll
    for (int j = 0; j < 8; j++) r8[j] = bb1;
    #pragma unroll
    for (int ky = 0; ky < 3; ky++)
        #pragma unroll
        for (int kx = 0; kx < 3; kx++) {
            float wv = kw[9 + ky*3 + kx];
            const float* rowp = xs + (py + 4 + 2*ky) * 88 + px0 + 2*kx + 6;
            #pragma unroll
            for (int j = 0; j < 8; j++) r8[j] += wv * rowp[j];
        }
    #pragma unroll
    for (int j = 0; j < 8; j++) o[j] += s1 * r8[j];

    #pragma unroll
    for (int j = 0; j < 8; j++) r8[j] = bb2;
    #pragma unroll
    for (int ky = 0; ky < 5; ky++)
        #pragma unroll
        for (int kx = 0; kx < 5; kx++) {
            float wv = kw[18 + ky*5 + kx];
            const float* rowp = xs + (py + 3*ky) * 88 + px0 + 3*kx + 2;
            #pragma unroll
            for (int j = 0; j < 8; j++) r8[j] += wv * rowp[j];
        }
    #pragma unroll
    for (int j = 0; j < 8; j++) o[j] = (o[j] + s2 * r8[j]) * pm;

    size_t go = ((size_t)(b * C_ + c)) * HW + (ty0 + py) * W_ + tx0 + px0;
    bf16 h0,l0,h1,l1,h2,l2,h3,l3,h4,l4,h5,l5,h6,l6,h7,l7;
    split_bf16(o[0],h0,l0); split_bf16(o[1],h1,l1);
    split_bf16(o[2],h2,l2); split_bf16(o[3],h3,l3);
    split_bf16(o[4],h4,l4); split_bf16(o[5],h5,l5);
    split_bf16(o[6],h6,l6); split_bf16(o[7],h7,l7);
    *(uint4*)(g_xah + go) = make_uint4(pack2(h0,h1), pack2(h2,h3), pack2(h4,h5), pack2(h6,h7));
    *(uint4*)(g_xal + go) = make_uint4(pack2(l0,l1), pack2(l2,l3), pack2(l4,l5), pack2(l6,l7));
}

// ---------------------------------------------------------------------------
// Kernel 3 (fully fused): x1 = x + proj(xa) + pb (smem only, f32 + bf16 plane)
//   h_oc = gelu(ffn1_oc(x1))  (smem plane, ping-pong per chunk)
//   out = x1 + ffn2(h) + b2   (acc across both chunks)
// x1 and h never touch DRAM.
// ---------------------------------------------------------------------------
__global__ __launch_bounds__(256, 2) void k_fused(
    const float* __restrict__ x, const float* __restrict__ pbias,
    const float* __restrict__ b1v, const float* __restrict__ b2v,
    float* __restrict__ out)
{
    extern __shared__ unsigned char smraw[];
    bf16* xah  = (bf16*)(smraw + F_A);           // xa hi
    bf16* xal  = (bf16*)(smraw + F_A + 13824);   // xa lo
    float* x1f = (float*)(smraw + F_A);          // x1 f32 [96][72] (aliases xa)
    bf16* x1b  = (bf16*)(smraw + F_X1B);         // x1 bf16 plane
    bf16* hsp  = (bf16*)(smraw + F_H);           // h bf16 plane (per chunk)
    bf16* wsh  = (bf16*)(smraw + F_WSH);
    bf16* wsl  = (bf16*)(smraw + F_WSL);
    float* stg = (float*)(smraw + F_WSH);        // stage aliases WSH when dead

    const int t = threadIdx.x, wid = t >> 5, lane = t & 31;
    const int b = blockIdx.y, p0 = blockIdx.x * 64;
    const size_t base = (size_t)b * C_ * HW + p0;

    copy_act2(g_xah + base, g_xal + base, xah, xal, t);
    copy_w(g_wpjh, g_wpjl, wsh, wsl, t);
    __syncthreads();

    const int wm = wid >> 2, wn = wid & 3;
    const int r = lane >> 1, c8 = (lane & 1) * 8;
    float* st = stg + wid * 256;

    // ---- proj GEMM (3-pass, full precision path) ----
    FragC acc[3];
    zero3(acc);
    gemm3(wsh, wsl, xah, xal, acc, wm, wn);
    __syncthreads();      // xa planes + wproj dead

    // ---- epilogue: x1 = acc + pb + x -> x1f (smem f32) + x1b (bf16 plane) ----
    const float* rb = x + base;
    #pragma unroll
    for (int mf = 0; mf < 3; mf++) {
        wmma::store_matrix_sync(st, acc[mf], 16, wmma::mem_row_major);
        __syncwarp();
        int mm = wm*48 + mf*16 + r;
        int pp = wn*16 + c8;
        float bb = __ldg(&pbias[mm]);
        const float* sp = st + r*16 + c8;
        const float* rp = rb + (size_t)mm * HW + pp;
        float4 s0 = *(const float4*)(sp);
        float4 s1 = *(const float4*)(sp + 4);
        float4 r0 = *(const float4*)(rp);
        float4 r1 = *(const float4*)(rp + 4);
        float v0 = s0.x+bb+r0.x, v1 = s0.y+bb+r0.y, v2 = s0.z+bb+r0.z, v3 = s0.w+bb+r0.w;
        float v4 = s1.x+bb+r1.x, v5 = s1.y+bb+r1.y, v6 = s1.z+bb+r1.z, v7 = s1.w+bb+r1.w;
        float* fp = x1f + mm * 72 + pp;
        *(float4*)(fp)     = make_float4(v0, v1, v2, v3);
        *(float4*)(fp + 4) = make_float4(v4, v5, v6, v7);
        bf16 h0 = __float2bfloat16_rn(v0), h1 = __float2bfloat16_rn(v1);
        bf16 h2 = __float2bfloat16_rn(v2), h3 = __float2bfloat16_rn(v3);
        bf16 h4 = __float2bfloat16_rn(v4), h5 = __float2bfloat16_rn(v5);
        bf16 h6 = __float2bfloat16_rn(v6), h7 = __float2bfloat16_rn(v7);
        uint2* ph = (uint2*)(x1b + mm * LDW + pp);
        ph[0] = make_uint2(pack2(h0,h1), pack2(h2,h3));
        ph[1] = make_uint2(pack2(h4,h5), pack2(h6,h7));
        __syncwarp();
    }

    // ---- per-chunk: ffn1 -> gelu -> h plane -> ffn2 accumulate ----
    FragC acc2[3];
    zero3(acc2);
    #pragma unroll 1
    for (int oc = 0; oc < 2; oc++) {
        __syncthreads();       // x1 planes ready / prior ws readers + stg done
        copy_w(g_w1h + oc * 96 * LDA, g_w1l + oc * 96 * LDA, wsh, wsl, t);
        __syncthreads();

        FragC a1[3];
        zero3(a1);
        gemm2(wsh, wsl, x1b, a1, wm, wn);
        __syncthreads();       // w1 dead -> stg alias

        #pragma unroll
        for (int mf = 0; mf < 3; mf++) {
            wmma::store_matrix_sync(st, a1[mf], 16, wmma::mem_row_major);
            __syncwarp();
            int kk = wm*48 + mf*16 + r;          // row within chunk 0..95
            int pp = wn*16 + c8;
            float bb = __ldg(&b1v[oc*96 + kk]);
            const float* sp = st + r*16 + c8;
            float4 s0 = *(const float4*)(sp);
            float4 s1 = *(const float4*)(sp + 4);
            bf16 g0 = __float2bfloat16_rn(gelu_fast(s0.x+bb));
            bf16 g1 = __float2bfloat16_rn(gelu_fast(s0.y+bb));
            bf16 g2 = __float2bfloat16_rn(gelu_fast(s0.z+bb));
            bf16 g3 = __float2bfloat16_rn(gelu_fast(s0.w+bb));
            bf16 g4 = __float2bfloat16_rn(gelu_fast(s1.x+bb));
            bf16 g5 = __float2bfloat16_rn(gelu_fast(s1.y+bb));
            bf16 g6 = __float2bfloat16_rn(gelu_fast(s1.z+bb));
            bf16 g7 = __float2bfloat16_rn(gelu_fast(s1.w+bb));
            uint2* hp = (uint2*)(hsp + kk * LDW + pp);
            hp[0] = make_uint2(pack2(g0,g1), pack2(g2,g3));
            hp[1] = make_uint2(pack2(g4,g5), pack2(g6,g7));
            __syncwarp();
        }
        __syncthreads();       // h plane complete + stg done

        copy_w(g_w2h + oc * 96 * LDA, g_w2l + oc * 96 * LDA, wsh, wsl, t);
        __syncthreads();
        gemm2(wsh, wsl, hsp, acc2, wm, wn);
        __syncthreads();       // w2 + h readers done (next oc overwrites both)
    }

    // ---- final epilogue: out = acc2 + b2 + x1 (smem f32) ----
    float* ob = out + base;
    #pragma unroll
    for (int mf = 0; mf < 3; mf++) {
        wmma::store_matrix_sync(st, acc2[mf], 16, wmma::mem_row_major);
        __syncwarp();
        int mm = wm*48 + mf*16 + r;
        int pp = wn*16 + c8;
        float bb = __ldg(&b2v[mm]);
        const float* sp = st + r*16 + c8;
        const float* fp = x1f + mm * 72 + pp;
        float4 s0 = *(const float4*)(sp);
        float4 s1 = *(const float4*)(sp + 4);
        float4 f0 = *(const float4*)(fp);
        float4 f1 = *(const float4*)(fp + 4);
        float* gp = ob + (size_t)mm * HW + pp;
        *(float4*)(gp)     = make_float4(s0.x+bb+f0.x, s0.y+bb+f0.y, s0.z+bb+f0.z, s0.w+bb+f0.w);
        *(float4*)(gp + 4) = make_float4(s1.x+bb+f1.x, s1.y+bb+f1.y, s1.z+bb+f1.z, s1.w+bb+f1.w);
        __syncwarp();
    }
}

// ---------------------------------------------------------------------------
extern "C" void kernel_launch(void* const* d_in, const int* in_sizes, int n_in,
                              void* d_out, int out_size)
{
    const float* x       = (const float*)d_in[0];
    const float* prompt  = (const float*)d_in[1];
    const float* sweights= (const float*)d_in[2];
    const float* ln_w    = (const float*)d_in[3];
    const float* ln_b    = (const float*)d_in[4];
    const float* e0_pw_w = (const float*)d_in[5];
    const float* e0_pw_b = (const float*)d_in[6];
    const float* e0_dw_w = (const float*)d_in[7];
    const float* e0_dw_b = (const float*)d_in[8];
    const float* e1_dw_w = (const float*)d_in[9];
    const float* e1_dw_b = (const float*)d_in[10];
    const float* e2_dw_w = (const float*)d_in[11];
    const float* e2_dw_b = (const float*)d_in[12];
    const float* proj_w  = (const float*)d_in[13];
    const float* proj_b  = (const float*)d_in[14];
    const float* ffn1_w  = (const float*)d_in[15];
    const float* ffn1_b  = (const float*)d_in[16];
    const float* ffn2_w  = (const float*)d_in[17];
    const float* ffn2_b  = (const float*)d_in[18];
    float* out = (float*)d_out;

    cudaFuncSetAttribute(k_ln_e0pw, cudaFuncAttributeMaxDynamicSharedMemorySize, S_END);
    cudaFuncSetAttribute(k_fused,   cudaFuncAttributeMaxDynamicSharedMemorySize, F_END);

    dim3 gg(HW / 64, B_);

    k_prep<<<216, 256>>>(e0_pw_w, proj_w, ffn1_w, ffn2_w);

    k_ln_e0pw<<<gg, 256, S_END>>>(x, ln_w, ln_b, e0_pw_b);

    dim3 gdw(16, C_, B_);
    k_dw<<<gdw, 512>>>(sweights, prompt,
                       e0_dw_w, e0_dw_b, e1_dw_w, e1_dw_b, e2_dw_w, e2_dw_b);

    k_fused<<<gg, 256, F_END>>>(x, proj_b, ffn1_b, ffn2_b, out);
}